// round 6
// baseline (speedup 1.0000x reference)
#include <cuda_runtime.h>

constexpr int NN  = 20000;   // nodes
constexpr int TT  = 12;      // encoder steps
constexpr int HOR = 6;       // decoder horizon
constexpr int FF  = 16;      // input features (== C, decoder feedback)
constexpr int EE  = 320000;  // edges
constexpr int HH  = 128;     // hidden
constexpr int CC  = 16;      // out channels

// ---------------- scratch (static device globals; no allocation) -----------
__device__ __align__(16) float g_xw12[TT][NN * HH]; // encoder x@gcn_w, all steps
__device__ __align__(16) float g_hg12[TT][NN * HH]; // encoder relu(gcn), all steps
__device__ __align__(16) float g_xw[NN * HH];       // decoder x@gcn_w
__device__ __align__(16) float g_agg[NN * HH];      // decoder relu(gcn)
__device__ __align__(16) float g_hb[3][NN * HH];    // rotating window buffers
__device__ __align__(16) float g_W[384 * HH];       // fused [A;B;C]
__device__ __align__(16) float g_dvec[HH];          // fused bias vector
__device__ int   g_is64;

// per-edge-set CSR (built once per launch)
__device__ int   g_deg[TT][NN];
__device__ int   g_indptr[TT][NN + 1];
__device__ int   g_cur[TT][NN];
__device__ float g_dinv[TT][NN];
__device__ int   g_csrc[TT][EE];
__device__ float g_cw[TT][EE];

// ---------------- f32x2 packed math helpers ---------------------------------
__device__ __forceinline__ unsigned long long pk2(float a) {
    unsigned long long r;
    asm("mov.b64 %0, {%1, %1};" : "=l"(r) : "f"(a));
    return r;
}
__device__ __forceinline__ void fma2(unsigned long long& c,
                                     unsigned long long a,
                                     unsigned long long b) {
    asm("fma.rn.f32x2 %0, %1, %2, %3;" : "=l"(c) : "l"(a), "l"(b), "l"(c));
}
__device__ __forceinline__ float2 up2(unsigned long long v) {
    float2 f;
    asm("mov.b64 {%0, %1}, %2;" : "=f"(f.x), "=f"(f.y) : "l"(v));
    return f;
}

// ---------------- edge-index dtype detection --------------------------------
__global__ void k_detect(const unsigned int* __restrict__ w) {
    int nz = 0;
    #pragma unroll 8
    for (int i = 0; i < 128; ++i) nz += (w[2 * i + 1] != 0u);
    g_is64 = (nz == 0) ? 1 : 0;
}

__device__ __forceinline__ int load_idx(const void* p, long long e) {
    int v;
    if (g_is64) v = (int)((const long long*)p)[e];
    else        v = ((const int*)p)[e];
    v = v < 0 ? 0 : (v >= NN ? NN - 1 : v);
    return v;
}

// ---------------- one-time prep: fold conv_w/proj_w into A,B,C -------------
__global__ void k_prep_W(const float* __restrict__ conv_w,
                         const float* __restrict__ proj_w) {
    __shared__ float w0[128], w1[128], w2[128];
    int c = blockIdx.x;       // 0..383
    int h = threadIdx.x;      // 0..127
    float acc = 0.f;
    if (c < 128) {
        w1[h] = conv_w[((128 + h) * 128 + c) * 3 + 0];
        __syncthreads();
        #pragma unroll 4
        for (int o = 0; o < 128; ++o) acc += w1[o] * proj_w[h * 384 + 128 + o];
    } else if (c < 256) {
        int cc = c - 128;
        w0[h] = conv_w[(h * 128 + cc) * 3 + 0];
        __syncthreads();
        #pragma unroll 4
        for (int o = 0; o < 128; ++o) acc += w0[o] * proj_w[h * 384 + o];
    } else {
        int cc = c - 256;
        w0[h] = conv_w[(h * 128 + cc) * 3 + 1];
        w1[h] = conv_w[((128 + h) * 128 + cc) * 3 + 1];
        w2[h] = conv_w[((256 + h) * 128 + cc) * 3 + 1];
        __syncthreads();
        #pragma unroll 2
        for (int o = 0; o < 128; ++o) {
            acc += w0[o] * proj_w[h * 384 + o]
                 + w1[o] * proj_w[h * 384 + 128 + o]
                 + w2[o] * proj_w[h * 384 + 256 + o];
        }
    }
    g_W[c * 128 + h] = acc;
}

__global__ void k_prep_d(const float* __restrict__ conv_b,
                         const float* __restrict__ proj_w,
                         const float* __restrict__ proj_b) {
    int h = threadIdx.x;
    float acc = proj_b[h];
    #pragma unroll 4
    for (int j = 0; j < 384; ++j) acc += conv_b[j] * proj_w[h * 384 + j];
    g_dvec[h] = acc;
}

__global__ void k_zero_win() {
    int idx = blockIdx.x * blockDim.x + threadIdx.x;
    if (idx < NN * HH) { g_hb[0][idx] = 0.f; g_hb[1][idx] = 0.f; }
}

// ---------------- CSR construction (once per launch) ------------------------
__global__ void k_zero_deg12() {
    int idx = blockIdx.x * blockDim.x + threadIdx.x;
    if (idx < TT * NN) (&g_deg[0][0])[idx] = 0;
}

__global__ void k_count12(const void* __restrict__ ei) {
    long long idx = (long long)blockIdx.x * blockDim.x + threadIdx.x;
    if (idx >= (long long)TT * EE) return;
    int set = (int)(idx / EE);
    int e   = (int)(idx % EE);
    int d = load_idx(ei, (long long)set * 2 * EE + EE + e);
    atomicAdd(&g_deg[set][d], 1);
}

__global__ void k_scan12() {
    __shared__ int sh[1024];
    int set = blockIdx.x;
    int t   = threadIdx.x;
    const int PER = 20;                       // 1024*20 >= NN
    int base = t * PER;
    int degs[PER];
    int sum = 0;
    #pragma unroll
    for (int i = 0; i < PER; ++i) {
        int n = base + i;
        degs[i] = (n < NN) ? g_deg[set][n] : 0;
        sum += degs[i];
    }
    sh[t] = sum;
    __syncthreads();
    for (int off = 1; off < 1024; off <<= 1) {
        int v = (t >= off) ? sh[t - off] : 0;
        __syncthreads();
        sh[t] += v;
        __syncthreads();
    }
    int run = sh[t] - sum;
    #pragma unroll
    for (int i = 0; i < PER; ++i) {
        int n = base + i;
        if (n < NN) {
            g_indptr[set][n] = run;
            g_cur[set][n]    = run;
            g_dinv[set][n]   = rsqrtf(1.0f + (float)degs[i]);
            run += degs[i];
        }
    }
    if (t == 1023) g_indptr[set][NN] = sh[1023];
}

__global__ void k_fill12(const void* __restrict__ ei) {
    long long idx = (long long)blockIdx.x * blockDim.x + threadIdx.x;
    if (idx >= (long long)TT * EE) return;
    int set = (int)(idx / EE);
    int e   = (int)(idx % EE);
    long long b = (long long)set * 2 * EE;
    int s = load_idx(ei, b + e);
    int d = load_idx(ei, b + EE + e);
    int pos = atomicAdd(&g_cur[set][d], 1);
    g_csrc[set][pos] = s;
    g_cw[set][pos]   = g_dinv[set][s] * g_dinv[set][d];
}

// ---------------- GCN kernels ------------------------------------------------
__device__ __forceinline__ void xw_body(const float* __restrict__ x,
                                        const float* __restrict__ gcn_w,
                                        float* __restrict__ xwout,
                                        int row0) {
    __shared__ float Ws[16 * 128];
    __shared__ float Xs[16 * 16];
    int tid = threadIdx.x;
    #pragma unroll
    for (int i = 0; i < 16; ++i) Ws[i * 128 + tid] = gcn_w[i * 128 + tid];
    #pragma unroll
    for (int j = tid; j < 256; j += 128) Xs[j] = x[row0 * 16 + j];
    __syncthreads();
    #pragma unroll
    for (int r = 0; r < 16; ++r) {
        float acc = 0.f;
        #pragma unroll
        for (int f = 0; f < 16; ++f) acc += Xs[r * 16 + f] * Ws[f * 128 + tid];
        xwout[(row0 + r) * 128 + tid] = acc;
    }
}

// all 12 encoder steps at once: grid (NN/16, TT)
__global__ void k_xw_all(const float* __restrict__ x_seq,
                         const float* __restrict__ gcn_w) {
    int set = blockIdx.y;
    xw_body(x_seq + (long long)set * NN * FF, gcn_w,
            &g_xw12[set][0], blockIdx.x * 16);
}

__global__ void k_xw1(const float* __restrict__ x,
                      const float* __restrict__ gcn_w) {
    xw_body(x, gcn_w, g_xw, blockIdx.x * 16);
}

// CSR gather + relu; one warp per node
__device__ __forceinline__ void gather_body(int set,
                                            const float* __restrict__ xw,
                                            float* __restrict__ hgout,
                                            const float* __restrict__ gcn_b) {
    int warp = (blockIdx.x * blockDim.x + threadIdx.x) >> 5;
    int lane = threadIdx.x & 31;
    if (warp >= NN) return;
    int node = warp;
    int beg = g_indptr[set][node];
    int end = g_indptr[set][node + 1];
    float di = g_dinv[set][node];
    float4 acc = __ldg(reinterpret_cast<const float4*>(xw + node * 128) + lane);
    float d2 = di * di;
    acc.x *= d2; acc.y *= d2; acc.z *= d2; acc.w *= d2;
    int i = beg;
    for (; i + 1 < end; i += 2) {
        int   s0 = g_csrc[set][i],     s1 = g_csrc[set][i + 1];
        float w0 = g_cw[set][i],       w1 = g_cw[set][i + 1];
        float4 u0 = __ldg(reinterpret_cast<const float4*>(xw + s0 * 128) + lane);
        float4 u1 = __ldg(reinterpret_cast<const float4*>(xw + s1 * 128) + lane);
        acc.x += u0.x * w0 + u1.x * w1;
        acc.y += u0.y * w0 + u1.y * w1;
        acc.z += u0.z * w0 + u1.z * w1;
        acc.w += u0.w * w0 + u1.w * w1;
    }
    if (i < end) {
        int   s0 = g_csrc[set][i];
        float w0 = g_cw[set][i];
        float4 u0 = __ldg(reinterpret_cast<const float4*>(xw + s0 * 128) + lane);
        acc.x += u0.x * w0; acc.y += u0.y * w0;
        acc.z += u0.z * w0; acc.w += u0.w * w0;
    }
    float4 b = __ldg(reinterpret_cast<const float4*>(gcn_b) + lane);
    acc.x = fmaxf(acc.x + b.x, 0.f);
    acc.y = fmaxf(acc.y + b.y, 0.f);
    acc.z = fmaxf(acc.z + b.z, 0.f);
    acc.w = fmaxf(acc.w + b.w, 0.f);
    *(reinterpret_cast<float4*>(hgout + node * 128) + lane) = acc;
}

__global__ void k_gather_all(const float* __restrict__ gcn_b) {
    int set = blockIdx.y;
    gather_body(set, &g_xw12[set][0], &g_hg12[set][0], gcn_b);
}

__global__ void k_gather1(int set, const float* __restrict__ gcn_b) {
    gather_body(set, g_xw, g_agg, gcn_b);
}

// ---------------- h_new GEMM (f32x2 packed) ----------------------------------
// h_new = [win1 | win2 | hg] @ g_W + g_dvec      (relu already applied to hg)
// hgsel: 0..11 -> g_hg12[hgsel], -1 -> g_agg      (resolved DEVICE-side)
__global__ void k_hnew(int i1, int i2, int hgsel, int idst) {
    __shared__ __align__(16) float In[64 * 32];
    __shared__ __align__(16) float Ws[32 * 128];
    const float* hg = (hgsel >= 0) ? &g_hg12[hgsel][0] : g_agg;
    int t    = threadIdx.x;
    int ty   = t >> 4;        // 0..15 (row group)
    int tx   = t & 15;        // 0..15 (8-col group)
    int row0 = blockIdx.x * 64;

    unsigned long long acc[4][4];   // 4 rows x 4 f32x2 pairs (8 cols)
    #pragma unroll
    for (int i = 0; i < 4; ++i)
        #pragma unroll
        for (int j = 0; j < 4; ++j) acc[i][j] = 0ull;

    #pragma unroll
    for (int kc = 0; kc < 12; ++kc) {
        const float* srcm = (kc < 4) ? g_hb[i1] : (kc < 8) ? g_hb[i2] : hg;
        int colbase = (kc & 3) * 32;
        #pragma unroll
        for (int i = 0; i < 8; ++i) {
            int L = t + 256 * i;
            int r = L >> 5, c = L & 31;
            int row = row0 + r;
            In[L] = (row < NN) ? srcm[row * 128 + colbase + c] : 0.f;
        }
        #pragma unroll
        for (int i = 0; i < 16; ++i) {
            int L = t + 256 * i;
            Ws[L] = g_W[kc * 4096 + L];
        }
        __syncthreads();
        #pragma unroll
        for (int k = 0; k < 32; ++k) {
            const unsigned long long* wp =
                reinterpret_cast<const unsigned long long*>(&Ws[k * 128 + tx * 8]);
            unsigned long long w0 = wp[0], w1 = wp[1], w2 = wp[2], w3 = wp[3];
            #pragma unroll
            for (int i = 0; i < 4; ++i) {
                unsigned long long a2 = pk2(In[(ty + 16 * i) * 32 + k]);
                fma2(acc[i][0], a2, w0);
                fma2(acc[i][1], a2, w1);
                fma2(acc[i][2], a2, w2);
                fma2(acc[i][3], a2, w3);
            }
        }
        __syncthreads();
    }

    const unsigned long long* dvp =
        reinterpret_cast<const unsigned long long*>(&g_dvec[tx * 8]);
    float2 d0 = up2(dvp[0]), d1 = up2(dvp[1]), d2 = up2(dvp[2]), d3 = up2(dvp[3]);
    #pragma unroll
    for (int i = 0; i < 4; ++i) {
        int row = row0 + ty + 16 * i;
        if (row < NN) {
            float2 a0 = up2(acc[i][0]), a1 = up2(acc[i][1]);
            float2 a2 = up2(acc[i][2]), a3 = up2(acc[i][3]);
            float4 o0 = {a0.x + d0.x, a0.y + d0.y, a1.x + d1.x, a1.y + d1.y};
            float4 o1 = {a2.x + d2.x, a2.y + d2.y, a3.x + d3.x, a3.y + d3.y};
            float4* dst = reinterpret_cast<float4*>(&g_hb[idst][row * 128 + tx * 8]);
            dst[0] = o0;
            dst[1] = o1;
        }
    }
}

// y = h_new @ head_w^T + head_b
__global__ void k_y(int isrc, const float* __restrict__ head_w,
                    const float* __restrict__ head_b,
                    float* __restrict__ out) {
    __shared__ float Hs[16][132];
    __shared__ float Ws[16][132];
    int t    = threadIdx.x;   // 256
    int row0 = blockIdx.x * 16;
    for (int i = t; i < 16 * 128; i += 256) Ws[i >> 7][i & 127] = head_w[i];
    for (int i = t; i < 16 * 128; i += 256) {
        int r = i >> 7;
        Hs[r][i & 127] = g_hb[isrc][(row0 + r) * 128 + (i & 127)];
    }
    __syncthreads();
    int r = t >> 4, c = t & 15;
    float acc = head_b[c];
    #pragma unroll 8
    for (int k = 0; k < 128; ++k) acc += Hs[r][k] * Ws[c][k];
    out[(row0 + r) * 16 + c] = acc;
}

// ---------------------------------------------------------------------------
extern "C" void kernel_launch(void* const* d_in, const int* in_sizes, int n_in,
                              void* d_out, int out_size) {
    const float* x_seq  = (const float*)d_in[0];
    const void*  ei     = d_in[1];
    const float* gcn_w  = (const float*)d_in[5];
    const float* gcn_b  = (const float*)d_in[6];
    const float* conv_w = (const float*)d_in[7];
    const float* conv_b = (const float*)d_in[8];
    const float* proj_w = (const float*)d_in[9];
    const float* proj_b = (const float*)d_in[10];
    const float* head_w = (const float*)d_in[11];
    const float* head_b = (const float*)d_in[12];
    float* out = (float*)d_out;

    // ---- one-time prep ----
    k_detect<<<1, 1>>>((const unsigned int*)ei);
    k_prep_W<<<384, 128>>>(conv_w, proj_w);
    k_prep_d<<<1, 128>>>(conv_b, proj_w, proj_b);
    k_zero_win<<<(NN * HH + 255) / 256, 256>>>();
    k_zero_deg12<<<(TT * NN + 255) / 256, 256>>>();
    {
        long long tot = (long long)TT * EE;
        int blocks = (int)((tot + 255) / 256);
        k_count12<<<blocks, 256>>>(ei);
        k_scan12<<<TT, 1024>>>();
        k_fill12<<<blocks, 256>>>(ei);
    }

    // ---- batched encoder GCN (independent of recurrence) ----
    {
        dim3 gx(NN / 16, TT);
        k_xw_all<<<gx, 128>>>(x_seq, gcn_w);
        dim3 gg((NN * 32 + 255) / 256, TT);
        k_gather_all<<<gg, 256>>>(gcn_b);
    }

    // ---- sequential loop ----
    int i1 = 0, i2 = 1, idst = 2;
    for (int t = 0; t < TT + HOR; ++t) {
        bool enc = (t < TT);

        int hgsel;
        if (enc)            hgsel = t;
        else if (t == TT)   hgsel = TT - 1;           // identical GCN to step 11
        else {
            const float* xin = out + (long long)(t - TT - 1) * NN * CC;
            k_xw1<<<NN / 16, 128>>>(xin, gcn_w);
            k_gather1<<<(NN * 32 + 255) / 256, 256>>>(TT - 1, gcn_b);
            hgsel = -1;
        }
        k_hnew<<<(NN + 63) / 64, 256>>>(i1, i2, hgsel, idst);
        if (!enc)
            k_y<<<NN / 16, 256>>>(idst, head_w, head_b,
                                  out + (long long)(t - TT) * NN * CC);

        int old1 = i1; i1 = i2; i2 = idst; idst = old1;
    }
}

// round 7
// speedup vs baseline: 1.5544x; 1.5544x over previous
#include <cuda_runtime.h>
#include <cuda_bf16.h>

constexpr int NN  = 20000;   // nodes
constexpr int TT  = 12;      // encoder steps
constexpr int HOR = 6;       // decoder horizon
constexpr int FF  = 16;      // input features (== C, decoder feedback)
constexpr int EE  = 320000;  // edges
constexpr int HH  = 128;     // hidden
constexpr int CC  = 16;      // out channels

// ---------------- scratch (static device globals; no allocation) -----------
__device__ __align__(16) float g_xw12[TT][NN * HH]; // encoder x@gcn_w, all steps
__device__ __align__(16) float g_hg12[TT][NN * HH]; // encoder relu(gcn), all steps
__device__ __align__(16) float g_xw[NN * HH];       // decoder x@gcn_w
__device__ __align__(16) float g_agg[NN * HH];      // decoder relu(gcn)
__device__ __align__(16) float g_hb[3][NN * HH];    // rotating window buffers
__device__ __align__(16) float g_W[384 * HH];       // fused [A;B;C] (K x N)
__device__ __align__(16) float g_dvec[HH];          // fused bias vector
__device__ __align__(16) unsigned g_Whi_pk[192 * HH]; // bf16x2-packed hi(W), pairs in K
__device__ __align__(16) unsigned g_Wlo_pk[192 * HH]; // bf16x2-packed lo(W)
__device__ int   g_is64;

// per-edge-set CSR (built once per launch)
__device__ int   g_deg[TT][NN];
__device__ int   g_indptr[TT][NN + 1];
__device__ int   g_cur[TT][NN];
__device__ float g_dinv[TT][NN];
__device__ int   g_csrc[TT][EE];
__device__ float g_cw[TT][EE];

// ---------------- edge-index dtype detection --------------------------------
__global__ void k_detect(const unsigned int* __restrict__ w) {
    int nz = 0;
    #pragma unroll 8
    for (int i = 0; i < 128; ++i) nz += (w[2 * i + 1] != 0u);
    g_is64 = (nz == 0) ? 1 : 0;
}

__device__ __forceinline__ int load_idx(const void* p, long long e) {
    int v;
    if (g_is64) v = (int)((const long long*)p)[e];
    else        v = ((const int*)p)[e];
    v = v < 0 ? 0 : (v >= NN ? NN - 1 : v);
    return v;
}

// ---------------- one-time prep: fold conv_w/proj_w into A,B,C -------------
__global__ void k_prep_W(const float* __restrict__ conv_w,
                         const float* __restrict__ proj_w) {
    __shared__ float w0[128], w1[128], w2[128];
    int c = blockIdx.x;       // 0..383
    int h = threadIdx.x;      // 0..127
    float acc = 0.f;
    if (c < 128) {
        w1[h] = conv_w[((128 + h) * 128 + c) * 3 + 0];
        __syncthreads();
        #pragma unroll 4
        for (int o = 0; o < 128; ++o) acc += w1[o] * proj_w[h * 384 + 128 + o];
    } else if (c < 256) {
        int cc = c - 128;
        w0[h] = conv_w[(h * 128 + cc) * 3 + 0];
        __syncthreads();
        #pragma unroll 4
        for (int o = 0; o < 128; ++o) acc += w0[o] * proj_w[h * 384 + o];
    } else {
        int cc = c - 256;
        w0[h] = conv_w[(h * 128 + cc) * 3 + 1];
        w1[h] = conv_w[((128 + h) * 128 + cc) * 3 + 1];
        w2[h] = conv_w[((256 + h) * 128 + cc) * 3 + 1];
        __syncthreads();
        #pragma unroll 2
        for (int o = 0; o < 128; ++o) {
            acc += w0[o] * proj_w[h * 384 + o]
                 + w1[o] * proj_w[h * 384 + 128 + o]
                 + w2[o] * proj_w[h * 384 + 256 + o];
        }
    }
    g_W[c * 128 + h] = acc;
}

__global__ void k_prep_d(const float* __restrict__ conv_b,
                         const float* __restrict__ proj_w,
                         const float* __restrict__ proj_b) {
    int h = threadIdx.x;
    float acc = proj_b[h];
    #pragma unroll 4
    for (int j = 0; j < 384; ++j) acc += conv_b[j] * proj_w[h * 384 + j];
    g_dvec[h] = acc;
}

// split W into bf16 hi/lo, packed as (W[2k][n], W[2k+1][n]) per 32-bit word
__device__ __forceinline__ unsigned pk_bf(__nv_bfloat16 a, __nv_bfloat16 b) {
    __nv_bfloat162 x; x.x = a; x.y = b;
    return *reinterpret_cast<unsigned*>(&x);
}
__global__ void k_prep_split() {
    int kp = blockIdx.x;      // 0..191
    int n  = threadIdx.x;     // 0..127
    float w0 = g_W[(2 * kp) * 128 + n];
    float w1 = g_W[(2 * kp + 1) * 128 + n];
    __nv_bfloat16 h0 = __float2bfloat16(w0);
    __nv_bfloat16 h1 = __float2bfloat16(w1);
    __nv_bfloat16 l0 = __float2bfloat16(w0 - __bfloat162float(h0));
    __nv_bfloat16 l1 = __float2bfloat16(w1 - __bfloat162float(h1));
    g_Whi_pk[kp * 128 + n] = pk_bf(h0, h1);
    g_Wlo_pk[kp * 128 + n] = pk_bf(l0, l1);
}

__global__ void k_zero_win() {
    int idx = blockIdx.x * blockDim.x + threadIdx.x;
    if (idx < NN * HH) { g_hb[0][idx] = 0.f; g_hb[1][idx] = 0.f; }
}

// ---------------- CSR construction (once per launch) ------------------------
__global__ void k_zero_deg12() {
    int idx = blockIdx.x * blockDim.x + threadIdx.x;
    if (idx < TT * NN) (&g_deg[0][0])[idx] = 0;
}

__global__ void k_count12(const void* __restrict__ ei) {
    long long idx = (long long)blockIdx.x * blockDim.x + threadIdx.x;
    if (idx >= (long long)TT * EE) return;
    int set = (int)(idx / EE);
    int e   = (int)(idx % EE);
    int d = load_idx(ei, (long long)set * 2 * EE + EE + e);
    atomicAdd(&g_deg[set][d], 1);
}

__global__ void k_scan12() {
    __shared__ int sh[1024];
    int set = blockIdx.x;
    int t   = threadIdx.x;
    const int PER = 20;                       // 1024*20 >= NN
    int base = t * PER;
    int degs[PER];
    int sum = 0;
    #pragma unroll
    for (int i = 0; i < PER; ++i) {
        int n = base + i;
        degs[i] = (n < NN) ? g_deg[set][n] : 0;
        sum += degs[i];
    }
    sh[t] = sum;
    __syncthreads();
    for (int off = 1; off < 1024; off <<= 1) {
        int v = (t >= off) ? sh[t - off] : 0;
        __syncthreads();
        sh[t] += v;
        __syncthreads();
    }
    int run = sh[t] - sum;
    #pragma unroll
    for (int i = 0; i < PER; ++i) {
        int n = base + i;
        if (n < NN) {
            g_indptr[set][n] = run;
            g_cur[set][n]    = run;
            g_dinv[set][n]   = rsqrtf(1.0f + (float)degs[i]);
            run += degs[i];
        }
    }
    if (t == 1023) g_indptr[set][NN] = sh[1023];
}

__global__ void k_fill12(const void* __restrict__ ei) {
    long long idx = (long long)blockIdx.x * blockDim.x + threadIdx.x;
    if (idx >= (long long)TT * EE) return;
    int set = (int)(idx / EE);
    int e   = (int)(idx % EE);
    long long b = (long long)set * 2 * EE;
    int s = load_idx(ei, b + e);
    int d = load_idx(ei, b + EE + e);
    int pos = atomicAdd(&g_cur[set][d], 1);
    g_csrc[set][pos] = s;
    g_cw[set][pos]   = g_dinv[set][s] * g_dinv[set][d];
}

// ---------------- GCN kernels ------------------------------------------------
__device__ __forceinline__ void xw_body(const float* __restrict__ x,
                                        const float* __restrict__ gcn_w,
                                        float* __restrict__ xwout,
                                        int row0) {
    __shared__ float Ws[16 * 128];
    __shared__ float Xs[16 * 16];
    int tid = threadIdx.x;
    #pragma unroll
    for (int i = 0; i < 16; ++i) Ws[i * 128 + tid] = gcn_w[i * 128 + tid];
    #pragma unroll
    for (int j = tid; j < 256; j += 128) Xs[j] = x[row0 * 16 + j];
    __syncthreads();
    #pragma unroll
    for (int r = 0; r < 16; ++r) {
        float acc = 0.f;
        #pragma unroll
        for (int f = 0; f < 16; ++f) acc += Xs[r * 16 + f] * Ws[f * 128 + tid];
        xwout[(row0 + r) * 128 + tid] = acc;
    }
}

__global__ void k_xw_all(const float* __restrict__ x_seq,
                         const float* __restrict__ gcn_w) {
    int set = blockIdx.y;
    xw_body(x_seq + (long long)set * NN * FF, gcn_w,
            &g_xw12[set][0], blockIdx.x * 16);
}

__global__ void k_xw1(const float* __restrict__ x,
                      const float* __restrict__ gcn_w) {
    xw_body(x, gcn_w, g_xw, blockIdx.x * 16);
}

__device__ __forceinline__ void gather_body(int set,
                                            const float* __restrict__ xw,
                                            float* __restrict__ hgout,
                                            const float* __restrict__ gcn_b) {
    int warp = (blockIdx.x * blockDim.x + threadIdx.x) >> 5;
    int lane = threadIdx.x & 31;
    if (warp >= NN) return;
    int node = warp;
    int beg = g_indptr[set][node];
    int end = g_indptr[set][node + 1];
    float di = g_dinv[set][node];
    float4 acc = __ldg(reinterpret_cast<const float4*>(xw + node * 128) + lane);
    float d2 = di * di;
    acc.x *= d2; acc.y *= d2; acc.z *= d2; acc.w *= d2;
    int i = beg;
    for (; i + 1 < end; i += 2) {
        int   s0 = g_csrc[set][i],     s1 = g_csrc[set][i + 1];
        float w0 = g_cw[set][i],       w1 = g_cw[set][i + 1];
        float4 u0 = __ldg(reinterpret_cast<const float4*>(xw + s0 * 128) + lane);
        float4 u1 = __ldg(reinterpret_cast<const float4*>(xw + s1 * 128) + lane);
        acc.x += u0.x * w0 + u1.x * w1;
        acc.y += u0.y * w0 + u1.y * w1;
        acc.z += u0.z * w0 + u1.z * w1;
        acc.w += u0.w * w0 + u1.w * w1;
    }
    if (i < end) {
        int   s0 = g_csrc[set][i];
        float w0 = g_cw[set][i];
        float4 u0 = __ldg(reinterpret_cast<const float4*>(xw + s0 * 128) + lane);
        acc.x += u0.x * w0; acc.y += u0.y * w0;
        acc.z += u0.z * w0; acc.w += u0.w * w0;
    }
    float4 b = __ldg(reinterpret_cast<const float4*>(gcn_b) + lane);
    acc.x = fmaxf(acc.x + b.x, 0.f);
    acc.y = fmaxf(acc.y + b.y, 0.f);
    acc.z = fmaxf(acc.z + b.z, 0.f);
    acc.w = fmaxf(acc.w + b.w, 0.f);
    *(reinterpret_cast<float4*>(hgout + node * 128) + lane) = acc;
}

__global__ void k_gather_all(const float* __restrict__ gcn_b) {
    int set = blockIdx.y;
    gather_body(set, &g_xw12[set][0], &g_hg12[set][0], gcn_b);
}

__global__ void k_gather1(int set, const float* __restrict__ gcn_b) {
    gather_body(set, g_xw, g_agg, gcn_b);
}

// ---------------- h_new GEMM: tensor-core bf16 split-precision ---------------
// h_new = [win1 | win2 | hg] @ W + d, W pre-split into bf16 hi/lo.
// D = Ahi*Whi + Ahi*Wlo + Alo*Whi  (fp32 accumulate)
// Block: 128 rows x 128 cols, 8 warps; warp w -> rows w*16, all 128 cols.

__device__ __forceinline__ void mma_bf16(float* c, const unsigned* a,
                                         unsigned b0, unsigned b1) {
    asm volatile(
        "mma.sync.aligned.m16n8k16.row.col.f32.bf16.bf16.f32 "
        "{%0,%1,%2,%3}, {%4,%5,%6,%7}, {%8,%9}, {%0,%1,%2,%3};"
        : "+f"(c[0]), "+f"(c[1]), "+f"(c[2]), "+f"(c[3])
        : "r"(a[0]), "r"(a[1]), "r"(a[2]), "r"(a[3]), "r"(b0), "r"(b1));
}

// A tile row stride (bf16 units): 24 -> banks (r*12 + w) mod 32 bijective
constexpr int AST = 24;
// W tile row stride (32-bit words): 136 -> conflict-free B fragment loads
constexpr int WST = 136;

__global__ void __launch_bounds__(256, 1)
k_hnew(int i1, int i2, int hgsel, int idst) {
    __shared__ __align__(16) __nv_bfloat16 Ah[2][128 * AST];
    __shared__ __align__(16) __nv_bfloat16 Al[2][128 * AST];
    __shared__ __align__(16) unsigned Wh[2][8 * WST];
    __shared__ __align__(16) unsigned Wl[2][8 * WST];

    const float* hg  = (hgsel >= 0) ? &g_hg12[hgsel][0] : g_agg;
    const float* hb1 = g_hb[i1];
    const float* hb2 = g_hb[i2];

    int t    = threadIdx.x;
    int w    = t >> 5;
    int l    = t & 31;
    int row0 = blockIdx.x * 128;
    int wr   = w * 16;

    float acc[16][4];
    #pragma unroll
    for (int nt = 0; nt < 16; ++nt)
        #pragma unroll
        for (int j = 0; j < 4; ++j) acc[nt][j] = 0.f;

    // staging thread mapping
    int arow = t >> 1, ahalf = t & 1;          // A: 128 rows x 2 halves of 8
    int wkk  = t >> 5, wns = (l) * 4;          // W: 8 rows x 32 uint4 segs

    // ---- prologue: stage chunk 0 into buffer 0 ----
    {
        int row = row0 + arow;
        float pv[8];
        if (row < NN) {
            const float4* p = reinterpret_cast<const float4*>(hb1 + (long long)row * 128 + ahalf * 8);
            float4 x0 = __ldg(p), x1 = __ldg(p + 1);
            pv[0]=x0.x; pv[1]=x0.y; pv[2]=x0.z; pv[3]=x0.w;
            pv[4]=x1.x; pv[5]=x1.y; pv[6]=x1.z; pv[7]=x1.w;
        } else {
            #pragma unroll
            for (int i = 0; i < 8; ++i) pv[i] = 0.f;
        }
        __nv_bfloat16 h[8], lo[8];
        #pragma unroll
        for (int i = 0; i < 8; ++i) {
            h[i]  = __float2bfloat16(pv[i]);
            lo[i] = __float2bfloat16(pv[i] - __bfloat162float(h[i]));
        }
        uint4 uh = {pk_bf(h[0],h[1]), pk_bf(h[2],h[3]), pk_bf(h[4],h[5]), pk_bf(h[6],h[7])};
        uint4 ul = {pk_bf(lo[0],lo[1]), pk_bf(lo[2],lo[3]), pk_bf(lo[4],lo[5]), pk_bf(lo[6],lo[7])};
        *reinterpret_cast<uint4*>(&Ah[0][arow * AST + ahalf * 8]) = uh;
        *reinterpret_cast<uint4*>(&Al[0][arow * AST + ahalf * 8]) = ul;
        uint4 pwh = __ldg(reinterpret_cast<const uint4*>(&g_Whi_pk[wkk * 128 + wns]));
        uint4 pwl = __ldg(reinterpret_cast<const uint4*>(&g_Wlo_pk[wkk * 128 + wns]));
        *reinterpret_cast<uint4*>(&Wh[0][wkk * WST + wns]) = pwh;
        *reinterpret_cast<uint4*>(&Wl[0][wkk * WST + wns]) = pwl;
    }
    __syncthreads();

    int rb  = wr + (l >> 2);     // fragment row (local)
    int cw  = 2 * (l & 3);       // fragment k element (within 8)

    for (int c = 0; c < 24; ++c) {
        int buf = c & 1;
        bool has = (c + 1 < 24);

        // ---- prefetch chunk c+1 into registers ----
        float pv[8];
        uint4 pwh, pwl;
        if (has) {
            int cn = c + 1;
            const float* srcm = (cn < 8) ? hb1 : (cn < 16) ? hb2 : hg;
            int colbase = (cn & 7) * 16;
            int row = row0 + arow;
            if (row < NN) {
                const float4* p = reinterpret_cast<const float4*>(
                    srcm + (long long)row * 128 + colbase + ahalf * 8);
                float4 x0 = __ldg(p), x1 = __ldg(p + 1);
                pv[0]=x0.x; pv[1]=x0.y; pv[2]=x0.z; pv[3]=x0.w;
                pv[4]=x1.x; pv[5]=x1.y; pv[6]=x1.z; pv[7]=x1.w;
            } else {
                #pragma unroll
                for (int i = 0; i < 8; ++i) pv[i] = 0.f;
            }
            pwh = __ldg(reinterpret_cast<const uint4*>(&g_Whi_pk[(cn * 8 + wkk) * 128 + wns]));
            pwl = __ldg(reinterpret_cast<const uint4*>(&g_Wlo_pk[(cn * 8 + wkk) * 128 + wns]));
        }

        // ---- compute on buffer buf ----
        const __nv_bfloat16* ah = &Ah[buf][0];
        const __nv_bfloat16* al = &Al[buf][0];
        unsigned ahi[4], alo[4];
        ahi[0] = *reinterpret_cast<const unsigned*>(&ah[rb * AST + cw]);
        ahi[1] = *reinterpret_cast<const unsigned*>(&ah[(rb + 8) * AST + cw]);
        ahi[2] = *reinterpret_cast<const unsigned*>(&ah[rb * AST + 8 + cw]);
        ahi[3] = *reinterpret_cast<const unsigned*>(&ah[(rb + 8) * AST + 8 + cw]);
        alo[0] = *reinterpret_cast<const unsigned*>(&al[rb * AST + cw]);
        alo[1] = *reinterpret_cast<const unsigned*>(&al[(rb + 8) * AST + cw]);
        alo[2] = *reinterpret_cast<const unsigned*>(&al[rb * AST + 8 + cw]);
        alo[3] = *reinterpret_cast<const unsigned*>(&al[(rb + 8) * AST + 8 + cw]);
        #pragma unroll
        for (int nt = 0; nt < 16; ++nt) {
            int wb = nt * 8 + (l >> 2);
            unsigned bh0 = Wh[buf][(l & 3) * WST + wb];
            unsigned bh1 = Wh[buf][(4 + (l & 3)) * WST + wb];
            unsigned bl0 = Wl[buf][(l & 3) * WST + wb];
            unsigned bl1 = Wl[buf][(4 + (l & 3)) * WST + wb];
            mma_bf16(acc[nt], ahi, bh0, bh1);
            mma_bf16(acc[nt], ahi, bl0, bl1);
            mma_bf16(acc[nt], alo, bh0, bh1);
        }

        // ---- convert & store prefetched chunk into the other buffer ----
        if (has) {
            int nbuf = buf ^ 1;
            __nv_bfloat16 h[8], lo[8];
            #pragma unroll
            for (int i = 0; i < 8; ++i) {
                h[i]  = __float2bfloat16(pv[i]);
                lo[i] = __float2bfloat16(pv[i] - __bfloat162float(h[i]));
            }
            uint4 uh = {pk_bf(h[0],h[1]), pk_bf(h[2],h[3]), pk_bf(h[4],h[5]), pk_bf(h[6],h[7])};
            uint4 ul = {pk_bf(lo[0],lo[1]), pk_bf(lo[2],lo[3]), pk_bf(lo[4],lo[5]), pk_bf(lo[6],lo[7])};
            *reinterpret_cast<uint4*>(&Ah[nbuf][arow * AST + ahalf * 8]) = uh;
            *reinterpret_cast<uint4*>(&Al[nbuf][arow * AST + ahalf * 8]) = ul;
            *reinterpret_cast<uint4*>(&Wh[nbuf][wkk * WST + wns]) = pwh;
            *reinterpret_cast<uint4*>(&Wl[nbuf][wkk * WST + wns]) = pwl;
        }
        __syncthreads();
    }

    // ---- epilogue: add bias, write h_new ----
    float* dst = g_hb[idst];
    int rA = row0 + rb;
    #pragma unroll
    for (int nt = 0; nt < 16; ++nt) {
        int col = nt * 8 + cw;
        float2 dv = *reinterpret_cast<const float2*>(&g_dvec[col]);
        if (rA < NN) {
            float2 o = {acc[nt][0] + dv.x, acc[nt][1] + dv.y};
            *reinterpret_cast<float2*>(&dst[(long long)rA * 128 + col]) = o;
        }
        if (rA + 8 < NN) {
            float2 o = {acc[nt][2] + dv.x, acc[nt][3] + dv.y};
            *reinterpret_cast<float2*>(&dst[(long long)(rA + 8) * 128 + col]) = o;
        }
    }
}

// y = h_new @ head_w^T + head_b
__global__ void k_y(int isrc, const float* __restrict__ head_w,
                    const float* __restrict__ head_b,
                    float* __restrict__ out) {
    __shared__ float Hs[16][132];
    __shared__ float Ws[16][132];
    int t    = threadIdx.x;   // 256
    int row0 = blockIdx.x * 16;
    for (int i = t; i < 16 * 128; i += 256) Ws[i >> 7][i & 127] = head_w[i];
    for (int i = t; i < 16 * 128; i += 256) {
        int r = i >> 7;
        Hs[r][i & 127] = g_hb[isrc][(row0 + r) * 128 + (i & 127)];
    }
    __syncthreads();
    int r = t >> 4, c = t & 15;
    float acc = head_b[c];
    #pragma unroll 8
    for (int k = 0; k < 128; ++k) acc += Hs[r][k] * Ws[c][k];
    out[(row0 + r) * 16 + c] = acc;
}

// ---------------------------------------------------------------------------
extern "C" void kernel_launch(void* const* d_in, const int* in_sizes, int n_in,
                              void* d_out, int out_size) {
    const float* x_seq  = (const float*)d_in[0];
    const void*  ei     = d_in[1];
    const float* gcn_w  = (const float*)d_in[5];
    const float* gcn_b  = (const float*)d_in[6];
    const float* conv_w = (const float*)d_in[7];
    const float* conv_b = (const float*)d_in[8];
    const float* proj_w = (const float*)d_in[9];
    const float* proj_b = (const float*)d_in[10];
    const float* head_w = (const float*)d_in[11];
    const float* head_b = (const float*)d_in[12];
    float* out = (float*)d_out;

    // ---- one-time prep ----
    k_detect<<<1, 1>>>((const unsigned int*)ei);
    k_prep_W<<<384, 128>>>(conv_w, proj_w);
    k_prep_d<<<1, 128>>>(conv_b, proj_w, proj_b);
    k_prep_split<<<192, 128>>>();
    k_zero_win<<<(NN * HH + 255) / 256, 256>>>();
    k_zero_deg12<<<(TT * NN + 255) / 256, 256>>>();
    {
        long long tot = (long long)TT * EE;
        int blocks = (int)((tot + 255) / 256);
        k_count12<<<blocks, 256>>>(ei);
        k_scan12<<<TT, 1024>>>();
        k_fill12<<<blocks, 256>>>(ei);
    }

    // ---- batched encoder GCN (independent of recurrence) ----
    {
        dim3 gx(NN / 16, TT);
        k_xw_all<<<gx, 128>>>(x_seq, gcn_w);
        dim3 gg((NN * 32 + 255) / 256, TT);
        k_gather_all<<<gg, 256>>>(gcn_b);
    }

    // ---- sequential loop ----
    int i1 = 0, i2 = 1, idst = 2;
    for (int t = 0; t < TT + HOR; ++t) {
        bool enc = (t < TT);

        int hgsel;
        if (enc)            hgsel = t;
        else if (t == TT)   hgsel = TT - 1;           // identical GCN to step 11
        else {
            const float* xin = out + (long long)(t - TT - 1) * NN * CC;
            k_xw1<<<NN / 16, 128>>>(xin, gcn_w);
            k_gather1<<<(NN * 32 + 255) / 256, 256>>>(TT - 1, gcn_b);
            hgsel = -1;
        }
        k_hnew<<<(NN + 127) / 128, 256>>>(i1, i2, hgsel, idst);
        if (!enc)
            k_y<<<NN / 16, 256>>>(idst, head_w, head_b,
                                  out + (long long)(t - TT) * NN * CC);

        int old1 = i1; i1 = i2; i2 = idst; idst = old1;
    }
}

// round 8
// speedup vs baseline: 1.6696x; 1.0741x over previous
#include <cuda_runtime.h>
#include <cuda_bf16.h>

constexpr int NN  = 20000;   // nodes
constexpr int TT  = 12;      // encoder steps
constexpr int HOR = 6;       // decoder horizon
constexpr int FF  = 16;      // input features (== C, decoder feedback)
constexpr int EE  = 320000;  // edges
constexpr int HH  = 128;     // hidden
constexpr int CC  = 16;      // out channels

// ---------------- scratch (static device globals; no allocation) -----------
__device__ __align__(16) float g_xw12[TT][NN * HH]; // encoder x@gcn_w, all steps
__device__ __align__(16) float g_xw[NN * HH];       // decoder x@gcn_w
__device__ __align__(16) float g_hb[3][NN * HH];    // window buffers (fp32, for k_y)
__device__ __align__(16) float g_W[384 * HH];       // fused [A;B;C] (K x N)
__device__ __align__(16) float g_dvec[HH];          // fused bias vector
__device__ __align__(16) unsigned g_Whi_pk[192 * HH]; // bf16x2-packed hi(W)
__device__ __align__(16) unsigned g_Wlo_pk[192 * HH]; // bf16x2-packed lo(W)

// pre-packed bf16 hi/lo activations (produced at write time)
__device__ __align__(16) unsigned g_hg12h[TT][NN * 64];
__device__ __align__(16) unsigned g_hg12l[TT][NN * 64];
__device__ __align__(16) unsigned g_hbh[3][NN * 64];
__device__ __align__(16) unsigned g_hbl[3][NN * 64];
__device__ __align__(16) unsigned g_aggh[NN * 64];
__device__ __align__(16) unsigned g_aggl[NN * 64];
__device__ int   g_is64;

// per-edge-set CSR (built once per launch)
__device__ int   g_deg[TT][NN];
__device__ int   g_indptr[TT][NN + 1];
__device__ int   g_cur[TT][NN];
__device__ float g_dinv[TT][NN];
__device__ int   g_csrc[TT][EE];
__device__ float g_cw[TT][EE];

// ---------------- helpers ----------------------------------------------------
__device__ __forceinline__ unsigned pk_bf(__nv_bfloat16 a, __nv_bfloat16 b) {
    __nv_bfloat162 x; x.x = a; x.y = b;
    return *reinterpret_cast<unsigned*>(&x);
}
// split (a,b) fp32 pair into packed hi word + packed lo word
__device__ __forceinline__ void split_pk(float a, float b,
                                         unsigned& hi, unsigned& lo) {
    __nv_bfloat16 ha = __float2bfloat16(a);
    __nv_bfloat16 hb = __float2bfloat16(b);
    __nv_bfloat16 la = __float2bfloat16(a - __bfloat162float(ha));
    __nv_bfloat16 lb = __float2bfloat16(b - __bfloat162float(hb));
    hi = pk_bf(ha, hb);
    lo = pk_bf(la, lb);
}

// ---------------- edge-index dtype detection --------------------------------
__global__ void k_detect(const unsigned int* __restrict__ w) {
    int nz = 0;
    #pragma unroll 8
    for (int i = 0; i < 128; ++i) nz += (w[2 * i + 1] != 0u);
    g_is64 = (nz == 0) ? 1 : 0;
}

__device__ __forceinline__ int load_idx(const void* p, long long e) {
    int v;
    if (g_is64) v = (int)((const long long*)p)[e];
    else        v = ((const int*)p)[e];
    v = v < 0 ? 0 : (v >= NN ? NN - 1 : v);
    return v;
}

// ---------------- one-time prep: fold conv_w/proj_w into A,B,C -------------
__global__ void k_prep_W(const float* __restrict__ conv_w,
                         const float* __restrict__ proj_w) {
    __shared__ float w0[128], w1[128], w2[128];
    int c = blockIdx.x;       // 0..383
    int h = threadIdx.x;      // 0..127
    float acc = 0.f;
    if (c < 128) {
        w1[h] = conv_w[((128 + h) * 128 + c) * 3 + 0];
        __syncthreads();
        #pragma unroll 4
        for (int o = 0; o < 128; ++o) acc += w1[o] * proj_w[h * 384 + 128 + o];
    } else if (c < 256) {
        int cc = c - 128;
        w0[h] = conv_w[(h * 128 + cc) * 3 + 0];
        __syncthreads();
        #pragma unroll 4
        for (int o = 0; o < 128; ++o) acc += w0[o] * proj_w[h * 384 + o];
    } else {
        int cc = c - 256;
        w0[h] = conv_w[(h * 128 + cc) * 3 + 1];
        w1[h] = conv_w[((128 + h) * 128 + cc) * 3 + 1];
        w2[h] = conv_w[((256 + h) * 128 + cc) * 3 + 1];
        __syncthreads();
        #pragma unroll 2
        for (int o = 0; o < 128; ++o) {
            acc += w0[o] * proj_w[h * 384 + o]
                 + w1[o] * proj_w[h * 384 + 128 + o]
                 + w2[o] * proj_w[h * 384 + 256 + o];
        }
    }
    g_W[c * 128 + h] = acc;
}

__global__ void k_prep_d(const float* __restrict__ conv_b,
                         const float* __restrict__ proj_w,
                         const float* __restrict__ proj_b) {
    int h = threadIdx.x;
    float acc = proj_b[h];
    #pragma unroll 4
    for (int j = 0; j < 384; ++j) acc += conv_b[j] * proj_w[h * 384 + j];
    g_dvec[h] = acc;
}

__global__ void k_prep_split() {
    int kp = blockIdx.x;      // 0..191
    int n  = threadIdx.x;     // 0..127
    unsigned hi, lo;
    split_pk(g_W[(2 * kp) * 128 + n], g_W[(2 * kp + 1) * 128 + n], hi, lo);
    g_Whi_pk[kp * 128 + n] = hi;
    g_Wlo_pk[kp * 128 + n] = lo;
}

__global__ void k_zero_win() {
    int idx = blockIdx.x * blockDim.x + threadIdx.x;
    if (idx < NN * 64) {
        g_hbh[0][idx] = 0u; g_hbl[0][idx] = 0u;
        g_hbh[1][idx] = 0u; g_hbl[1][idx] = 0u;
    }
}

// ---------------- CSR construction (once per launch) ------------------------
__global__ void k_zero_deg12() {
    int idx = blockIdx.x * blockDim.x + threadIdx.x;
    if (idx < TT * NN) (&g_deg[0][0])[idx] = 0;
}

__global__ void k_count12(const void* __restrict__ ei) {
    long long idx = (long long)blockIdx.x * blockDim.x + threadIdx.x;
    if (idx >= (long long)TT * EE) return;
    int set = (int)(idx / EE);
    int e   = (int)(idx % EE);
    int d = load_idx(ei, (long long)set * 2 * EE + EE + e);
    atomicAdd(&g_deg[set][d], 1);
}

__global__ void k_scan12() {
    __shared__ int sh[1024];
    int set = blockIdx.x;
    int t   = threadIdx.x;
    const int PER = 20;                       // 1024*20 >= NN
    int base = t * PER;
    int degs[PER];
    int sum = 0;
    #pragma unroll
    for (int i = 0; i < PER; ++i) {
        int n = base + i;
        degs[i] = (n < NN) ? g_deg[set][n] : 0;
        sum += degs[i];
    }
    sh[t] = sum;
    __syncthreads();
    for (int off = 1; off < 1024; off <<= 1) {
        int v = (t >= off) ? sh[t - off] : 0;
        __syncthreads();
        sh[t] += v;
        __syncthreads();
    }
    int run = sh[t] - sum;
    #pragma unroll
    for (int i = 0; i < PER; ++i) {
        int n = base + i;
        if (n < NN) {
            g_indptr[set][n] = run;
            g_cur[set][n]    = run;
            g_dinv[set][n]   = rsqrtf(1.0f + (float)degs[i]);
            run += degs[i];
        }
    }
    if (t == 1023) g_indptr[set][NN] = sh[1023];
}

__global__ void k_fill12(const void* __restrict__ ei) {
    long long idx = (long long)blockIdx.x * blockDim.x + threadIdx.x;
    if (idx >= (long long)TT * EE) return;
    int set = (int)(idx / EE);
    int e   = (int)(idx % EE);
    long long b = (long long)set * 2 * EE;
    int s = load_idx(ei, b + e);
    int d = load_idx(ei, b + EE + e);
    int pos = atomicAdd(&g_cur[set][d], 1);
    g_csrc[set][pos] = s;
    g_cw[set][pos]   = g_dinv[set][s] * g_dinv[set][d];
}

// ---------------- GCN kernels ------------------------------------------------
__device__ __forceinline__ void xw_body(const float* __restrict__ x,
                                        const float* __restrict__ gcn_w,
                                        float* __restrict__ xwout,
                                        int row0) {
    __shared__ float Ws[16 * 128];
    __shared__ float Xs[16 * 16];
    int tid = threadIdx.x;
    #pragma unroll
    for (int i = 0; i < 16; ++i) Ws[i * 128 + tid] = gcn_w[i * 128 + tid];
    #pragma unroll
    for (int j = tid; j < 256; j += 128) Xs[j] = x[row0 * 16 + j];
    __syncthreads();
    #pragma unroll
    for (int r = 0; r < 16; ++r) {
        float acc = 0.f;
        #pragma unroll
        for (int f = 0; f < 16; ++f) acc += Xs[r * 16 + f] * Ws[f * 128 + tid];
        xwout[(row0 + r) * 128 + tid] = acc;
    }
}

__global__ void k_xw_all(const float* __restrict__ x_seq,
                         const float* __restrict__ gcn_w) {
    int set = blockIdx.y;
    xw_body(x_seq + (long long)set * NN * FF, gcn_w,
            &g_xw12[set][0], blockIdx.x * 16);
}

__global__ void k_xw1(const float* __restrict__ x,
                      const float* __restrict__ gcn_w) {
    xw_body(x, gcn_w, g_xw, blockIdx.x * 16);
}

// CSR gather + relu; writes bf16 hi/lo packed output directly
__device__ __forceinline__ void gather_body(int set,
                                            const float* __restrict__ xw,
                                            unsigned* __restrict__ outh,
                                            unsigned* __restrict__ outl,
                                            const float* __restrict__ gcn_b) {
    int warp = (blockIdx.x * blockDim.x + threadIdx.x) >> 5;
    int lane = threadIdx.x & 31;
    if (warp >= NN) return;
    int node = warp;
    int beg = g_indptr[set][node];
    int end = g_indptr[set][node + 1];
    float di = g_dinv[set][node];
    float4 acc = __ldg(reinterpret_cast<const float4*>(xw + node * 128) + lane);
    float d2 = di * di;
    acc.x *= d2; acc.y *= d2; acc.z *= d2; acc.w *= d2;
    int i = beg;
    for (; i + 1 < end; i += 2) {
        int   s0 = g_csrc[set][i],     s1 = g_csrc[set][i + 1];
        float w0 = g_cw[set][i],       w1 = g_cw[set][i + 1];
        float4 u0 = __ldg(reinterpret_cast<const float4*>(xw + s0 * 128) + lane);
        float4 u1 = __ldg(reinterpret_cast<const float4*>(xw + s1 * 128) + lane);
        acc.x += u0.x * w0 + u1.x * w1;
        acc.y += u0.y * w0 + u1.y * w1;
        acc.z += u0.z * w0 + u1.z * w1;
        acc.w += u0.w * w0 + u1.w * w1;
    }
    if (i < end) {
        int   s0 = g_csrc[set][i];
        float w0 = g_cw[set][i];
        float4 u0 = __ldg(reinterpret_cast<const float4*>(xw + s0 * 128) + lane);
        acc.x += u0.x * w0; acc.y += u0.y * w0;
        acc.z += u0.z * w0; acc.w += u0.w * w0;
    }
    float4 b = __ldg(reinterpret_cast<const float4*>(gcn_b) + lane);
    acc.x = fmaxf(acc.x + b.x, 0.f);
    acc.y = fmaxf(acc.y + b.y, 0.f);
    acc.z = fmaxf(acc.z + b.z, 0.f);
    acc.w = fmaxf(acc.w + b.w, 0.f);
    unsigned h0, l0, h1, l1;
    split_pk(acc.x, acc.y, h0, l0);
    split_pk(acc.z, acc.w, h1, l1);
    uint2 uh = {h0, h1}, ul = {l0, l1};
    *reinterpret_cast<uint2*>(outh + node * 64 + lane * 2) = uh;
    *reinterpret_cast<uint2*>(outl + node * 64 + lane * 2) = ul;
}

__global__ void k_gather_all(const float* __restrict__ gcn_b) {
    int set = blockIdx.y;
    gather_body(set, &g_xw12[set][0], &g_hg12h[set][0], &g_hg12l[set][0], gcn_b);
}

__global__ void k_gather1(int set, const float* __restrict__ gcn_b) {
    gather_body(set, g_xw, g_aggh, g_aggl, gcn_b);
}

// ---------------- h_new GEMM: tensor-core bf16 split-precision ---------------
// A inputs pre-packed bf16 hi/lo; D = Ahi*Whi + Ahi*Wlo + Alo*Whi (fp32 acc).
// Block: 128 rows x 128 cols, 8 warps.

__device__ __forceinline__ void mma_bf16(float* c, const unsigned* a,
                                         unsigned b0, unsigned b1) {
    asm volatile(
        "mma.sync.aligned.m16n8k16.row.col.f32.bf16.bf16.f32 "
        "{%0,%1,%2,%3}, {%4,%5,%6,%7}, {%8,%9}, {%0,%1,%2,%3};"
        : "+f"(c[0]), "+f"(c[1]), "+f"(c[2]), "+f"(c[3])
        : "r"(a[0]), "r"(a[1]), "r"(a[2]), "r"(a[3]), "r"(b0), "r"(b1));
}

constexpr int ASTW = 12;   // A smem row stride in 32-bit words (8 data + 4 pad)
constexpr int WST  = 136;  // W smem row stride in words

__global__ void __launch_bounds__(256, 2)
k_hnew(int i1, int i2, int hgsel, int idst, int c0) {
    __shared__ __align__(16) unsigned Ah[2][128 * ASTW];
    __shared__ __align__(16) unsigned Al[2][128 * ASTW];
    __shared__ __align__(16) unsigned Wh[2][8 * WST];
    __shared__ __align__(16) unsigned Wl[2][8 * WST];

    const unsigned* hgh = (hgsel >= 0) ? &g_hg12h[hgsel][0] : g_aggh;
    const unsigned* hgl = (hgsel >= 0) ? &g_hg12l[hgsel][0] : g_aggl;
    const unsigned* h1h = g_hbh[i1];
    const unsigned* h1l = g_hbl[i1];
    const unsigned* h2h = g_hbh[i2];
    const unsigned* h2l = g_hbl[i2];

    int t    = threadIdx.x;
    int w    = t >> 5;
    int l    = t & 31;
    int row0 = blockIdx.x * 128;
    int wr   = w * 16;

    float acc[16][4];
    #pragma unroll
    for (int nt = 0; nt < 16; ++nt)
        #pragma unroll
        for (int j = 0; j < 4; ++j) acc[nt][j] = 0.f;

    // staging thread mapping: A 128 rows x 2 uint4-halves; W 8 rows x 32 uint4
    int arow = t >> 1, ahalf = t & 1;
    int wkk  = t >> 5, wns = l * 4;
    long long agi = (long long)(row0 + arow) * 64 + ahalf * 4;
    bool arow_ok = (row0 + arow) < NN;

    // ---- prologue: stage chunk c0 into buffer 0 ----
    {
        const unsigned* sh_ = (c0 < 8) ? h1h : (c0 < 16) ? h2h : hgh;
        const unsigned* sl_ = (c0 < 8) ? h1l : (c0 < 16) ? h2l : hgl;
        uint4 uh = {0,0,0,0}, ul = {0,0,0,0};
        if (arow_ok) {
            uh = __ldg(reinterpret_cast<const uint4*>(sh_ + agi + (c0 & 7) * 8));
            ul = __ldg(reinterpret_cast<const uint4*>(sl_ + agi + (c0 & 7) * 8));
        }
        *reinterpret_cast<uint4*>(&Ah[0][arow * ASTW + ahalf * 4]) = uh;
        *reinterpret_cast<uint4*>(&Al[0][arow * ASTW + ahalf * 4]) = ul;
        uint4 pwh = __ldg(reinterpret_cast<const uint4*>(&g_Whi_pk[(c0 * 8 + wkk) * 128 + wns]));
        uint4 pwl = __ldg(reinterpret_cast<const uint4*>(&g_Wlo_pk[(c0 * 8 + wkk) * 128 + wns]));
        *reinterpret_cast<uint4*>(&Wh[0][wkk * WST + wns]) = pwh;
        *reinterpret_cast<uint4*>(&Wl[0][wkk * WST + wns]) = pwl;
    }
    __syncthreads();

    int rb = wr + (l >> 2);     // fragment row (local)
    int kw = l & 3;             // fragment k-pair word

    for (int c = c0; c < 24; ++c) {
        int buf = (c - c0) & 1;
        bool has = (c + 1 < 24);

        // ---- prefetch chunk c+1 into registers ----
        uint4 uh = {0,0,0,0}, ul = {0,0,0,0}, pwh, pwl;
        if (has) {
            int cn = c + 1;
            const unsigned* sh_ = (cn < 8) ? h1h : (cn < 16) ? h2h : hgh;
            const unsigned* sl_ = (cn < 8) ? h1l : (cn < 16) ? h2l : hgl;
            if (arow_ok) {
                uh = __ldg(reinterpret_cast<const uint4*>(sh_ + agi + (cn & 7) * 8));
                ul = __ldg(reinterpret_cast<const uint4*>(sl_ + agi + (cn & 7) * 8));
            }
            pwh = __ldg(reinterpret_cast<const uint4*>(&g_Whi_pk[(cn * 8 + wkk) * 128 + wns]));
            pwl = __ldg(reinterpret_cast<const uint4*>(&g_Wlo_pk[(cn * 8 + wkk) * 128 + wns]));
        }

        // ---- compute on buffer buf ----
        const unsigned* ah = &Ah[buf][0];
        const unsigned* al = &Al[buf][0];
        unsigned ahi[4], alo[4];
        ahi[0] = ah[rb * ASTW + kw];
        ahi[1] = ah[(rb + 8) * ASTW + kw];
        ahi[2] = ah[rb * ASTW + 4 + kw];
        ahi[3] = ah[(rb + 8) * ASTW + 4 + kw];
        alo[0] = al[rb * ASTW + kw];
        alo[1] = al[(rb + 8) * ASTW + kw];
        alo[2] = al[rb * ASTW + 4 + kw];
        alo[3] = al[(rb + 8) * ASTW + 4 + kw];
        #pragma unroll
        for (int nt = 0; nt < 16; ++nt) {
            int wb = nt * 8 + (l >> 2);
            unsigned bh0 = Wh[buf][kw * WST + wb];
            unsigned bh1 = Wh[buf][(4 + kw) * WST + wb];
            unsigned bl0 = Wl[buf][kw * WST + wb];
            unsigned bl1 = Wl[buf][(4 + kw) * WST + wb];
            mma_bf16(acc[nt], ahi, bh0, bh1);
            mma_bf16(acc[nt], ahi, bl0, bl1);
            mma_bf16(acc[nt], alo, bh0, bh1);
        }

        // ---- store prefetched chunk into the other buffer ----
        if (has) {
            int nbuf = buf ^ 1;
            *reinterpret_cast<uint4*>(&Ah[nbuf][arow * ASTW + ahalf * 4]) = uh;
            *reinterpret_cast<uint4*>(&Al[nbuf][arow * ASTW + ahalf * 4]) = ul;
            *reinterpret_cast<uint4*>(&Wh[nbuf][wkk * WST + wns]) = pwh;
            *reinterpret_cast<uint4*>(&Wl[nbuf][wkk * WST + wns]) = pwl;
        }
        __syncthreads();
    }

    // ---- epilogue: add bias; write fp32 h_new AND packed bf16 hi/lo ----
    float* dst = g_hb[idst];
    unsigned* dsth = g_hbh[idst];
    unsigned* dstl = g_hbl[idst];
    int cw = 2 * (l & 3);
    int rA = row0 + rb;
    #pragma unroll
    for (int nt = 0; nt < 16; ++nt) {
        int col = nt * 8 + cw;
        float2 dv = *reinterpret_cast<const float2*>(&g_dvec[col]);
        if (rA < NN) {
            float ox = acc[nt][0] + dv.x, oy = acc[nt][1] + dv.y;
            *reinterpret_cast<float2*>(&dst[(long long)rA * 128 + col]) = {ox, oy};
            unsigned hi, lo;
            split_pk(ox, oy, hi, lo);
            dsth[(long long)rA * 64 + col / 2] = hi;
            dstl[(long long)rA * 64 + col / 2] = lo;
        }
        if (rA + 8 < NN) {
            float ox = acc[nt][2] + dv.x, oy = acc[nt][3] + dv.y;
            *reinterpret_cast<float2*>(&dst[(long long)(rA + 8) * 128 + col]) = {ox, oy};
            unsigned hi, lo;
            split_pk(ox, oy, hi, lo);
            dsth[(long long)(rA + 8) * 64 + col / 2] = hi;
            dstl[(long long)(rA + 8) * 64 + col / 2] = lo;
        }
    }
}

// y = h_new @ head_w^T + head_b
__global__ void k_y(int isrc, const float* __restrict__ head_w,
                    const float* __restrict__ head_b,
                    float* __restrict__ out) {
    __shared__ float Hs[16][132];
    __shared__ float Ws[16][132];
    int t    = threadIdx.x;   // 256
    int row0 = blockIdx.x * 16;
    for (int i = t; i < 16 * 128; i += 256) Ws[i >> 7][i & 127] = head_w[i];
    for (int i = t; i < 16 * 128; i += 256) {
        int r = i >> 7;
        Hs[r][i & 127] = g_hb[isrc][(row0 + r) * 128 + (i & 127)];
    }
    __syncthreads();
    int r = t >> 4, c = t & 15;
    float acc = head_b[c];
    #pragma unroll 8
    for (int k = 0; k < 128; ++k) acc += Hs[r][k] * Ws[c][k];
    out[(row0 + r) * 16 + c] = acc;
}

// ---------------------------------------------------------------------------
extern "C" void kernel_launch(void* const* d_in, const int* in_sizes, int n_in,
                              void* d_out, int out_size) {
    const float* x_seq  = (const float*)d_in[0];
    const void*  ei     = d_in[1];
    const float* gcn_w  = (const float*)d_in[5];
    const float* gcn_b  = (const float*)d_in[6];
    const float* conv_w = (const float*)d_in[7];
    const float* conv_b = (const float*)d_in[8];
    const float* proj_w = (const float*)d_in[9];
    const float* proj_b = (const float*)d_in[10];
    const float* head_w = (const float*)d_in[11];
    const float* head_b = (const float*)d_in[12];
    float* out = (float*)d_out;

    // ---- one-time prep ----
    k_detect<<<1, 1>>>((const unsigned int*)ei);
    k_prep_W<<<384, 128>>>(conv_w, proj_w);
    k_prep_d<<<1, 128>>>(conv_b, proj_w, proj_b);
    k_prep_split<<<192, 128>>>();
    k_zero_win<<<(NN * 64 + 255) / 256, 256>>>();
    k_zero_deg12<<<(TT * NN + 255) / 256, 256>>>();
    {
        long long tot = (long long)TT * EE;
        int blocks = (int)((tot + 255) / 256);
        k_count12<<<blocks, 256>>>(ei);
        k_scan12<<<TT, 1024>>>();
        k_fill12<<<blocks, 256>>>(ei);
    }

    // ---- batched encoder GCN (independent of recurrence) ----
    {
        dim3 gx(NN / 16, TT);
        k_xw_all<<<gx, 128>>>(x_seq, gcn_w);
        dim3 gg((NN * 32 + 255) / 256, TT);
        k_gather_all<<<gg, 256>>>(gcn_b);
    }

    // ---- sequential loop ----
    int i1 = 0, i2 = 1, idst = 2;
    for (int t = 0; t < TT + HOR; ++t) {
        bool enc = (t < TT);

        int hgsel;
        if (enc)            hgsel = t;
        else if (t == TT)   hgsel = TT - 1;           // identical GCN to step 11
        else {
            const float* xin = out + (long long)(t - TT - 1) * NN * CC;
            k_xw1<<<NN / 16, 128>>>(xin, gcn_w);
            k_gather1<<<(NN * 32 + 255) / 256, 256>>>(TT - 1, gcn_b);
            hgsel = -1;
        }
        int c0 = (t == 0) ? 16 : (t == 1) ? 8 : 0;    // skip zero window chunks
        k_hnew<<<(NN + 127) / 128, 256>>>(i1, i2, hgsel, idst, c0);
        if (!enc)
            k_y<<<NN / 16, 256>>>(idst, head_w, head_b,
                                  out + (long long)(t - TT) * NN * CC);

        int old1 = i1; i1 = i2; i2 = idst; idst = old1;
    }
}

// round 9
// speedup vs baseline: 1.7947x; 1.0749x over previous
#include <cuda_runtime.h>
#include <cuda_bf16.h>

constexpr int NN  = 20000;   // nodes
constexpr int TT  = 12;      // encoder steps
constexpr int HOR = 6;       // decoder horizon
constexpr int FF  = 16;      // input features (== C, decoder feedback)
constexpr int EE  = 320000;  // edges
constexpr int HH  = 128;     // hidden
constexpr int CC  = 16;      // out channels

// ---------------- scratch (static device globals; no allocation) -----------
__device__ __align__(16) float g_aggx12[TT][NN * FF]; // aggregated inputs, enc
__device__ __align__(16) float g_aggx[NN * FF];       // aggregated inputs, dec
__device__ __align__(16) float g_hb[3][NN * HH];      // window buffers (fp32, k_y)
__device__ __align__(16) float g_W[384 * HH];         // fused [A;B;C] (K x N)
__device__ __align__(16) float g_dvec[HH];            // fused bias vector
__device__ __align__(16) unsigned g_Whi_pk[192 * HH]; // bf16x2-packed hi(W)
__device__ __align__(16) unsigned g_Wlo_pk[192 * HH]; // bf16x2-packed lo(W)

// pre-packed bf16 hi/lo activations
__device__ __align__(16) unsigned g_hg12h[TT][NN * 64];
__device__ __align__(16) unsigned g_hg12l[TT][NN * 64];
__device__ __align__(16) unsigned g_hbh[3][NN * 64];
__device__ __align__(16) unsigned g_hbl[3][NN * 64];
__device__ __align__(16) unsigned g_aggh[NN * 64];
__device__ __align__(16) unsigned g_aggl[NN * 64];
__device__ int   g_is64;

// per-edge-set CSR (built once per launch)
__device__ int   g_deg[TT][NN];
__device__ int   g_indptr[TT][NN + 1];
__device__ int   g_cur[TT][NN];
__device__ float g_dinv[TT][NN];
__device__ int   g_csrc[TT][EE];
__device__ float g_cw[TT][EE];

// ---------------- helpers ----------------------------------------------------
__device__ __forceinline__ unsigned pk_bf(__nv_bfloat16 a, __nv_bfloat16 b) {
    __nv_bfloat162 x; x.x = a; x.y = b;
    return *reinterpret_cast<unsigned*>(&x);
}
__device__ __forceinline__ void split_pk(float a, float b,
                                         unsigned& hi, unsigned& lo) {
    __nv_bfloat16 ha = __float2bfloat16(a);
    __nv_bfloat16 hb = __float2bfloat16(b);
    __nv_bfloat16 la = __float2bfloat16(a - __bfloat162float(ha));
    __nv_bfloat16 lb = __float2bfloat16(b - __bfloat162float(hb));
    hi = pk_bf(ha, hb);
    lo = pk_bf(la, lb);
}

// ---------------- edge-index dtype detection --------------------------------
__global__ void k_detect(const unsigned int* __restrict__ w) {
    int nz = 0;
    #pragma unroll 8
    for (int i = 0; i < 128; ++i) nz += (w[2 * i + 1] != 0u);
    g_is64 = (nz == 0) ? 1 : 0;
}

__device__ __forceinline__ int load_idx(const void* p, long long e) {
    int v;
    if (g_is64) v = (int)((const long long*)p)[e];
    else        v = ((const int*)p)[e];
    v = v < 0 ? 0 : (v >= NN ? NN - 1 : v);
    return v;
}

// ---------------- one-time prep: fold conv_w/proj_w into A,B,C -------------
__global__ void k_prep_W(const float* __restrict__ conv_w,
                         const float* __restrict__ proj_w) {
    __shared__ float w0[128], w1[128], w2[128];
    int c = blockIdx.x;       // 0..383
    int h = threadIdx.x;      // 0..127
    float acc = 0.f;
    if (c < 128) {
        w1[h] = conv_w[((128 + h) * 128 + c) * 3 + 0];
        __syncthreads();
        #pragma unroll 4
        for (int o = 0; o < 128; ++o) acc += w1[o] * proj_w[h * 384 + 128 + o];
    } else if (c < 256) {
        int cc = c - 128;
        w0[h] = conv_w[(h * 128 + cc) * 3 + 0];
        __syncthreads();
        #pragma unroll 4
        for (int o = 0; o < 128; ++o) acc += w0[o] * proj_w[h * 384 + o];
    } else {
        int cc = c - 256;
        w0[h] = conv_w[(h * 128 + cc) * 3 + 1];
        w1[h] = conv_w[((128 + h) * 128 + cc) * 3 + 1];
        w2[h] = conv_w[((256 + h) * 128 + cc) * 3 + 1];
        __syncthreads();
        #pragma unroll 2
        for (int o = 0; o < 128; ++o) {
            acc += w0[o] * proj_w[h * 384 + o]
                 + w1[o] * proj_w[h * 384 + 128 + o]
                 + w2[o] * proj_w[h * 384 + 256 + o];
        }
    }
    g_W[c * 128 + h] = acc;
}

__global__ void k_prep_d(const float* __restrict__ conv_b,
                         const float* __restrict__ proj_w,
                         const float* __restrict__ proj_b) {
    int h = threadIdx.x;
    float acc = proj_b[h];
    #pragma unroll 4
    for (int j = 0; j < 384; ++j) acc += conv_b[j] * proj_w[h * 384 + j];
    g_dvec[h] = acc;
}

__global__ void k_prep_split() {
    int kp = blockIdx.x;      // 0..191
    int n  = threadIdx.x;     // 0..127
    unsigned hi, lo;
    split_pk(g_W[(2 * kp) * 128 + n], g_W[(2 * kp + 1) * 128 + n], hi, lo);
    g_Whi_pk[kp * 128 + n] = hi;
    g_Wlo_pk[kp * 128 + n] = lo;
}

__global__ void k_zero_win() {
    int idx = blockIdx.x * blockDim.x + threadIdx.x;
    if (idx < NN * 64) {
        g_hbh[0][idx] = 0u; g_hbl[0][idx] = 0u;
        g_hbh[1][idx] = 0u; g_hbl[1][idx] = 0u;
    }
}

// ---------------- CSR construction (once per launch) ------------------------
__global__ void k_zero_deg12() {
    int idx = blockIdx.x * blockDim.x + threadIdx.x;
    if (idx < TT * NN) (&g_deg[0][0])[idx] = 0;
}

__global__ void k_count12(const void* __restrict__ ei) {
    long long idx = (long long)blockIdx.x * blockDim.x + threadIdx.x;
    if (idx >= (long long)TT * EE) return;
    int set = (int)(idx / EE);
    int e   = (int)(idx % EE);
    int d = load_idx(ei, (long long)set * 2 * EE + EE + e);
    atomicAdd(&g_deg[set][d], 1);
}

__global__ void k_scan12() {
    __shared__ int sh[1024];
    int set = blockIdx.x;
    int t   = threadIdx.x;
    const int PER = 20;                       // 1024*20 >= NN
    int base = t * PER;
    int degs[PER];
    int sum = 0;
    #pragma unroll
    for (int i = 0; i < PER; ++i) {
        int n = base + i;
        degs[i] = (n < NN) ? g_deg[set][n] : 0;
        sum += degs[i];
    }
    sh[t] = sum;
    __syncthreads();
    for (int off = 1; off < 1024; off <<= 1) {
        int v = (t >= off) ? sh[t - off] : 0;
        __syncthreads();
        sh[t] += v;
        __syncthreads();
    }
    int run = sh[t] - sum;
    #pragma unroll
    for (int i = 0; i < PER; ++i) {
        int n = base + i;
        if (n < NN) {
            g_indptr[set][n] = run;
            g_cur[set][n]    = run;
            g_dinv[set][n]   = rsqrtf(1.0f + (float)degs[i]);
            run += degs[i];
        }
    }
    if (t == 1023) g_indptr[set][NN] = sh[1023];
}

__global__ void k_fill12(const void* __restrict__ ei) {
    long long idx = (long long)blockIdx.x * blockDim.x + threadIdx.x;
    if (idx >= (long long)TT * EE) return;
    int set = (int)(idx / EE);
    int e   = (int)(idx % EE);
    long long b = (long long)set * 2 * EE;
    int s = load_idx(ei, b + e);
    int d = load_idx(ei, b + EE + e);
    int pos = atomicAdd(&g_cur[set][d], 1);
    g_csrc[set][pos] = s;
    g_cw[set][pos]   = g_dinv[set][s] * g_dinv[set][d];
}

// ---------------- GCN stage 1: aggregate 16-dim inputs -----------------------
// aggx[n] = sum_e w_e * x[src_e] + dinv[n]^2 * x[n]        (16 floats per node)
// one warp per node; lanes 0-15 even edges, 16-31 odd edges; shfl-combine.
__device__ __forceinline__ void gx_body(int set, const float* __restrict__ x,
                                        float* __restrict__ out) {
    int warp = (blockIdx.x * blockDim.x + threadIdx.x) >> 5;
    int lane = threadIdx.x & 31;
    if (warp >= NN) return;
    int node = warp;
    int f    = lane & 15;
    int half = lane >> 4;
    int beg = g_indptr[set][node];
    int end = g_indptr[set][node + 1];
    float di = g_dinv[set][node];
    float acc = (half == 0) ? __ldg(&x[node * 16 + f]) * di * di : 0.f;
    for (int i = beg + half; i < end; i += 2) {
        int   s = g_csrc[set][i];
        float w = g_cw[set][i];
        acc += w * __ldg(&x[s * 16 + f]);
    }
    acc += __shfl_down_sync(0xffffffffu, acc, 16);
    if (half == 0) out[node * 16 + f] = acc;
}

__global__ void k_gx_all(const float* __restrict__ x_seq) {
    int set = blockIdx.y;
    gx_body(set, x_seq + (long long)set * NN * FF, &g_aggx12[set][0]);
}

__global__ void k_gx1(int set, const float* __restrict__ x) {
    gx_body(set, x, g_aggx);
}

// ---------------- GCN stage 2: hg = relu(aggx @ gcn_w + b), split+pack -------
// 16 nodes per block, 128 threads (thread = output col)
__device__ __forceinline__ void hgw_body(const float* __restrict__ aggx,
                                         const float* __restrict__ gcn_w,
                                         const float* __restrict__ gcn_b,
                                         unsigned* __restrict__ outh,
                                         unsigned* __restrict__ outl,
                                         int row0) {
    __shared__ float Ws[16 * 128];
    __shared__ float Xs[16 * 16];
    int tid = threadIdx.x;
    #pragma unroll
    for (int i = 0; i < 16; ++i) Ws[i * 128 + tid] = gcn_w[i * 128 + tid];
    #pragma unroll
    for (int j = tid; j < 256; j += 128) Xs[j] = aggx[row0 * 16 + j];
    __syncthreads();
    float b = gcn_b[tid];
    #pragma unroll
    for (int r = 0; r < 16; ++r) {
        float acc = b;
        #pragma unroll
        for (int f = 0; f < 16; ++f) acc += Xs[r * 16 + f] * Ws[f * 128 + tid];
        acc = fmaxf(acc, 0.f);
        float vo = __shfl_xor_sync(0xffffffffu, acc, 1);
        if (!(tid & 1)) {
            unsigned hi, lo;
            split_pk(acc, vo, hi, lo);
            outh[(row0 + r) * 64 + (tid >> 1)] = hi;
            outl[(row0 + r) * 64 + (tid >> 1)] = lo;
        }
    }
}

__global__ void k_hgw_all(const float* __restrict__ gcn_w,
                          const float* __restrict__ gcn_b) {
    int set = blockIdx.y;
    hgw_body(&g_aggx12[set][0], gcn_w, gcn_b,
             &g_hg12h[set][0], &g_hg12l[set][0], blockIdx.x * 16);
}

__global__ void k_hgw1(const float* __restrict__ gcn_w,
                       const float* __restrict__ gcn_b) {
    hgw_body(g_aggx, gcn_w, gcn_b, g_aggh, g_aggl, blockIdx.x * 16);
}

// ---------------- h_new GEMM: tensor-core bf16 split-precision ---------------
__device__ __forceinline__ void mma_bf16(float* c, const unsigned* a,
                                         unsigned b0, unsigned b1) {
    asm volatile(
        "mma.sync.aligned.m16n8k16.row.col.f32.bf16.bf16.f32 "
        "{%0,%1,%2,%3}, {%4,%5,%6,%7}, {%8,%9}, {%0,%1,%2,%3};"
        : "+f"(c[0]), "+f"(c[1]), "+f"(c[2]), "+f"(c[3])
        : "r"(a[0]), "r"(a[1]), "r"(a[2]), "r"(a[3]), "r"(b0), "r"(b1));
}

constexpr int ASTW = 12;   // A smem row stride in words (8 data + 4 pad)
constexpr int WST  = 136;  // W smem row stride in words

__global__ void __launch_bounds__(256, 2)
k_hnew(int i1, int i2, int hgsel, int idst, int c0) {
    __shared__ __align__(16) unsigned Ah[2][128 * ASTW];
    __shared__ __align__(16) unsigned Al[2][128 * ASTW];
    __shared__ __align__(16) unsigned Wh[2][8 * WST];
    __shared__ __align__(16) unsigned Wl[2][8 * WST];

    const unsigned* hgh = (hgsel >= 0) ? &g_hg12h[hgsel][0] : g_aggh;
    const unsigned* hgl = (hgsel >= 0) ? &g_hg12l[hgsel][0] : g_aggl;
    const unsigned* h1h = g_hbh[i1];
    const unsigned* h1l = g_hbl[i1];
    const unsigned* h2h = g_hbh[i2];
    const unsigned* h2l = g_hbl[i2];

    int t    = threadIdx.x;
    int w    = t >> 5;
    int l    = t & 31;
    int row0 = blockIdx.x * 128;
    int wr   = w * 16;

    float acc[16][4];
    #pragma unroll
    for (int nt = 0; nt < 16; ++nt)
        #pragma unroll
        for (int j = 0; j < 4; ++j) acc[nt][j] = 0.f;

    int arow = t >> 1, ahalf = t & 1;
    int wkk  = t >> 5, wns = l * 4;
    long long agi = (long long)(row0 + arow) * 64 + ahalf * 4;
    bool arow_ok = (row0 + arow) < NN;

    {
        const unsigned* sh_ = (c0 < 8) ? h1h : (c0 < 16) ? h2h : hgh;
        const unsigned* sl_ = (c0 < 8) ? h1l : (c0 < 16) ? h2l : hgl;
        uint4 uh = {0,0,0,0}, ul = {0,0,0,0};
        if (arow_ok) {
            uh = __ldg(reinterpret_cast<const uint4*>(sh_ + agi + (c0 & 7) * 8));
            ul = __ldg(reinterpret_cast<const uint4*>(sl_ + agi + (c0 & 7) * 8));
        }
        *reinterpret_cast<uint4*>(&Ah[0][arow * ASTW + ahalf * 4]) = uh;
        *reinterpret_cast<uint4*>(&Al[0][arow * ASTW + ahalf * 4]) = ul;
        uint4 pwh = __ldg(reinterpret_cast<const uint4*>(&g_Whi_pk[(c0 * 8 + wkk) * 128 + wns]));
        uint4 pwl = __ldg(reinterpret_cast<const uint4*>(&g_Wlo_pk[(c0 * 8 + wkk) * 128 + wns]));
        *reinterpret_cast<uint4*>(&Wh[0][wkk * WST + wns]) = pwh;
        *reinterpret_cast<uint4*>(&Wl[0][wkk * WST + wns]) = pwl;
    }
    __syncthreads();

    int rb = wr + (l >> 2);
    int kw = l & 3;

    for (int c = c0; c < 24; ++c) {
        int buf = (c - c0) & 1;
        bool has = (c + 1 < 24);

        uint4 uh = {0,0,0,0}, ul = {0,0,0,0}, pwh, pwl;
        if (has) {
            int cn = c + 1;
            const unsigned* sh_ = (cn < 8) ? h1h : (cn < 16) ? h2h : hgh;
            const unsigned* sl_ = (cn < 8) ? h1l : (cn < 16) ? h2l : hgl;
            if (arow_ok) {
                uh = __ldg(reinterpret_cast<const uint4*>(sh_ + agi + (cn & 7) * 8));
                ul = __ldg(reinterpret_cast<const uint4*>(sl_ + agi + (cn & 7) * 8));
            }
            pwh = __ldg(reinterpret_cast<const uint4*>(&g_Whi_pk[(cn * 8 + wkk) * 128 + wns]));
            pwl = __ldg(reinterpret_cast<const uint4*>(&g_Wlo_pk[(cn * 8 + wkk) * 128 + wns]));
        }

        const unsigned* ah = &Ah[buf][0];
        const unsigned* al = &Al[buf][0];
        unsigned ahi[4], alo[4];
        ahi[0] = ah[rb * ASTW + kw];
        ahi[1] = ah[(rb + 8) * ASTW + kw];
        ahi[2] = ah[rb * ASTW + 4 + kw];
        ahi[3] = ah[(rb + 8) * ASTW + 4 + kw];
        alo[0] = al[rb * ASTW + kw];
        alo[1] = al[(rb + 8) * ASTW + kw];
        alo[2] = al[rb * ASTW + 4 + kw];
        alo[3] = al[(rb + 8) * ASTW + 4 + kw];
        #pragma unroll
        for (int nt = 0; nt < 16; ++nt) {
            int wb = nt * 8 + (l >> 2);
            unsigned bh0 = Wh[buf][kw * WST + wb];
            unsigned bh1 = Wh[buf][(4 + kw) * WST + wb];
            unsigned bl0 = Wl[buf][kw * WST + wb];
            unsigned bl1 = Wl[buf][(4 + kw) * WST + wb];
            mma_bf16(acc[nt], ahi, bh0, bh1);
            mma_bf16(acc[nt], ahi, bl0, bl1);
            mma_bf16(acc[nt], alo, bh0, bh1);
        }

        if (has) {
            int nbuf = buf ^ 1;
            *reinterpret_cast<uint4*>(&Ah[nbuf][arow * ASTW + ahalf * 4]) = uh;
            *reinterpret_cast<uint4*>(&Al[nbuf][arow * ASTW + ahalf * 4]) = ul;
            *reinterpret_cast<uint4*>(&Wh[nbuf][wkk * WST + wns]) = pwh;
            *reinterpret_cast<uint4*>(&Wl[nbuf][wkk * WST + wns]) = pwl;
        }
        __syncthreads();
    }

    float* dst = g_hb[idst];
    unsigned* dsth = g_hbh[idst];
    unsigned* dstl = g_hbl[idst];
    int cw = 2 * (l & 3);
    int rA = row0 + rb;
    #pragma unroll
    for (int nt = 0; nt < 16; ++nt) {
        int col = nt * 8 + cw;
        float2 dv = *reinterpret_cast<const float2*>(&g_dvec[col]);
        if (rA < NN) {
            float ox = acc[nt][0] + dv.x, oy = acc[nt][1] + dv.y;
            *reinterpret_cast<float2*>(&dst[(long long)rA * 128 + col]) = {ox, oy};
            unsigned hi, lo;
            split_pk(ox, oy, hi, lo);
            dsth[(long long)rA * 64 + col / 2] = hi;
            dstl[(long long)rA * 64 + col / 2] = lo;
        }
        if (rA + 8 < NN) {
            float ox = acc[nt][2] + dv.x, oy = acc[nt][3] + dv.y;
            *reinterpret_cast<float2*>(&dst[(long long)(rA + 8) * 128 + col]) = {ox, oy};
            unsigned hi, lo;
            split_pk(ox, oy, hi, lo);
            dsth[(long long)(rA + 8) * 64 + col / 2] = hi;
            dstl[(long long)(rA + 8) * 64 + col / 2] = lo;
        }
    }
}

// y = h_new @ head_w^T + head_b
__global__ void k_y(int isrc, const float* __restrict__ head_w,
                    const float* __restrict__ head_b,
                    float* __restrict__ out) {
    __shared__ float Hs[16][132];
    __shared__ float Ws[16][132];
    int t    = threadIdx.x;   // 256
    int row0 = blockIdx.x * 16;
    for (int i = t; i < 16 * 128; i += 256) Ws[i >> 7][i & 127] = head_w[i];
    for (int i = t; i < 16 * 128; i += 256) {
        int r = i >> 7;
        Hs[r][i & 127] = g_hb[isrc][(row0 + r) * 128 + (i & 127)];
    }
    __syncthreads();
    int r = t >> 4, c = t & 15;
    float acc = head_b[c];
    #pragma unroll 8
    for (int k = 0; k < 128; ++k) acc += Hs[r][k] * Ws[c][k];
    out[(row0 + r) * 16 + c] = acc;
}

// ---------------------------------------------------------------------------
extern "C" void kernel_launch(void* const* d_in, const int* in_sizes, int n_in,
                              void* d_out, int out_size) {
    const float* x_seq  = (const float*)d_in[0];
    const void*  ei     = d_in[1];
    const float* gcn_w  = (const float*)d_in[5];
    const float* gcn_b  = (const float*)d_in[6];
    const float* conv_w = (const float*)d_in[7];
    const float* conv_b = (const float*)d_in[8];
    const float* proj_w = (const float*)d_in[9];
    const float* proj_b = (const float*)d_in[10];
    const float* head_w = (const float*)d_in[11];
    const float* head_b = (const float*)d_in[12];
    float* out = (float*)d_out;

    // ---- one-time prep ----
    k_detect<<<1, 1>>>((const unsigned int*)ei);
    k_prep_W<<<384, 128>>>(conv_w, proj_w);
    k_prep_d<<<1, 128>>>(conv_b, proj_w, proj_b);
    k_prep_split<<<192, 128>>>();
    k_zero_win<<<(NN * 64 + 255) / 256, 256>>>();
    k_zero_deg12<<<(TT * NN + 255) / 256, 256>>>();
    {
        long long tot = (long long)TT * EE;
        int blocks = (int)((tot + 255) / 256);
        k_count12<<<blocks, 256>>>(ei);
        k_scan12<<<TT, 1024>>>();
        k_fill12<<<blocks, 256>>>(ei);
    }

    // ---- batched encoder GCN: aggregate 16-dim inputs, then weight multiply
    {
        dim3 gg((NN * 32 + 255) / 256, TT);
        k_gx_all<<<gg, 256>>>(x_seq);
        dim3 gh(NN / 16, TT);
        k_hgw_all<<<gh, 128>>>(gcn_w, gcn_b);
    }

    // ---- sequential loop ----
    int i1 = 0, i2 = 1, idst = 2;
    for (int t = 0; t < TT + HOR; ++t) {
        bool enc = (t < TT);

        int hgsel;
        if (enc)            hgsel = t;
        else if (t == TT)   hgsel = TT - 1;           // identical GCN to step 11
        else {
            const float* xin = out + (long long)(t - TT - 1) * NN * CC;
            k_gx1<<<(NN * 32 + 255) / 256, 256>>>(TT - 1, xin);
            k_hgw1<<<NN / 16, 128>>>(gcn_w, gcn_b);
            hgsel = -1;
        }
        int c0 = (t == 0) ? 16 : (t == 1) ? 8 : 0;    // skip zero window chunks
        k_hnew<<<(NN + 127) / 128, 256>>>(i1, i2, hgsel, idst, c0);
        if (!enc)
            k_y<<<NN / 16, 256>>>(idst, head_w, head_b,
                                  out + (long long)(t - TT) * NN * CC);

        int old1 = i1; i1 = i2; i2 = idst; idst = old1;
    }
}

// round 10
// speedup vs baseline: 2.0835x; 1.1609x over previous
#include <cuda_runtime.h>
#include <cuda_bf16.h>

constexpr int NN  = 20000;   // nodes
constexpr int TT  = 12;      // encoder steps
constexpr int HOR = 6;       // decoder horizon
constexpr int FF  = 16;      // input features (== C, decoder feedback)
constexpr int EE  = 320000;  // edges
constexpr int HH  = 128;     // hidden
constexpr int CC  = 16;      // out channels

// ---------------- scratch (static device globals; no allocation) -----------
__device__ __align__(16) float g_dvec[HH];            // fused bias vector
__device__ __align__(16) unsigned g_Whi_pk[192 * HH]; // bf16x2-packed hi(W)
__device__ __align__(16) unsigned g_Wlo_pk[192 * HH]; // bf16x2-packed lo(W)

// pre-packed bf16 hi/lo activations
__device__ __align__(16) unsigned g_hg12h[TT][NN * 64];
__device__ __align__(16) unsigned g_hg12l[TT][NN * 64];
__device__ __align__(16) unsigned g_hbh[3][NN * 64];
__device__ __align__(16) unsigned g_hbl[3][NN * 64];
__device__ __align__(16) unsigned g_aggh[NN * 64];
__device__ __align__(16) unsigned g_aggl[NN * 64];
__device__ int   g_is64;

// per-edge-set CSR (built once per launch)
__device__ int   g_deg[TT][NN];
__device__ int   g_indptr[TT][NN + 1];
__device__ int   g_cur[TT][NN];
__device__ float g_dinv[TT][NN];
__device__ int   g_csrc[TT][EE];
__device__ float g_cw[TT][EE];

// ---------------- helpers ----------------------------------------------------
__device__ __forceinline__ unsigned pk_bf(__nv_bfloat16 a, __nv_bfloat16 b) {
    __nv_bfloat162 x; x.x = a; x.y = b;
    return *reinterpret_cast<unsigned*>(&x);
}
__device__ __forceinline__ void split_pk(float a, float b,
                                         unsigned& hi, unsigned& lo) {
    __nv_bfloat16 ha = __float2bfloat16(a);
    __nv_bfloat16 hb = __float2bfloat16(b);
    __nv_bfloat16 la = __float2bfloat16(a - __bfloat162float(ha));
    __nv_bfloat16 lb = __float2bfloat16(b - __bfloat162float(hb));
    hi = pk_bf(ha, hb);
    lo = pk_bf(la, lb);
}

__device__ __forceinline__ int load_idx(const void* p, long long e) {
    int v;
    if (g_is64) v = (int)((const long long*)p)[e];
    else        v = ((const int*)p)[e];
    v = v < 0 ? 0 : (v >= NN ? NN - 1 : v);
    return v;
}

// ---------------- launch 1: detect dtype + zero degree arrays ---------------
__global__ void k_init(const unsigned* __restrict__ w) {
    long long idx = (long long)blockIdx.x * blockDim.x + threadIdx.x;
    if (idx < (long long)TT * NN) (&g_deg[0][0])[idx] = 0;
    if (idx == 0) {
        int nz = 0;
        #pragma unroll 8
        for (int i = 0; i < 128; ++i) nz += (w[2 * i + 1] != 0u);
        g_is64 = (nz == 0) ? 1 : 0;
    }
}

// ---------------- launch 2: fold conv/proj -> W, split to bf16, dvec --------
__global__ void k_prepWsd(const float* __restrict__ conv_w,
                          const float* __restrict__ proj_w,
                          const float* __restrict__ conv_b,
                          const float* __restrict__ proj_b) {
    int h = threadIdx.x;
    if (blockIdx.x == 192) {             // dvec
        float acc = proj_b[h];
        #pragma unroll 4
        for (int j = 0; j < 384; ++j) acc += conv_b[j] * proj_w[h * 384 + j];
        g_dvec[h] = acc;
        return;
    }
    __shared__ float wa[6][128];
    int kp = blockIdx.x;                 // 0..191
    int c0 = 2 * kp, c1 = c0 + 1;
    float a0 = 0.f, a1 = 0.f;
    if (c0 < 128) {
        wa[0][h] = conv_w[((128 + h) * 128 + c0) * 3 + 0];
        wa[1][h] = conv_w[((128 + h) * 128 + c1) * 3 + 0];
        __syncthreads();
        #pragma unroll 4
        for (int o = 0; o < 128; ++o) {
            float p = proj_w[h * 384 + 128 + o];
            a0 += wa[0][o] * p; a1 += wa[1][o] * p;
        }
    } else if (c0 < 256) {
        int cc0 = c0 - 128, cc1 = c1 - 128;
        wa[0][h] = conv_w[(h * 128 + cc0) * 3 + 0];
        wa[1][h] = conv_w[(h * 128 + cc1) * 3 + 0];
        __syncthreads();
        #pragma unroll 4
        for (int o = 0; o < 128; ++o) {
            float p = proj_w[h * 384 + o];
            a0 += wa[0][o] * p; a1 += wa[1][o] * p;
        }
    } else {
        int cc0 = c0 - 256, cc1 = c1 - 256;
        wa[0][h] = conv_w[(h * 128 + cc0) * 3 + 1];
        wa[1][h] = conv_w[((128 + h) * 128 + cc0) * 3 + 1];
        wa[2][h] = conv_w[((256 + h) * 128 + cc0) * 3 + 1];
        wa[3][h] = conv_w[(h * 128 + cc1) * 3 + 1];
        wa[4][h] = conv_w[((128 + h) * 128 + cc1) * 3 + 1];
        wa[5][h] = conv_w[((256 + h) * 128 + cc1) * 3 + 1];
        __syncthreads();
        #pragma unroll 2
        for (int o = 0; o < 128; ++o) {
            float p0 = proj_w[h * 384 + o];
            float p1 = proj_w[h * 384 + 128 + o];
            float p2 = proj_w[h * 384 + 256 + o];
            a0 += wa[0][o] * p0 + wa[1][o] * p1 + wa[2][o] * p2;
            a1 += wa[3][o] * p0 + wa[4][o] * p1 + wa[5][o] * p2;
        }
    }
    unsigned hi, lo;
    split_pk(a0, a1, hi, lo);
    g_Whi_pk[kp * 128 + h] = hi;
    g_Wlo_pk[kp * 128 + h] = lo;
}

// ---------------- CSR construction (launches 3-5) ----------------------------
__global__ void k_count12(const void* __restrict__ ei) {
    long long idx = (long long)blockIdx.x * blockDim.x + threadIdx.x;
    if (idx >= (long long)TT * EE) return;
    int set = (int)(idx / EE);
    int e   = (int)(idx % EE);
    int d = load_idx(ei, (long long)set * 2 * EE + EE + e);
    atomicAdd(&g_deg[set][d], 1);
}

__global__ void k_scan12() {
    __shared__ int sh[1024];
    int set = blockIdx.x;
    int t   = threadIdx.x;
    const int PER = 20;                       // 1024*20 >= NN
    int base = t * PER;
    int degs[PER];
    int sum = 0;
    #pragma unroll
    for (int i = 0; i < PER; ++i) {
        int n = base + i;
        degs[i] = (n < NN) ? g_deg[set][n] : 0;
        sum += degs[i];
    }
    sh[t] = sum;
    __syncthreads();
    for (int off = 1; off < 1024; off <<= 1) {
        int v = (t >= off) ? sh[t - off] : 0;
        __syncthreads();
        sh[t] += v;
        __syncthreads();
    }
    int run = sh[t] - sum;
    #pragma unroll
    for (int i = 0; i < PER; ++i) {
        int n = base + i;
        if (n < NN) {
            g_indptr[set][n] = run;
            g_cur[set][n]    = run;
            g_dinv[set][n]   = rsqrtf(1.0f + (float)degs[i]);
            run += degs[i];
        }
    }
    if (t == 1023) g_indptr[set][NN] = sh[1023];
}

__global__ void k_fill12(const void* __restrict__ ei) {
    long long idx = (long long)blockIdx.x * blockDim.x + threadIdx.x;
    if (idx >= (long long)TT * EE) return;
    int set = (int)(idx / EE);
    int e   = (int)(idx % EE);
    long long b = (long long)set * 2 * EE;
    int s = load_idx(ei, b + e);
    int d = load_idx(ei, b + EE + e);
    int pos = atomicAdd(&g_cur[set][d], 1);
    g_csrc[set][pos] = s;
    g_cw[set][pos]   = g_dinv[set][s] * g_dinv[set][d];
}

// ---------------- fused GCN: aggregate -> weight multiply -> split+pack ------
// block = 16 nodes, 128 threads. Phase1: each node served by 8 lanes
// (2 features each). Phase2: thread = output col.
__device__ __forceinline__ void gcn_body(const float* __restrict__ x, int set,
                                         unsigned* __restrict__ outh,
                                         unsigned* __restrict__ outl,
                                         const float* __restrict__ gcn_w,
                                         const float* __restrict__ gcn_b,
                                         int row0) {
    __shared__ float Xs[16 * 16];
    __shared__ float Ws[16 * 128];
    int tid = threadIdx.x;
    #pragma unroll
    for (int i = 0; i < 16; ++i) Ws[i * 128 + tid] = gcn_w[i * 128 + tid];

    int lane   = tid & 31;
    int nlocal = (tid >> 5) * 4 + (lane >> 3);   // 0..15
    int f2     = lane & 7;                        // feature pair
    int node   = row0 + nlocal;
    float di = g_dinv[set][node];
    float2 acc = *reinterpret_cast<const float2*>(&x[node * 16 + 2 * f2]);
    float d2 = di * di;
    acc.x *= d2; acc.y *= d2;
    int beg = g_indptr[set][node], end = g_indptr[set][node + 1];
    for (int i = beg; i < end; ++i) {
        int   s  = g_csrc[set][i];
        float wt = g_cw[set][i];
        float2 u = *reinterpret_cast<const float2*>(&x[s * 16 + 2 * f2]);
        acc.x += wt * u.x; acc.y += wt * u.y;
    }
    Xs[nlocal * 16 + 2 * f2]     = acc.x;
    Xs[nlocal * 16 + 2 * f2 + 1] = acc.y;
    __syncthreads();

    float b = gcn_b[tid];
    #pragma unroll
    for (int r = 0; r < 16; ++r) {
        float a = b;
        #pragma unroll
        for (int f = 0; f < 16; ++f) a += Xs[r * 16 + f] * Ws[f * 128 + tid];
        a = fmaxf(a, 0.f);
        float vo = __shfl_xor_sync(0xffffffffu, a, 1);
        if (!(tid & 1)) {
            unsigned hi, lo;
            split_pk(a, vo, hi, lo);
            outh[(row0 + r) * 64 + (tid >> 1)] = hi;
            outl[(row0 + r) * 64 + (tid >> 1)] = lo;
        }
    }
}

__global__ void k_gcn_all(const float* __restrict__ x_seq,
                          const float* __restrict__ gcn_w,
                          const float* __restrict__ gcn_b) {
    int set = blockIdx.y;
    gcn_body(x_seq + (long long)set * NN * FF, set,
             &g_hg12h[set][0], &g_hg12l[set][0], gcn_w, gcn_b, blockIdx.x * 16);
}

__global__ void k_gcn1(const float* __restrict__ x,
                       const float* __restrict__ gcn_w,
                       const float* __restrict__ gcn_b) {
    gcn_body(x, TT - 1, g_aggh, g_aggl, gcn_w, gcn_b, blockIdx.x * 16);
}

// ---------------- h_new GEMM + fused y head ----------------------------------
__device__ __forceinline__ void mma_bf16(float* c, const unsigned* a,
                                         unsigned b0, unsigned b1) {
    asm volatile(
        "mma.sync.aligned.m16n8k16.row.col.f32.bf16.bf16.f32 "
        "{%0,%1,%2,%3}, {%4,%5,%6,%7}, {%8,%9}, {%0,%1,%2,%3};"
        : "+f"(c[0]), "+f"(c[1]), "+f"(c[2]), "+f"(c[3])
        : "r"(a[0]), "r"(a[1]), "r"(a[2]), "r"(a[3]), "r"(b0), "r"(b1));
}

constexpr int ASTW = 12;   // A smem row stride in words (8 data + 4 pad)
constexpr int WST  = 136;  // W smem row stride in words

__global__ void __launch_bounds__(256, 2)
k_hnew(int i1, int i2, int hgsel, int idst, int c0, int do_y,
       const float* __restrict__ head_w, const float* __restrict__ head_b,
       float* __restrict__ outy) {
    __shared__ __align__(16) unsigned Ah[2][128 * ASTW];
    __shared__ __align__(16) unsigned Al[2][128 * ASTW];
    __shared__ __align__(16) unsigned Wh[2][8 * WST];
    __shared__ __align__(16) unsigned Wl[2][8 * WST];

    const unsigned* hgh = (hgsel >= 0) ? &g_hg12h[hgsel][0] : g_aggh;
    const unsigned* hgl = (hgsel >= 0) ? &g_hg12l[hgsel][0] : g_aggl;
    const unsigned* h1h = g_hbh[i1];
    const unsigned* h1l = g_hbl[i1];
    const unsigned* h2h = g_hbh[i2];
    const unsigned* h2l = g_hbl[i2];

    int t    = threadIdx.x;
    int w    = t >> 5;
    int l    = t & 31;
    int row0 = blockIdx.x * 128;
    int wr   = w * 16;

    float acc[16][4];
    #pragma unroll
    for (int nt = 0; nt < 16; ++nt)
        #pragma unroll
        for (int j = 0; j < 4; ++j) acc[nt][j] = 0.f;

    int arow = t >> 1, ahalf = t & 1;
    int wkk  = t >> 5, wns = l * 4;
    long long agi = (long long)(row0 + arow) * 64 + ahalf * 4;
    bool arow_ok = (row0 + arow) < NN;

    {
        const unsigned* sh_ = (c0 < 8) ? h1h : (c0 < 16) ? h2h : hgh;
        const unsigned* sl_ = (c0 < 8) ? h1l : (c0 < 16) ? h2l : hgl;
        uint4 uh = {0,0,0,0}, ul = {0,0,0,0};
        if (arow_ok) {
            uh = __ldg(reinterpret_cast<const uint4*>(sh_ + agi + (c0 & 7) * 8));
            ul = __ldg(reinterpret_cast<const uint4*>(sl_ + agi + (c0 & 7) * 8));
        }
        *reinterpret_cast<uint4*>(&Ah[0][arow * ASTW + ahalf * 4]) = uh;
        *reinterpret_cast<uint4*>(&Al[0][arow * ASTW + ahalf * 4]) = ul;
        uint4 pwh = __ldg(reinterpret_cast<const uint4*>(&g_Whi_pk[(c0 * 8 + wkk) * 128 + wns]));
        uint4 pwl = __ldg(reinterpret_cast<const uint4*>(&g_Wlo_pk[(c0 * 8 + wkk) * 128 + wns]));
        *reinterpret_cast<uint4*>(&Wh[0][wkk * WST + wns]) = pwh;
        *reinterpret_cast<uint4*>(&Wl[0][wkk * WST + wns]) = pwl;
    }
    __syncthreads();

    int rb = wr + (l >> 2);
    int kw = l & 3;

    for (int c = c0; c < 24; ++c) {
        int buf = (c - c0) & 1;
        bool has = (c + 1 < 24);

        uint4 uh = {0,0,0,0}, ul = {0,0,0,0}, pwh, pwl;
        if (has) {
            int cn = c + 1;
            const unsigned* sh_ = (cn < 8) ? h1h : (cn < 16) ? h2h : hgh;
            const unsigned* sl_ = (cn < 8) ? h1l : (cn < 16) ? h2l : hgl;
            if (arow_ok) {
                uh = __ldg(reinterpret_cast<const uint4*>(sh_ + agi + (cn & 7) * 8));
                ul = __ldg(reinterpret_cast<const uint4*>(sl_ + agi + (cn & 7) * 8));
            }
            pwh = __ldg(reinterpret_cast<const uint4*>(&g_Whi_pk[(cn * 8 + wkk) * 128 + wns]));
            pwl = __ldg(reinterpret_cast<const uint4*>(&g_Wlo_pk[(cn * 8 + wkk) * 128 + wns]));
        }

        const unsigned* ah = &Ah[buf][0];
        const unsigned* al = &Al[buf][0];
        unsigned ahi[4], alo[4];
        ahi[0] = ah[rb * ASTW + kw];
        ahi[1] = ah[(rb + 8) * ASTW + kw];
        ahi[2] = ah[rb * ASTW + 4 + kw];
        ahi[3] = ah[(rb + 8) * ASTW + 4 + kw];
        alo[0] = al[rb * ASTW + kw];
        alo[1] = al[(rb + 8) * ASTW + kw];
        alo[2] = al[rb * ASTW + 4 + kw];
        alo[3] = al[(rb + 8) * ASTW + 4 + kw];
        #pragma unroll
        for (int nt = 0; nt < 16; ++nt) {
            int wb = nt * 8 + (l >> 2);
            unsigned bh0 = Wh[buf][kw * WST + wb];
            unsigned bh1 = Wh[buf][(4 + kw) * WST + wb];
            unsigned bl0 = Wl[buf][kw * WST + wb];
            unsigned bl1 = Wl[buf][(4 + kw) * WST + wb];
            mma_bf16(acc[nt], ahi, bh0, bh1);
            mma_bf16(acc[nt], ahi, bl0, bl1);
            mma_bf16(acc[nt], alo, bh0, bh1);
        }

        if (has) {
            int nbuf = buf ^ 1;
            *reinterpret_cast<uint4*>(&Ah[nbuf][arow * ASTW + ahalf * 4]) = uh;
            *reinterpret_cast<uint4*>(&Al[nbuf][arow * ASTW + ahalf * 4]) = ul;
            *reinterpret_cast<uint4*>(&Wh[nbuf][wkk * WST + wns]) = pwh;
            *reinterpret_cast<uint4*>(&Wl[nbuf][wkk * WST + wns]) = pwl;
        }
        __syncthreads();
    }

    // ---- epilogue: bias into acc; store packed bf16 hi/lo; optional y ----
    unsigned* dsth = g_hbh[idst];
    unsigned* dstl = g_hbl[idst];
    int cw = 2 * (l & 3);
    int rA = row0 + rb;
    #pragma unroll
    for (int nt = 0; nt < 16; ++nt) {
        int col = nt * 8 + cw;
        float2 dv = *reinterpret_cast<const float2*>(&g_dvec[col]);
        acc[nt][0] += dv.x; acc[nt][1] += dv.y;
        acc[nt][2] += dv.x; acc[nt][3] += dv.y;
        unsigned hi, lo;
        if (rA < NN) {
            split_pk(acc[nt][0], acc[nt][1], hi, lo);
            dsth[(long long)rA * 64 + col / 2] = hi;
            dstl[(long long)rA * 64 + col / 2] = lo;
        }
        if (rA + 8 < NN) {
            split_pk(acc[nt][2], acc[nt][3], hi, lo);
            dsth[(long long)(rA + 8) * 64 + col / 2] = hi;
            dstl[(long long)(rA + 8) * 64 + col / 2] = lo;
        }
    }

    if (do_y) {
        // reuse dead A-tile smem for head_w (16x128 fp32 = 8KB)
        float* Hw = reinterpret_cast<float*>(&Ah[0][0]);
        for (int i = t; i < 16 * 128; i += 256) Hw[i] = head_w[i];
        __syncthreads();
        #pragma unroll
        for (int ch = 0; ch < 16; ++ch) {
            float s0 = 0.f, s1 = 0.f;
            #pragma unroll
            for (int nt = 0; nt < 16; ++nt) {
                int col = nt * 8 + cw;
                float w0 = Hw[ch * 128 + col], w1 = Hw[ch * 128 + col + 1];
                s0 += acc[nt][0] * w0 + acc[nt][1] * w1;
                s1 += acc[nt][2] * w0 + acc[nt][3] * w1;
            }
            s0 += __shfl_xor_sync(0xffffffffu, s0, 1);
            s0 += __shfl_xor_sync(0xffffffffu, s0, 2);
            s1 += __shfl_xor_sync(0xffffffffu, s1, 1);
            s1 += __shfl_xor_sync(0xffffffffu, s1, 2);
            if ((l & 3) == 0) {
                float hb = __ldg(&head_b[ch]);
                if (rA < NN)     outy[(long long)rA * 16 + ch] = s0 + hb;
                if (rA + 8 < NN) outy[(long long)(rA + 8) * 16 + ch] = s1 + hb;
            }
        }
    }
}

// ---------------------------------------------------------------------------
extern "C" void kernel_launch(void* const* d_in, const int* in_sizes, int n_in,
                              void* d_out, int out_size) {
    const float* x_seq  = (const float*)d_in[0];
    const void*  ei     = d_in[1];
    const float* gcn_w  = (const float*)d_in[5];
    const float* gcn_b  = (const float*)d_in[6];
    const float* conv_w = (const float*)d_in[7];
    const float* conv_b = (const float*)d_in[8];
    const float* proj_w = (const float*)d_in[9];
    const float* proj_b = (const float*)d_in[10];
    const float* head_w = (const float*)d_in[11];
    const float* head_b = (const float*)d_in[12];
    float* out = (float*)d_out;

    // launches 1-5: init, prep, CSR
    k_init<<<(TT * NN + 255) / 256, 256>>>((const unsigned*)ei);
    k_prepWsd<<<193, 128>>>(conv_w, proj_w, conv_b, proj_b);
    {
        long long tot = (long long)TT * EE;
        int blocks = (int)((tot + 255) / 256);
        k_count12<<<blocks, 256>>>(ei);
        k_scan12<<<TT, 1024>>>();
        k_fill12<<<blocks, 256>>>(ei);
    }

    // launch 6: all 12 encoder GCNs (fused aggregate+multiply)
    {
        dim3 gg(NN / 16, TT);
        k_gcn_all<<<gg, 128>>>(x_seq, gcn_w, gcn_b);
    }

    // sequential loop
    int i1 = 0, i2 = 1, idst = 2;
    for (int t = 0; t < TT + HOR; ++t) {
        bool enc = (t < TT);

        int hgsel;
        float* outy = out;
        if (enc)            hgsel = t;
        else if (t == TT) { hgsel = TT - 1; outy = out; }      // identical GCN
        else {
            const float* xin = out + (long long)(t - TT - 1) * NN * CC;
            k_gcn1<<<NN / 16, 128>>>(xin, gcn_w, gcn_b);
            hgsel = -1;
            outy = out + (long long)(t - TT) * NN * CC;
        }
        int c0 = (t == 0) ? 16 : (t == 1) ? 8 : 0;    // skip zero window chunks
        k_hnew<<<(NN + 127) / 128, 256>>>(i1, i2, hgsel, idst, c0,
                                          enc ? 0 : 1, head_w, head_b, outy);

        int old1 = i1; i1 = i2; i2 = idst; idst = old1;
    }
}

// round 11
// speedup vs baseline: 2.3736x; 1.1393x over previous
#include <cuda_runtime.h>
#include <cuda_bf16.h>

constexpr int NN  = 20000;   // nodes
constexpr int TT  = 12;      // encoder steps
constexpr int HOR = 6;       // decoder horizon
constexpr int FF  = 16;      // input features (== C, decoder feedback)
constexpr int EE  = 320000;  // edges
constexpr int HH  = 128;     // hidden
constexpr int CC  = 16;      // out channels

// ---------------- scratch (static device globals; no allocation) -----------
__device__ __align__(16) float g_W[384 * HH];         // fused [A;B;C] fp32
__device__ __align__(16) float g_dvec[HH];            // fused bias vector
__device__ __align__(16) unsigned g_Whi_pk[192 * HH]; // bf16x2-packed hi(W)
__device__ __align__(16) unsigned g_Wlo_pk[192 * HH]; // bf16x2-packed lo(W)

// linear-recurrence transfer matrices and big encoder weight
__device__ __align__(16) float g_R[TT][HH * HH];      // R(k), k=0..11
__device__ __align__(16) float g_bbig[2][HH];         // bias(10), bias(11)
__device__ __align__(16) unsigned g_Wt_hi[2][768 * HH];
__device__ __align__(16) unsigned g_Wt_lo[2][768 * HH];

// pre-packed bf16 hi/lo activations
__device__ __align__(16) unsigned g_hg12h[TT][NN * 64];
__device__ __align__(16) unsigned g_hg12l[TT][NN * 64];
__device__ __align__(16) unsigned g_hbh[3][NN * 64];
__device__ __align__(16) unsigned g_hbl[3][NN * 64];
__device__ __align__(16) unsigned g_aggh[NN * 64];
__device__ __align__(16) unsigned g_aggl[NN * 64];
__device__ int   g_is64;

// per-edge-set CSR (built once per launch)
__device__ int   g_deg[TT][NN];
__device__ int   g_indptr[TT][NN + 1];
__device__ int   g_cur[TT][NN];
__device__ float g_dinv[TT][NN];
__device__ int   g_csrc[TT][EE];
__device__ float g_cw[TT][EE];

// ---------------- helpers ----------------------------------------------------
__device__ __forceinline__ unsigned pk_bf(__nv_bfloat16 a, __nv_bfloat16 b) {
    __nv_bfloat162 x; x.x = a; x.y = b;
    return *reinterpret_cast<unsigned*>(&x);
}
__device__ __forceinline__ void split_pk(float a, float b,
                                         unsigned& hi, unsigned& lo) {
    __nv_bfloat16 ha = __float2bfloat16(a);
    __nv_bfloat16 hb = __float2bfloat16(b);
    __nv_bfloat16 la = __float2bfloat16(a - __bfloat162float(ha));
    __nv_bfloat16 lb = __float2bfloat16(b - __bfloat162float(hb));
    hi = pk_bf(ha, hb);
    lo = pk_bf(la, lb);
}

__device__ __forceinline__ int load_idx(const void* p, long long e) {
    int v;
    if (g_is64) v = (int)((const long long*)p)[e];
    else        v = ((const int*)p)[e];
    v = v < 0 ? 0 : (v >= NN ? NN - 1 : v);
    return v;
}

// ---------------- launch 1: detect dtype + zero degree arrays ---------------
__global__ void k_init(const unsigned* __restrict__ w) {
    long long idx = (long long)blockIdx.x * blockDim.x + threadIdx.x;
    if (idx < (long long)TT * NN) (&g_deg[0][0])[idx] = 0;
    if (idx == 0) {
        int nz = 0;
        #pragma unroll 8
        for (int i = 0; i < 128; ++i) nz += (w[2 * i + 1] != 0u);
        g_is64 = (nz == 0) ? 1 : 0;
    }
}

// ---------------- launch 2: fold conv/proj -> W (fp32 + bf16 split), dvec ---
__global__ void k_prepWsd(const float* __restrict__ conv_w,
                          const float* __restrict__ proj_w,
                          const float* __restrict__ conv_b,
                          const float* __restrict__ proj_b) {
    int h = threadIdx.x;
    if (blockIdx.x == 192) {             // dvec
        float acc = proj_b[h];
        #pragma unroll 4
        for (int j = 0; j < 384; ++j) acc += conv_b[j] * proj_w[h * 384 + j];
        g_dvec[h] = acc;
        return;
    }
    __shared__ float wa[6][128];
    int kp = blockIdx.x;                 // 0..191
    int c0 = 2 * kp, c1 = c0 + 1;
    float a0 = 0.f, a1 = 0.f;
    if (c0 < 128) {
        wa[0][h] = conv_w[((128 + h) * 128 + c0) * 3 + 0];
        wa[1][h] = conv_w[((128 + h) * 128 + c1) * 3 + 0];
        __syncthreads();
        #pragma unroll 4
        for (int o = 0; o < 128; ++o) {
            float p = proj_w[h * 384 + 128 + o];
            a0 += wa[0][o] * p; a1 += wa[1][o] * p;
        }
    } else if (c0 < 256) {
        int cc0 = c0 - 128, cc1 = c1 - 128;
        wa[0][h] = conv_w[(h * 128 + cc0) * 3 + 0];
        wa[1][h] = conv_w[(h * 128 + cc1) * 3 + 0];
        __syncthreads();
        #pragma unroll 4
        for (int o = 0; o < 128; ++o) {
            float p = proj_w[h * 384 + o];
            a0 += wa[0][o] * p; a1 += wa[1][o] * p;
        }
    } else {
        int cc0 = c0 - 256, cc1 = c1 - 256;
        wa[0][h] = conv_w[(h * 128 + cc0) * 3 + 1];
        wa[1][h] = conv_w[((128 + h) * 128 + cc0) * 3 + 1];
        wa[2][h] = conv_w[((256 + h) * 128 + cc0) * 3 + 1];
        wa[3][h] = conv_w[(h * 128 + cc1) * 3 + 1];
        wa[4][h] = conv_w[((128 + h) * 128 + cc1) * 3 + 1];
        wa[5][h] = conv_w[((256 + h) * 128 + cc1) * 3 + 1];
        __syncthreads();
        #pragma unroll 2
        for (int o = 0; o < 128; ++o) {
            float p0 = proj_w[h * 384 + o];
            float p1 = proj_w[h * 384 + 128 + o];
            float p2 = proj_w[h * 384 + 256 + o];
            a0 += wa[0][o] * p0 + wa[1][o] * p1 + wa[2][o] * p2;
            a1 += wa[3][o] * p0 + wa[4][o] * p1 + wa[5][o] * p2;
        }
    }
    g_W[c0 * 128 + h] = a0;
    g_W[c1 * 128 + h] = a1;
    unsigned hi, lo;
    split_pk(a0, a1, hi, lo);
    g_Whi_pk[kp * 128 + h] = hi;
    g_Wlo_pk[kp * 128 + h] = lo;
}

// ---------------- CSR construction ----------------------------------------
__global__ void k_count12(const void* __restrict__ ei) {
    long long idx = (long long)blockIdx.x * blockDim.x + threadIdx.x;
    if (idx >= (long long)TT * EE) return;
    int set = (int)(idx / EE);
    int e   = (int)(idx % EE);
    int d = load_idx(ei, (long long)set * 2 * EE + EE + e);
    atomicAdd(&g_deg[set][d], 1);
}

__global__ void k_scan12() {
    __shared__ int sh[1024];
    int set = blockIdx.x;
    int t   = threadIdx.x;
    const int PER = 20;
    int base = t * PER;
    int degs[PER];
    int sum = 0;
    #pragma unroll
    for (int i = 0; i < PER; ++i) {
        int n = base + i;
        degs[i] = (n < NN) ? g_deg[set][n] : 0;
        sum += degs[i];
    }
    sh[t] = sum;
    __syncthreads();
    for (int off = 1; off < 1024; off <<= 1) {
        int v = (t >= off) ? sh[t - off] : 0;
        __syncthreads();
        sh[t] += v;
        __syncthreads();
    }
    int run = sh[t] - sum;
    #pragma unroll
    for (int i = 0; i < PER; ++i) {
        int n = base + i;
        if (n < NN) {
            g_indptr[set][n] = run;
            g_cur[set][n]    = run;
            g_dinv[set][n]   = rsqrtf(1.0f + (float)degs[i]);
            run += degs[i];
        }
    }
    if (t == 1023) g_indptr[set][NN] = sh[1023];
}

__global__ void k_fill12(const void* __restrict__ ei) {
    long long idx = (long long)blockIdx.x * blockDim.x + threadIdx.x;
    if (idx >= (long long)TT * EE) return;
    int set = (int)(idx / EE);
    int e   = (int)(idx % EE);
    long long b = (long long)set * 2 * EE;
    int s = load_idx(ei, b + e);
    int d = load_idx(ei, b + EE + e);
    int pos = atomicAdd(&g_cur[set][d], 1);
    g_csrc[set][pos] = s;
    g_cw[set][pos]   = g_dinv[set][s] * g_dinv[set][d];
}

// ---------------- fused GCN: aggregate -> weight multiply -> split+pack ------
__device__ __forceinline__ void gcn_body(const float* __restrict__ x, int set,
                                         unsigned* __restrict__ outh,
                                         unsigned* __restrict__ outl,
                                         const float* __restrict__ gcn_w,
                                         const float* __restrict__ gcn_b,
                                         int row0) {
    __shared__ float Xs[16 * 16];
    __shared__ float Ws[16 * 128];
    int tid = threadIdx.x;
    #pragma unroll
    for (int i = 0; i < 16; ++i) Ws[i * 128 + tid] = gcn_w[i * 128 + tid];

    int lane   = tid & 31;
    int nlocal = (tid >> 5) * 4 + (lane >> 3);
    int f2     = lane & 7;
    int node   = row0 + nlocal;
    float di = g_dinv[set][node];
    float2 acc = *reinterpret_cast<const float2*>(&x[node * 16 + 2 * f2]);
    float d2 = di * di;
    acc.x *= d2; acc.y *= d2;
    int beg = g_indptr[set][node], end = g_indptr[set][node + 1];
    for (int i = beg; i < end; ++i) {
        int   s  = g_csrc[set][i];
        float wt = g_cw[set][i];
        float2 u = *reinterpret_cast<const float2*>(&x[s * 16 + 2 * f2]);
        acc.x += wt * u.x; acc.y += wt * u.y;
    }
    Xs[nlocal * 16 + 2 * f2]     = acc.x;
    Xs[nlocal * 16 + 2 * f2 + 1] = acc.y;
    __syncthreads();

    float b = gcn_b[tid];
    #pragma unroll
    for (int r = 0; r < 16; ++r) {
        float a = b;
        #pragma unroll
        for (int f = 0; f < 16; ++f) a += Xs[r * 16 + f] * Ws[f * 128 + tid];
        a = fmaxf(a, 0.f);
        float vo = __shfl_xor_sync(0xffffffffu, a, 1);
        if (!(tid & 1)) {
            unsigned hi, lo;
            split_pk(a, vo, hi, lo);
            outh[(row0 + r) * 64 + (tid >> 1)] = hi;
            outl[(row0 + r) * 64 + (tid >> 1)] = lo;
        }
    }
}

__global__ void k_gcn_all(const float* __restrict__ x_seq,
                          const float* __restrict__ gcn_w,
                          const float* __restrict__ gcn_b) {
    int set = blockIdx.y;
    gcn_body(x_seq + (long long)set * NN * FF, set,
             &g_hg12h[set][0], &g_hg12l[set][0], gcn_w, gcn_b, blockIdx.x * 16);
}

__global__ void k_gcn1(const float* __restrict__ x,
                       const float* __restrict__ gcn_w,
                       const float* __restrict__ gcn_b) {
    gcn_body(x, TT - 1, g_aggh, g_aggl, gcn_w, gcn_b, blockIdx.x * 16);
}

// ---------------- linear-recurrence transfer matrices ------------------------
// R(0) = C (g_W rows 256..383)
__global__ void k_R0() {
    int r = blockIdx.x, h = threadIdx.x;
    g_R[0][r * 128 + h] = g_W[(256 + r) * 128 + h];
}
// R(k) = R(k-1)·B + R(k-2)·A   (B = g_W rows 128..255, A = rows 0..127)
__global__ void k_Rstep(int k) {
    __shared__ float r1[128], r2[128];
    int r = blockIdx.x, h = threadIdx.x;
    r1[h] = g_R[k - 1][r * 128 + h];
    r2[h] = (k >= 2) ? g_R[k - 2][r * 128 + h] : 0.f;
    __syncthreads();
    float acc = 0.f;
    #pragma unroll 4
    for (int o = 0; o < 128; ++o)
        acc += r1[o] * g_W[(128 + o) * 128 + h] + r2[o] * g_W[o * 128 + h];
    g_R[k][r * 128 + h] = acc;
}
// bias(t) = bias(t-1)·B + bias(t-2)·A + d ; store bias(10), bias(11)
__global__ void k_bias() {
    __shared__ float b1[128], b2[128];
    int h = threadIdx.x;
    float d = g_dvec[h];
    b1[h] = 0.f; b2[h] = 0.f;
    __syncthreads();
    for (int t = 0; t <= 11; ++t) {
        float acc = d;
        #pragma unroll 4
        for (int o = 0; o < 128; ++o)
            acc += b1[o] * g_W[(128 + o) * 128 + h] + b2[o] * g_W[o * 128 + h];
        __syncthreads();
        b2[h] = b1[h];
        b1[h] = acc;
        if (t == 10) g_bbig[0][h] = acc;
        if (t == 11) g_bbig[1][h] = acc;
        __syncthreads();
    }
}
// pack Wbig[target]: row block s = R(T-s); K=1536, packed pairs in K
__global__ void k_packbig() {
    int kp  = blockIdx.x;   // 0..767
    int tgt = blockIdx.y;   // 0 -> h(10), 1 -> h(11)
    int h   = threadIdx.x;
    int k0 = 2 * kp;
    int s  = k0 >> 7;
    int j0 = k0 & 127;
    int T  = tgt ? 11 : 10;
    int kk = T - s;
    float w0 = (kk >= 0) ? g_R[kk][j0 * 128 + h] : 0.f;
    float w1 = (kk >= 0) ? g_R[kk][(j0 + 1) * 128 + h] : 0.f;
    unsigned hi, lo;
    split_pk(w0, w1, hi, lo);
    g_Wt_hi[tgt][kp * 128 + h] = hi;
    g_Wt_lo[tgt][kp * 128 + h] = lo;
}

// ---------------- MMA helper ---------------------------------------------
__device__ __forceinline__ void mma_bf16(float* c, const unsigned* a,
                                         unsigned b0, unsigned b1) {
    asm volatile(
        "mma.sync.aligned.m16n8k16.row.col.f32.bf16.bf16.f32 "
        "{%0,%1,%2,%3}, {%4,%5,%6,%7}, {%8,%9}, {%0,%1,%2,%3};"
        : "+f"(c[0]), "+f"(c[1]), "+f"(c[2]), "+f"(c[3])
        : "r"(a[0]), "r"(a[1]), "r"(a[2]), "r"(a[3]), "r"(b0), "r"(b1));
}

constexpr int ASTW = 12;   // A smem row stride in words (8 data + 4 pad)
constexpr int WST  = 136;  // W smem row stride in words

// ---------------- big encoder GEMM: h(10), h(11) in one launch ---------------
// grid (157, 2); tgt = blockIdx.y; A = g_hg12[c>>3]; 96 chunks of k=16.
__global__ void __launch_bounds__(256, 2)
k_hbig() {
    __shared__ __align__(16) unsigned Ah[2][128 * ASTW];
    __shared__ __align__(16) unsigned Al[2][128 * ASTW];
    __shared__ __align__(16) unsigned Wh[2][8 * WST];
    __shared__ __align__(16) unsigned Wl[2][8 * WST];

    int tgt  = blockIdx.y;
    const unsigned* whp = g_Wt_hi[tgt];
    const unsigned* wlp = g_Wt_lo[tgt];

    int t    = threadIdx.x;
    int w    = t >> 5;
    int l    = t & 31;
    int row0 = blockIdx.x * 128;
    int wr   = w * 16;

    float acc[16][4];
    #pragma unroll
    for (int nt = 0; nt < 16; ++nt)
        #pragma unroll
        for (int j = 0; j < 4; ++j) acc[nt][j] = 0.f;

    int arow = t >> 1, ahalf = t & 1;
    int wkk  = t >> 5, wns = l * 4;
    long long agi = (long long)(row0 + arow) * 64 + ahalf * 4;
    bool arow_ok = (row0 + arow) < NN;

    {
        uint4 uh = {0,0,0,0}, ul = {0,0,0,0};
        if (arow_ok) {
            uh = __ldg(reinterpret_cast<const uint4*>(&g_hg12h[0][0] + agi));
            ul = __ldg(reinterpret_cast<const uint4*>(&g_hg12l[0][0] + agi));
        }
        *reinterpret_cast<uint4*>(&Ah[0][arow * ASTW + ahalf * 4]) = uh;
        *reinterpret_cast<uint4*>(&Al[0][arow * ASTW + ahalf * 4]) = ul;
        uint4 pwh = __ldg(reinterpret_cast<const uint4*>(&whp[wkk * 128 + wns]));
        uint4 pwl = __ldg(reinterpret_cast<const uint4*>(&wlp[wkk * 128 + wns]));
        *reinterpret_cast<uint4*>(&Wh[0][wkk * WST + wns]) = pwh;
        *reinterpret_cast<uint4*>(&Wl[0][wkk * WST + wns]) = pwl;
    }
    __syncthreads();

    int rb = wr + (l >> 2);
    int kw = l & 3;

    #pragma unroll 1
    for (int c = 0; c < 96; ++c) {
        int buf = c & 1;
        bool has = (c + 1 < 96);

        uint4 uh = {0,0,0,0}, ul = {0,0,0,0}, pwh, pwl;
        if (has) {
            int cn = c + 1;
            const unsigned* sh_ = &g_hg12h[cn >> 3][0];
            const unsigned* sl_ = &g_hg12l[cn >> 3][0];
            if (arow_ok) {
                uh = __ldg(reinterpret_cast<const uint4*>(sh_ + agi + (cn & 7) * 8));
                ul = __ldg(reinterpret_cast<const uint4*>(sl_ + agi + (cn & 7) * 8));
            }
            pwh = __ldg(reinterpret_cast<const uint4*>(&whp[(cn * 8 + wkk) * 128 + wns]));
            pwl = __ldg(reinterpret_cast<const uint4*>(&wlp[(cn * 8 + wkk) * 128 + wns]));
        }

        const unsigned* ah = &Ah[buf][0];
        const unsigned* al = &Al[buf][0];
        unsigned ahi[4], alo[4];
        ahi[0] = ah[rb * ASTW + kw];
        ahi[1] = ah[(rb + 8) * ASTW + kw];
        ahi[2] = ah[rb * ASTW + 4 + kw];
        ahi[3] = ah[(rb + 8) * ASTW + 4 + kw];
        alo[0] = al[rb * ASTW + kw];
        alo[1] = al[(rb + 8) * ASTW + kw];
        alo[2] = al[rb * ASTW + 4 + kw];
        alo[3] = al[(rb + 8) * ASTW + 4 + kw];
        #pragma unroll
        for (int nt = 0; nt < 16; ++nt) {
            int wb = nt * 8 + (l >> 2);
            unsigned bh0 = Wh[buf][kw * WST + wb];
            unsigned bh1 = Wh[buf][(4 + kw) * WST + wb];
            unsigned bl0 = Wl[buf][kw * WST + wb];
            unsigned bl1 = Wl[buf][(4 + kw) * WST + wb];
            mma_bf16(acc[nt], ahi, bh0, bh1);
            mma_bf16(acc[nt], ahi, bl0, bl1);
            mma_bf16(acc[nt], alo, bh0, bh1);
        }

        if (has) {
            int nbuf = buf ^ 1;
            *reinterpret_cast<uint4*>(&Ah[nbuf][arow * ASTW + ahalf * 4]) = uh;
            *reinterpret_cast<uint4*>(&Al[nbuf][arow * ASTW + ahalf * 4]) = ul;
            *reinterpret_cast<uint4*>(&Wh[nbuf][wkk * WST + wns]) = pwh;
            *reinterpret_cast<uint4*>(&Wl[nbuf][wkk * WST + wns]) = pwl;
        }
        __syncthreads();
    }

    // epilogue: bias, store packed bf16 hi/lo into window buffer `tgt`
    unsigned* dsth = g_hbh[tgt];
    unsigned* dstl = g_hbl[tgt];
    const float* bb = g_bbig[tgt];
    int cw = 2 * (l & 3);
    int rA = row0 + rb;
    #pragma unroll
    for (int nt = 0; nt < 16; ++nt) {
        int col = nt * 8 + cw;
        float2 dv = *reinterpret_cast<const float2*>(&bb[col]);
        unsigned hi, lo;
        if (rA < NN) {
            split_pk(acc[nt][0] + dv.x, acc[nt][1] + dv.y, hi, lo);
            dsth[(long long)rA * 64 + col / 2] = hi;
            dstl[(long long)rA * 64 + col / 2] = lo;
        }
        if (rA + 8 < NN) {
            split_pk(acc[nt][2] + dv.x, acc[nt][3] + dv.y, hi, lo);
            dsth[(long long)(rA + 8) * 64 + col / 2] = hi;
            dstl[(long long)(rA + 8) * 64 + col / 2] = lo;
        }
    }
}

// ---------------- decoder h_new GEMM + fused y head --------------------------
__global__ void __launch_bounds__(256, 2)
k_hnew(int i1, int i2, int hgsel, int idst,
       const float* __restrict__ head_w, const float* __restrict__ head_b,
       float* __restrict__ outy) {
    __shared__ __align__(16) unsigned Ah[2][128 * ASTW];
    __shared__ __align__(16) unsigned Al[2][128 * ASTW];
    __shared__ __align__(16) unsigned Wh[2][8 * WST];
    __shared__ __align__(16) unsigned Wl[2][8 * WST];

    const unsigned* hgh = (hgsel >= 0) ? &g_hg12h[hgsel][0] : g_aggh;
    const unsigned* hgl = (hgsel >= 0) ? &g_hg12l[hgsel][0] : g_aggl;
    const unsigned* h1h = g_hbh[i1];
    const unsigned* h1l = g_hbl[i1];
    const unsigned* h2h = g_hbh[i2];
    const unsigned* h2l = g_hbl[i2];

    int t    = threadIdx.x;
    int w    = t >> 5;
    int l    = t & 31;
    int row0 = blockIdx.x * 128;
    int wr   = w * 16;

    float acc[16][4];
    #pragma unroll
    for (int nt = 0; nt < 16; ++nt)
        #pragma unroll
        for (int j = 0; j < 4; ++j) acc[nt][j] = 0.f;

    int arow = t >> 1, ahalf = t & 1;
    int wkk  = t >> 5, wns = l * 4;
    long long agi = (long long)(row0 + arow) * 64 + ahalf * 4;
    bool arow_ok = (row0 + arow) < NN;

    {
        uint4 uh = {0,0,0,0}, ul = {0,0,0,0};
        if (arow_ok) {
            uh = __ldg(reinterpret_cast<const uint4*>(h1h + agi));
            ul = __ldg(reinterpret_cast<const uint4*>(h1l + agi));
        }
        *reinterpret_cast<uint4*>(&Ah[0][arow * ASTW + ahalf * 4]) = uh;
        *reinterpret_cast<uint4*>(&Al[0][arow * ASTW + ahalf * 4]) = ul;
        uint4 pwh = __ldg(reinterpret_cast<const uint4*>(&g_Whi_pk[wkk * 128 + wns]));
        uint4 pwl = __ldg(reinterpret_cast<const uint4*>(&g_Wlo_pk[wkk * 128 + wns]));
        *reinterpret_cast<uint4*>(&Wh[0][wkk * WST + wns]) = pwh;
        *reinterpret_cast<uint4*>(&Wl[0][wkk * WST + wns]) = pwl;
    }
    __syncthreads();

    int rb = wr + (l >> 2);
    int kw = l & 3;

    for (int c = 0; c < 24; ++c) {
        int buf = c & 1;
        bool has = (c + 1 < 24);

        uint4 uh = {0,0,0,0}, ul = {0,0,0,0}, pwh, pwl;
        if (has) {
            int cn = c + 1;
            const unsigned* sh_ = (cn < 8) ? h1h : (cn < 16) ? h2h : hgh;
            const unsigned* sl_ = (cn < 8) ? h1l : (cn < 16) ? h2l : hgl;
            if (arow_ok) {
                uh = __ldg(reinterpret_cast<const uint4*>(sh_ + agi + (cn & 7) * 8));
                ul = __ldg(reinterpret_cast<const uint4*>(sl_ + agi + (cn & 7) * 8));
            }
            pwh = __ldg(reinterpret_cast<const uint4*>(&g_Whi_pk[(cn * 8 + wkk) * 128 + wns]));
            pwl = __ldg(reinterpret_cast<const uint4*>(&g_Wlo_pk[(cn * 8 + wkk) * 128 + wns]));
        }

        const unsigned* ah = &Ah[buf][0];
        const unsigned* al = &Al[buf][0];
        unsigned ahi[4], alo[4];
        ahi[0] = ah[rb * ASTW + kw];
        ahi[1] = ah[(rb + 8) * ASTW + kw];
        ahi[2] = ah[rb * ASTW + 4 + kw];
        ahi[3] = ah[(rb + 8) * ASTW + 4 + kw];
        alo[0] = al[rb * ASTW + kw];
        alo[1] = al[(rb + 8) * ASTW + kw];
        alo[2] = al[rb * ASTW + 4 + kw];
        alo[3] = al[(rb + 8) * ASTW + 4 + kw];
        #pragma unroll
        for (int nt = 0; nt < 16; ++nt) {
            int wb = nt * 8 + (l >> 2);
            unsigned bh0 = Wh[buf][kw * WST + wb];
            unsigned bh1 = Wh[buf][(4 + kw) * WST + wb];
            unsigned bl0 = Wl[buf][kw * WST + wb];
            unsigned bl1 = Wl[buf][(4 + kw) * WST + wb];
            mma_bf16(acc[nt], ahi, bh0, bh1);
            mma_bf16(acc[nt], ahi, bl0, bl1);
            mma_bf16(acc[nt], alo, bh0, bh1);
        }

        if (has) {
            int nbuf = buf ^ 1;
            *reinterpret_cast<uint4*>(&Ah[nbuf][arow * ASTW + ahalf * 4]) = uh;
            *reinterpret_cast<uint4*>(&Al[nbuf][arow * ASTW + ahalf * 4]) = ul;
            *reinterpret_cast<uint4*>(&Wh[nbuf][wkk * WST + wns]) = pwh;
            *reinterpret_cast<uint4*>(&Wl[nbuf][wkk * WST + wns]) = pwl;
        }
        __syncthreads();
    }

    // epilogue: bias into acc; store packed bf16 hi/lo; fused y head
    unsigned* dsth = g_hbh[idst];
    unsigned* dstl = g_hbl[idst];
    int cw = 2 * (l & 3);
    int rA = row0 + rb;
    #pragma unroll
    for (int nt = 0; nt < 16; ++nt) {
        int col = nt * 8 + cw;
        float2 dv = *reinterpret_cast<const float2*>(&g_dvec[col]);
        acc[nt][0] += dv.x; acc[nt][1] += dv.y;
        acc[nt][2] += dv.x; acc[nt][3] += dv.y;
        unsigned hi, lo;
        if (rA < NN) {
            split_pk(acc[nt][0], acc[nt][1], hi, lo);
            dsth[(long long)rA * 64 + col / 2] = hi;
            dstl[(long long)rA * 64 + col / 2] = lo;
        }
        if (rA + 8 < NN) {
            split_pk(acc[nt][2], acc[nt][3], hi, lo);
            dsth[(long long)(rA + 8) * 64 + col / 2] = hi;
            dstl[(long long)(rA + 8) * 64 + col / 2] = lo;
        }
    }

    // y = h_new @ head_w^T + head_b (reuse dead A-tile smem for head_w)
    float* Hw = reinterpret_cast<float*>(&Ah[0][0]);
    for (int i = t; i < 16 * 128; i += 256) Hw[i] = head_w[i];
    __syncthreads();
    #pragma unroll
    for (int ch = 0; ch < 16; ++ch) {
        float s0 = 0.f, s1 = 0.f;
        #pragma unroll
        for (int nt = 0; nt < 16; ++nt) {
            int col = nt * 8 + cw;
            float w0 = Hw[ch * 128 + col], w1 = Hw[ch * 128 + col + 1];
            s0 += acc[nt][0] * w0 + acc[nt][1] * w1;
            s1 += acc[nt][2] * w0 + acc[nt][3] * w1;
        }
        s0 += __shfl_xor_sync(0xffffffffu, s0, 1);
        s0 += __shfl_xor_sync(0xffffffffu, s0, 2);
        s1 += __shfl_xor_sync(0xffffffffu, s1, 1);
        s1 += __shfl_xor_sync(0xffffffffu, s1, 2);
        if ((l & 3) == 0) {
            float hb = __ldg(&head_b[ch]);
            if (rA < NN)     outy[(long long)rA * 16 + ch] = s0 + hb;
            if (rA + 8 < NN) outy[(long long)(rA + 8) * 16 + ch] = s1 + hb;
        }
    }
}

// ---------------------------------------------------------------------------
extern "C" void kernel_launch(void* const* d_in, const int* in_sizes, int n_in,
                              void* d_out, int out_size) {
    const float* x_seq  = (const float*)d_in[0];
    const void*  ei     = d_in[1];
    const float* gcn_w  = (const float*)d_in[5];
    const float* gcn_b  = (const float*)d_in[6];
    const float* conv_w = (const float*)d_in[7];
    const float* conv_b = (const float*)d_in[8];
    const float* proj_w = (const float*)d_in[9];
    const float* proj_b = (const float*)d_in[10];
    const float* head_w = (const float*)d_in[11];
    const float* head_b = (const float*)d_in[12];
    float* out = (float*)d_out;

    // prep + CSR
    k_init<<<(TT * NN + 255) / 256, 256>>>((const unsigned*)ei);
    k_prepWsd<<<193, 128>>>(conv_w, proj_w, conv_b, proj_b);
    {
        long long tot = (long long)TT * EE;
        int blocks = (int)((tot + 255) / 256);
        k_count12<<<blocks, 256>>>(ei);
        k_scan12<<<TT, 1024>>>();
        k_fill12<<<blocks, 256>>>(ei);
    }

    // all 12 encoder GCNs
    {
        dim3 gg(NN / 16, TT);
        k_gcn_all<<<gg, 128>>>(x_seq, gcn_w, gcn_b);
    }

    // transfer matrices R(0..11), biases, big weight pack
    k_R0<<<128, 128>>>();
    for (int k = 1; k <= 11; ++k) k_Rstep<<<128, 128>>>(k);
    k_bias<<<1, 128>>>();
    k_packbig<<<dim3(768, 2), 128>>>();

    // one wide GEMM: h(10) -> buffer 0, h(11) -> buffer 1
    k_hbig<<<dim3((NN + 127) / 128, 2), 256>>>();

    // decoder: 6 serial steps with feedback
    int i1 = 0, i2 = 1, idst = 2;
    for (int t = TT; t < TT + HOR; ++t) {
        int hgsel;
        float* outy = out + (long long)(t - TT) * NN * CC;
        if (t == TT) hgsel = TT - 1;     // identical GCN to encoder step 11
        else {
            const float* xin = out + (long long)(t - TT - 1) * NN * CC;
            k_gcn1<<<NN / 16, 128>>>(xin, gcn_w, gcn_b);
            hgsel = -1;
        }
        k_hnew<<<(NN + 127) / 128, 256>>>(i1, i2, hgsel, idst,
                                          head_w, head_b, outy);
        int old1 = i1; i1 = i2; i2 = idst; idst = old1;
    }
}

// round 12
// speedup vs baseline: 2.6216x; 1.1045x over previous
#include <cuda_runtime.h>
#include <cuda_bf16.h>

constexpr int NN  = 20000;   // nodes
constexpr int TT  = 12;      // encoder steps
constexpr int HOR = 6;       // decoder horizon
constexpr int FF  = 16;      // input features (== C, decoder feedback)
constexpr int EE  = 320000;  // edges
constexpr int HH  = 128;     // hidden
constexpr int CC  = 16;      // out channels

// ---------------- scratch (static device globals; no allocation) -----------
__device__ __align__(16) float g_W[384 * HH];         // fused [A;B;C] fp32
__device__ __align__(16) float g_dvec[HH];            // fused bias vector
__device__ __align__(16) unsigned g_Whi_pk[192 * HH]; // bf16x2-packed hi(W)
__device__ __align__(16) unsigned g_Wlo_pk[192 * HH]; // bf16x2-packed lo(W)

// big encoder weight (packed directly by k_Rchain) and biases
__device__ __align__(16) float g_bbig[2][HH];         // bias(10), bias(11)
__device__ __align__(16) unsigned g_Wt_hi[2][768 * HH];
__device__ __align__(16) unsigned g_Wt_lo[2][768 * HH];

// pre-packed bf16 hi/lo activations
__device__ __align__(16) unsigned g_hg12h[TT][NN * 64];
__device__ __align__(16) unsigned g_hg12l[TT][NN * 64];
__device__ __align__(16) unsigned g_hbh[3][NN * 64];
__device__ __align__(16) unsigned g_hbl[3][NN * 64];
__device__ __align__(16) unsigned g_aggh[NN * 64];
__device__ __align__(16) unsigned g_aggl[NN * 64];
__device__ int   g_is64;

// per-edge-set CSR (built once per launch)
__device__ int   g_deg[TT][NN];
__device__ int   g_indptr[TT][NN + 1];
__device__ int   g_cur[TT][NN];
__device__ float g_dinv[TT][NN];
__device__ int   g_csrc[TT][EE];
__device__ float g_cw[TT][EE];
__device__ int   g_psum[TT][10];

// ---------------- helpers ----------------------------------------------------
__device__ __forceinline__ unsigned pk_bf(__nv_bfloat16 a, __nv_bfloat16 b) {
    __nv_bfloat162 x; x.x = a; x.y = b;
    return *reinterpret_cast<unsigned*>(&x);
}
__device__ __forceinline__ void split_pk(float a, float b,
                                         unsigned& hi, unsigned& lo) {
    __nv_bfloat16 ha = __float2bfloat16(a);
    __nv_bfloat16 hb = __float2bfloat16(b);
    __nv_bfloat16 la = __float2bfloat16(a - __bfloat162float(ha));
    __nv_bfloat16 lb = __float2bfloat16(b - __bfloat162float(hb));
    hi = pk_bf(ha, hb);
    lo = pk_bf(la, lb);
}

__device__ __forceinline__ int load_idx(const void* p, long long e) {
    int v;
    if (g_is64) v = (int)((const long long*)p)[e];
    else        v = ((const int*)p)[e];
    v = v < 0 ? 0 : (v >= NN ? NN - 1 : v);
    return v;
}

// ---------------- launch 1: detect dtype + zero degree arrays ---------------
__global__ void k_init(const unsigned* __restrict__ w) {
    long long idx = (long long)blockIdx.x * blockDim.x + threadIdx.x;
    if (idx < (long long)TT * NN) (&g_deg[0][0])[idx] = 0;
    if (idx == 0) {
        int nz = 0;
        #pragma unroll 8
        for (int i = 0; i < 128; ++i) nz += (w[2 * i + 1] != 0u);
        g_is64 = (nz == 0) ? 1 : 0;
    }
}

// ---------------- launch 2: fold conv/proj -> W (fp32 + bf16 split), dvec ---
__global__ void k_prepWsd(const float* __restrict__ conv_w,
                          const float* __restrict__ proj_w,
                          const float* __restrict__ conv_b,
                          const float* __restrict__ proj_b) {
    int h = threadIdx.x;
    if (blockIdx.x == 192) {             // dvec
        float acc = proj_b[h];
        #pragma unroll 4
        for (int j = 0; j < 384; ++j) acc += conv_b[j] * proj_w[h * 384 + j];
        g_dvec[h] = acc;
        return;
    }
    __shared__ float wa[6][128];
    int kp = blockIdx.x;                 // 0..191
    int c0 = 2 * kp, c1 = c0 + 1;
    float a0 = 0.f, a1 = 0.f;
    if (c0 < 128) {
        wa[0][h] = conv_w[((128 + h) * 128 + c0) * 3 + 0];
        wa[1][h] = conv_w[((128 + h) * 128 + c1) * 3 + 0];
        __syncthreads();
        #pragma unroll 4
        for (int o = 0; o < 128; ++o) {
            float p = proj_w[h * 384 + 128 + o];
            a0 += wa[0][o] * p; a1 += wa[1][o] * p;
        }
    } else if (c0 < 256) {
        int cc0 = c0 - 128, cc1 = c1 - 128;
        wa[0][h] = conv_w[(h * 128 + cc0) * 3 + 0];
        wa[1][h] = conv_w[(h * 128 + cc1) * 3 + 0];
        __syncthreads();
        #pragma unroll 4
        for (int o = 0; o < 128; ++o) {
            float p = proj_w[h * 384 + o];
            a0 += wa[0][o] * p; a1 += wa[1][o] * p;
        }
    } else {
        int cc0 = c0 - 256, cc1 = c1 - 256;
        wa[0][h] = conv_w[(h * 128 + cc0) * 3 + 1];
        wa[1][h] = conv_w[((128 + h) * 128 + cc0) * 3 + 1];
        wa[2][h] = conv_w[((256 + h) * 128 + cc0) * 3 + 1];
        wa[3][h] = conv_w[(h * 128 + cc1) * 3 + 1];
        wa[4][h] = conv_w[((128 + h) * 128 + cc1) * 3 + 1];
        wa[5][h] = conv_w[((256 + h) * 128 + cc1) * 3 + 1];
        __syncthreads();
        #pragma unroll 2
        for (int o = 0; o < 128; ++o) {
            float p0 = proj_w[h * 384 + o];
            float p1 = proj_w[h * 384 + 128 + o];
            float p2 = proj_w[h * 384 + 256 + o];
            a0 += wa[0][o] * p0 + wa[1][o] * p1 + wa[2][o] * p2;
            a1 += wa[3][o] * p0 + wa[4][o] * p1 + wa[5][o] * p2;
        }
    }
    g_W[c0 * 128 + h] = a0;
    g_W[c1 * 128 + h] = a1;
    unsigned hi, lo;
    split_pk(a0, a1, hi, lo);
    g_Whi_pk[kp * 128 + h] = hi;
    g_Wlo_pk[kp * 128 + h] = lo;
}

// ---------------- CSR construction ----------------------------------------
__global__ void k_count12(const void* __restrict__ ei) {
    long long idx = (long long)blockIdx.x * blockDim.x + threadIdx.x;
    if (idx >= (long long)TT * EE) return;
    int set = (int)(idx / EE);
    int e   = (int)(idx % EE);
    int d = load_idx(ei, (long long)set * 2 * EE + EE + e);
    atomicAdd(&g_deg[set][d], 1);
}

// phase A: per-chunk degree sums (10 chunks of 2000 per set)
__global__ void k_scanA() {
    __shared__ int wsum[8];
    int set = blockIdx.y, chunk = blockIdx.x;
    int t = threadIdx.x, lane = t & 31, wid = t >> 5;
    int base = chunk * 2000;
    int acc = 0;
    for (int j = t; j < 2000; j += 256) acc += g_deg[set][base + j];
    #pragma unroll
    for (int d = 16; d > 0; d >>= 1) acc += __shfl_down_sync(~0u, acc, d);
    if (lane == 0) wsum[wid] = acc;
    __syncthreads();
    if (t == 0) {
        int s = 0;
        #pragma unroll
        for (int w = 0; w < 8; ++w) s += wsum[w];
        g_psum[set][chunk] = s;
    }
}

// phase B: in-chunk exclusive scan + indptr/cur/dinv emit
__global__ void k_scanB() {
    __shared__ int sm[2048];
    __shared__ int woff[8];
    __shared__ int s_off;
    int set = blockIdx.y, chunk = blockIdx.x;
    int t = threadIdx.x, lane = t & 31, wid = t >> 5;
    int base = chunk * 2000;
    if (t == 0) {
        int o = 0;
        for (int c = 0; c < chunk; ++c) o += g_psum[set][c];
        s_off = o;
    }
    for (int j = t; j < 2048; j += 256)
        sm[j] = (j < 2000) ? g_deg[set][base + j] : 0;
    __syncthreads();
    int v[8];
    int run = 0;
    #pragma unroll
    for (int i = 0; i < 8; ++i) { v[i] = sm[t * 8 + i]; run += v[i]; }
    int x = run;
    #pragma unroll
    for (int d = 1; d < 32; d <<= 1) {
        int y = __shfl_up_sync(~0u, x, d);
        if (lane >= d) x += y;
    }
    if (lane == 31) woff[wid] = x;
    __syncthreads();
    if (t == 0) {
        int o = 0;
        #pragma unroll
        for (int w = 0; w < 8; ++w) { int tmp = woff[w]; woff[w] = o; o += tmp; }
    }
    __syncthreads();
    int runp = s_off + woff[wid] + (x - run);
    #pragma unroll
    for (int i = 0; i < 8; ++i) {
        int j = t * 8 + i;
        if (j < 2000) {
            int n = base + j;
            g_indptr[set][n] = runp;
            g_cur[set][n]    = runp;
            g_dinv[set][n]   = rsqrtf(1.0f + (float)v[i]);
            runp += v[i];
        }
    }
    if (chunk == 9 && t == 249) g_indptr[set][NN] = runp;
}

__global__ void k_fill12(const void* __restrict__ ei) {
    long long idx = (long long)blockIdx.x * blockDim.x + threadIdx.x;
    if (idx >= (long long)TT * EE) return;
    int set = (int)(idx / EE);
    int e   = (int)(idx % EE);
    long long b = (long long)set * 2 * EE;
    int s = load_idx(ei, b + e);
    int d = load_idx(ei, b + EE + e);
    int pos = atomicAdd(&g_cur[set][d], 1);
    g_csrc[set][pos] = s;
    g_cw[set][pos]   = g_dinv[set][s] * g_dinv[set][d];
}

// ---------------- fused GCN: aggregate -> weight multiply -> split+pack ------
__device__ __forceinline__ void gcn_body(const float* __restrict__ x, int set,
                                         unsigned* __restrict__ outh,
                                         unsigned* __restrict__ outl,
                                         const float* __restrict__ gcn_w,
                                         const float* __restrict__ gcn_b,
                                         int row0) {
    __shared__ float Xs[16 * 16];
    __shared__ float Ws[16 * 128];
    int tid = threadIdx.x;
    #pragma unroll
    for (int i = 0; i < 16; ++i) Ws[i * 128 + tid] = gcn_w[i * 128 + tid];

    int lane   = tid & 31;
    int nlocal = (tid >> 5) * 4 + (lane >> 3);
    int f2     = lane & 7;
    int node   = row0 + nlocal;
    float di = g_dinv[set][node];
    float2 acc = *reinterpret_cast<const float2*>(&x[node * 16 + 2 * f2]);
    float d2 = di * di;
    acc.x *= d2; acc.y *= d2;
    int beg = g_indptr[set][node], end = g_indptr[set][node + 1];
    for (int i = beg; i < end; ++i) {
        int   s  = g_csrc[set][i];
        float wt = g_cw[set][i];
        float2 u = *reinterpret_cast<const float2*>(&x[s * 16 + 2 * f2]);
        acc.x += wt * u.x; acc.y += wt * u.y;
    }
    Xs[nlocal * 16 + 2 * f2]     = acc.x;
    Xs[nlocal * 16 + 2 * f2 + 1] = acc.y;
    __syncthreads();

    float b = gcn_b[tid];
    #pragma unroll
    for (int r = 0; r < 16; ++r) {
        float a = b;
        #pragma unroll
        for (int f = 0; f < 16; ++f) a += Xs[r * 16 + f] * Ws[f * 128 + tid];
        a = fmaxf(a, 0.f);
        float vo = __shfl_xor_sync(0xffffffffu, a, 1);
        if (!(tid & 1)) {
            unsigned hi, lo;
            split_pk(a, vo, hi, lo);
            outh[(row0 + r) * 64 + (tid >> 1)] = hi;
            outl[(row0 + r) * 64 + (tid >> 1)] = lo;
        }
    }
}

__global__ void k_gcn_all(const float* __restrict__ x_seq,
                          const float* __restrict__ gcn_w,
                          const float* __restrict__ gcn_b) {
    int set = blockIdx.y;
    gcn_body(x_seq + (long long)set * NN * FF, set,
             &g_hg12h[set][0], &g_hg12l[set][0], gcn_w, gcn_b, blockIdx.x * 16);
}

__global__ void k_gcn1(const float* __restrict__ x,
                       const float* __restrict__ gcn_w,
                       const float* __restrict__ gcn_b) {
    gcn_body(x, TT - 1, g_aggh, g_aggl, gcn_w, gcn_b, blockIdx.x * 16);
}

// ---------------- single-launch R chain + bias + Wt pack ---------------------
// R(k) = R(k-1)·B + R(k-2)·A is row-independent: block b owns rows 2b, 2b+1,
// iterates k locally, and emits packed Wt rows directly. Block 64 does biases.
__global__ void k_Rchain() {
    __shared__ float cur[2][128], prev[2][128];
    int b = blockIdx.x;
    int h = threadIdx.x;

    if (b == 64) {                       // bias recurrence
        __shared__ float b1[128], b2[128];
        float d = g_dvec[h];
        b1[h] = 0.f; b2[h] = 0.f;
        __syncthreads();
        for (int t = 0; t <= 11; ++t) {
            float acc = d;
            #pragma unroll 4
            for (int o = 0; o < 128; ++o)
                acc += b1[o] * g_W[(128 + o) * 128 + h] + b2[o] * g_W[o * 128 + h];
            __syncthreads();
            b2[h] = b1[h];
            b1[h] = acc;
            if (t == 10) g_bbig[0][h] = acc;
            if (t == 11) g_bbig[1][h] = acc;
            __syncthreads();
        }
        return;
    }

    int r0 = 2 * b;
    cur[0][h]  = g_W[(256 + r0) * 128 + h];       // R(0) = C
    cur[1][h]  = g_W[(256 + r0 + 1) * 128 + h];
    prev[0][h] = 0.f; prev[1][h] = 0.f;
    // tgt0 (T=10) s=11 row block has no R contribution -> zero
    g_Wt_hi[0][(11 * 64 + b) * 128 + h] = 0u;
    g_Wt_lo[0][(11 * 64 + b) * 128 + h] = 0u;
    __syncthreads();

    for (int k = 0; k <= 11; ++k) {
        unsigned hi, lo;
        split_pk(cur[0][h], cur[1][h], hi, lo);
        if (k <= 10) {
            int s = 10 - k;
            g_Wt_hi[0][(s * 64 + b) * 128 + h] = hi;
            g_Wt_lo[0][(s * 64 + b) * 128 + h] = lo;
        }
        {
            int s = 11 - k;
            g_Wt_hi[1][(s * 64 + b) * 128 + h] = hi;
            g_Wt_lo[1][(s * 64 + b) * 128 + h] = lo;
        }
        if (k == 11) break;
        float a0 = 0.f, a1 = 0.f;
        #pragma unroll 4
        for (int o = 0; o < 128; ++o) {
            float Bv = g_W[(128 + o) * 128 + h];
            float Av = g_W[o * 128 + h];
            a0 += cur[0][o] * Bv + prev[0][o] * Av;
            a1 += cur[1][o] * Bv + prev[1][o] * Av;
        }
        __syncthreads();
        prev[0][h] = cur[0][h]; prev[1][h] = cur[1][h];
        __syncthreads();
        cur[0][h] = a0; cur[1][h] = a1;
        __syncthreads();
    }
}

// ---------------- MMA helper ---------------------------------------------
__device__ __forceinline__ void mma_bf16(float* c, const unsigned* a,
                                         unsigned b0, unsigned b1) {
    asm volatile(
        "mma.sync.aligned.m16n8k16.row.col.f32.bf16.bf16.f32 "
        "{%0,%1,%2,%3}, {%4,%5,%6,%7}, {%8,%9}, {%0,%1,%2,%3};"
        : "+f"(c[0]), "+f"(c[1]), "+f"(c[2]), "+f"(c[3])
        : "r"(a[0]), "r"(a[1]), "r"(a[2]), "r"(a[3]), "r"(b0), "r"(b1));
}

constexpr int ASTW = 12;   // A smem row stride in words (8 data + 4 pad)
constexpr int WST  = 136;  // W smem row stride in words

// ---------------- big encoder GEMM: h(10), h(11) in one launch ---------------
__global__ void __launch_bounds__(256, 2)
k_hbig() {
    __shared__ __align__(16) unsigned Ah[2][128 * ASTW];
    __shared__ __align__(16) unsigned Al[2][128 * ASTW];
    __shared__ __align__(16) unsigned Wh[2][8 * WST];
    __shared__ __align__(16) unsigned Wl[2][8 * WST];

    int tgt  = blockIdx.y;
    const unsigned* whp = g_Wt_hi[tgt];
    const unsigned* wlp = g_Wt_lo[tgt];

    int t    = threadIdx.x;
    int w    = t >> 5;
    int l    = t & 31;
    int row0 = blockIdx.x * 128;
    int wr   = w * 16;

    float acc[16][4];
    #pragma unroll
    for (int nt = 0; nt < 16; ++nt)
        #pragma unroll
        for (int j = 0; j < 4; ++j) acc[nt][j] = 0.f;

    int arow = t >> 1, ahalf = t & 1;
    int wkk  = t >> 5, wns = l * 4;
    long long agi = (long long)(row0 + arow) * 64 + ahalf * 4;
    bool arow_ok = (row0 + arow) < NN;

    {
        uint4 uh = {0,0,0,0}, ul = {0,0,0,0};
        if (arow_ok) {
            uh = __ldg(reinterpret_cast<const uint4*>(&g_hg12h[0][0] + agi));
            ul = __ldg(reinterpret_cast<const uint4*>(&g_hg12l[0][0] + agi));
        }
        *reinterpret_cast<uint4*>(&Ah[0][arow * ASTW + ahalf * 4]) = uh;
        *reinterpret_cast<uint4*>(&Al[0][arow * ASTW + ahalf * 4]) = ul;
        uint4 pwh = __ldg(reinterpret_cast<const uint4*>(&whp[wkk * 128 + wns]));
        uint4 pwl = __ldg(reinterpret_cast<const uint4*>(&wlp[wkk * 128 + wns]));
        *reinterpret_cast<uint4*>(&Wh[0][wkk * WST + wns]) = pwh;
        *reinterpret_cast<uint4*>(&Wl[0][wkk * WST + wns]) = pwl;
    }
    __syncthreads();

    int rb = wr + (l >> 2);
    int kw = l & 3;

    #pragma unroll 1
    for (int c = 0; c < 96; ++c) {
        int buf = c & 1;
        bool has = (c + 1 < 96);

        uint4 uh = {0,0,0,0}, ul = {0,0,0,0}, pwh, pwl;
        if (has) {
            int cn = c + 1;
            const unsigned* sh_ = &g_hg12h[cn >> 3][0];
            const unsigned* sl_ = &g_hg12l[cn >> 3][0];
            if (arow_ok) {
                uh = __ldg(reinterpret_cast<const uint4*>(sh_ + agi + (cn & 7) * 8));
                ul = __ldg(reinterpret_cast<const uint4*>(sl_ + agi + (cn & 7) * 8));
            }
            pwh = __ldg(reinterpret_cast<const uint4*>(&whp[(cn * 8 + wkk) * 128 + wns]));
            pwl = __ldg(reinterpret_cast<const uint4*>(&wlp[(cn * 8 + wkk) * 128 + wns]));
        }

        const unsigned* ah = &Ah[buf][0];
        const unsigned* al = &Al[buf][0];
        unsigned ahi[4], alo[4];
        ahi[0] = ah[rb * ASTW + kw];
        ahi[1] = ah[(rb + 8) * ASTW + kw];
        ahi[2] = ah[rb * ASTW + 4 + kw];
        ahi[3] = ah[(rb + 8) * ASTW + 4 + kw];
        alo[0] = al[rb * ASTW + kw];
        alo[1] = al[(rb + 8) * ASTW + kw];
        alo[2] = al[rb * ASTW + 4 + kw];
        alo[3] = al[(rb + 8) * ASTW + 4 + kw];
        #pragma unroll
        for (int nt = 0; nt < 16; ++nt) {
            int wb = nt * 8 + (l >> 2);
            unsigned bh0 = Wh[buf][kw * WST + wb];
            unsigned bh1 = Wh[buf][(4 + kw) * WST + wb];
            unsigned bl0 = Wl[buf][kw * WST + wb];
            unsigned bl1 = Wl[buf][(4 + kw) * WST + wb];
            mma_bf16(acc[nt], ahi, bh0, bh1);
            mma_bf16(acc[nt], ahi, bl0, bl1);
            mma_bf16(acc[nt], alo, bh0, bh1);
        }

        if (has) {
            int nbuf = buf ^ 1;
            *reinterpret_cast<uint4*>(&Ah[nbuf][arow * ASTW + ahalf * 4]) = uh;
            *reinterpret_cast<uint4*>(&Al[nbuf][arow * ASTW + ahalf * 4]) = ul;
            *reinterpret_cast<uint4*>(&Wh[nbuf][wkk * WST + wns]) = pwh;
            *reinterpret_cast<uint4*>(&Wl[nbuf][wkk * WST + wns]) = pwl;
        }
        __syncthreads();
    }

    unsigned* dsth = g_hbh[tgt];
    unsigned* dstl = g_hbl[tgt];
    const float* bb = g_bbig[tgt];
    int cw = 2 * (l & 3);
    int rA = row0 + rb;
    #pragma unroll
    for (int nt = 0; nt < 16; ++nt) {
        int col = nt * 8 + cw;
        float2 dv = *reinterpret_cast<const float2*>(&bb[col]);
        unsigned hi, lo;
        if (rA < NN) {
            split_pk(acc[nt][0] + dv.x, acc[nt][1] + dv.y, hi, lo);
            dsth[(long long)rA * 64 + col / 2] = hi;
            dstl[(long long)rA * 64 + col / 2] = lo;
        }
        if (rA + 8 < NN) {
            split_pk(acc[nt][2] + dv.x, acc[nt][3] + dv.y, hi, lo);
            dsth[(long long)(rA + 8) * 64 + col / 2] = hi;
            dstl[(long long)(rA + 8) * 64 + col / 2] = lo;
        }
    }
}

// ---------------- decoder h_new GEMM + fused y head --------------------------
__global__ void __launch_bounds__(256, 2)
k_hnew(int i1, int i2, int hgsel, int idst,
       const float* __restrict__ head_w, const float* __restrict__ head_b,
       float* __restrict__ outy) {
    __shared__ __align__(16) unsigned Ah[2][128 * ASTW];
    __shared__ __align__(16) unsigned Al[2][128 * ASTW];
    __shared__ __align__(16) unsigned Wh[2][8 * WST];
    __shared__ __align__(16) unsigned Wl[2][8 * WST];

    const unsigned* hgh = (hgsel >= 0) ? &g_hg12h[hgsel][0] : g_aggh;
    const unsigned* hgl = (hgsel >= 0) ? &g_hg12l[hgsel][0] : g_aggl;
    const unsigned* h1h = g_hbh[i1];
    const unsigned* h1l = g_hbl[i1];
    const unsigned* h2h = g_hbh[i2];
    const unsigned* h2l = g_hbl[i2];

    int t    = threadIdx.x;
    int w    = t >> 5;
    int l    = t & 31;
    int row0 = blockIdx.x * 128;
    int wr   = w * 16;

    float acc[16][4];
    #pragma unroll
    for (int nt = 0; nt < 16; ++nt)
        #pragma unroll
        for (int j = 0; j < 4; ++j) acc[nt][j] = 0.f;

    int arow = t >> 1, ahalf = t & 1;
    int wkk  = t >> 5, wns = l * 4;
    long long agi = (long long)(row0 + arow) * 64 + ahalf * 4;
    bool arow_ok = (row0 + arow) < NN;

    {
        uint4 uh = {0,0,0,0}, ul = {0,0,0,0};
        if (arow_ok) {
            uh = __ldg(reinterpret_cast<const uint4*>(h1h + agi));
            ul = __ldg(reinterpret_cast<const uint4*>(h1l + agi));
        }
        *reinterpret_cast<uint4*>(&Ah[0][arow * ASTW + ahalf * 4]) = uh;
        *reinterpret_cast<uint4*>(&Al[0][arow * ASTW + ahalf * 4]) = ul;
        uint4 pwh = __ldg(reinterpret_cast<const uint4*>(&g_Whi_pk[wkk * 128 + wns]));
        uint4 pwl = __ldg(reinterpret_cast<const uint4*>(&g_Wlo_pk[wkk * 128 + wns]));
        *reinterpret_cast<uint4*>(&Wh[0][wkk * WST + wns]) = pwh;
        *reinterpret_cast<uint4*>(&Wl[0][wkk * WST + wns]) = pwl;
    }
    __syncthreads();

    int rb = wr + (l >> 2);
    int kw = l & 3;

    for (int c = 0; c < 24; ++c) {
        int buf = c & 1;
        bool has = (c + 1 < 24);

        uint4 uh = {0,0,0,0}, ul = {0,0,0,0}, pwh, pwl;
        if (has) {
            int cn = c + 1;
            const unsigned* sh_ = (cn < 8) ? h1h : (cn < 16) ? h2h : hgh;
            const unsigned* sl_ = (cn < 8) ? h1l : (cn < 16) ? h2l : hgl;
            if (arow_ok) {
                uh = __ldg(reinterpret_cast<const uint4*>(sh_ + agi + (cn & 7) * 8));
                ul = __ldg(reinterpret_cast<const uint4*>(sl_ + agi + (cn & 7) * 8));
            }
            pwh = __ldg(reinterpret_cast<const uint4*>(&g_Whi_pk[(cn * 8 + wkk) * 128 + wns]));
            pwl = __ldg(reinterpret_cast<const uint4*>(&g_Wlo_pk[(cn * 8 + wkk) * 128 + wns]));
        }

        const unsigned* ah = &Ah[buf][0];
        const unsigned* al = &Al[buf][0];
        unsigned ahi[4], alo[4];
        ahi[0] = ah[rb * ASTW + kw];
        ahi[1] = ah[(rb + 8) * ASTW + kw];
        ahi[2] = ah[rb * ASTW + 4 + kw];
        ahi[3] = ah[(rb + 8) * ASTW + 4 + kw];
        alo[0] = al[rb * ASTW + kw];
        alo[1] = al[(rb + 8) * ASTW + kw];
        alo[2] = al[rb * ASTW + 4 + kw];
        alo[3] = al[(rb + 8) * ASTW + 4 + kw];
        #pragma unroll
        for (int nt = 0; nt < 16; ++nt) {
            int wb = nt * 8 + (l >> 2);
            unsigned bh0 = Wh[buf][kw * WST + wb];
            unsigned bh1 = Wh[buf][(4 + kw) * WST + wb];
            unsigned bl0 = Wl[buf][kw * WST + wb];
            unsigned bl1 = Wl[buf][(4 + kw) * WST + wb];
            mma_bf16(acc[nt], ahi, bh0, bh1);
            mma_bf16(acc[nt], ahi, bl0, bl1);
            mma_bf16(acc[nt], alo, bh0, bh1);
        }

        if (has) {
            int nbuf = buf ^ 1;
            *reinterpret_cast<uint4*>(&Ah[nbuf][arow * ASTW + ahalf * 4]) = uh;
            *reinterpret_cast<uint4*>(&Al[nbuf][arow * ASTW + ahalf * 4]) = ul;
            *reinterpret_cast<uint4*>(&Wh[nbuf][wkk * WST + wns]) = pwh;
            *reinterpret_cast<uint4*>(&Wl[nbuf][wkk * WST + wns]) = pwl;
        }
        __syncthreads();
    }

    // epilogue: bias into acc; store packed bf16 hi/lo; fused y head
    unsigned* dsth = g_hbh[idst];
    unsigned* dstl = g_hbl[idst];
    int cw = 2 * (l & 3);
    int rA = row0 + rb;
    #pragma unroll
    for (int nt = 0; nt < 16; ++nt) {
        int col = nt * 8 + cw;
        float2 dv = *reinterpret_cast<const float2*>(&g_dvec[col]);
        acc[nt][0] += dv.x; acc[nt][1] += dv.y;
        acc[nt][2] += dv.x; acc[nt][3] += dv.y;
        unsigned hi, lo;
        if (rA < NN) {
            split_pk(acc[nt][0], acc[nt][1], hi, lo);
            dsth[(long long)rA * 64 + col / 2] = hi;
            dstl[(long long)rA * 64 + col / 2] = lo;
        }
        if (rA + 8 < NN) {
            split_pk(acc[nt][2], acc[nt][3], hi, lo);
            dsth[(long long)(rA + 8) * 64 + col / 2] = hi;
            dstl[(long long)(rA + 8) * 64 + col / 2] = lo;
        }
    }

    // y = h_new @ head_w^T + head_b (reuse dead A-tile smem for head_w)
    float* Hw = reinterpret_cast<float*>(&Ah[0][0]);
    for (int i = t; i < 16 * 128; i += 256) Hw[i] = head_w[i];
    __syncthreads();
    #pragma unroll
    for (int ch = 0; ch < 16; ++ch) {
        float s0 = 0.f, s1 = 0.f;
        #pragma unroll
        for (int nt = 0; nt < 16; ++nt) {
            int col = nt * 8 + cw;
            float w0 = Hw[ch * 128 + col], w1 = Hw[ch * 128 + col + 1];
            s0 += acc[nt][0] * w0 + acc[nt][1] * w1;
            s1 += acc[nt][2] * w0 + acc[nt][3] * w1;
        }
        s0 += __shfl_xor_sync(0xffffffffu, s0, 1);
        s0 += __shfl_xor_sync(0xffffffffu, s0, 2);
        s1 += __shfl_xor_sync(0xffffffffu, s1, 1);
        s1 += __shfl_xor_sync(0xffffffffu, s1, 2);
        if ((l & 3) == 0) {
            float hb = __ldg(&head_b[ch]);
            if (rA < NN)     outy[(long long)rA * 16 + ch] = s0 + hb;
            if (rA + 8 < NN) outy[(long long)(rA + 8) * 16 + ch] = s1 + hb;
        }
    }
}

// ---------------------------------------------------------------------------
extern "C" void kernel_launch(void* const* d_in, const int* in_sizes, int n_in,
                              void* d_out, int out_size) {
    const float* x_seq  = (const float*)d_in[0];
    const void*  ei     = d_in[1];
    const float* gcn_w  = (const float*)d_in[5];
    const float* gcn_b  = (const float*)d_in[6];
    const float* conv_w = (const float*)d_in[7];
    const float* conv_b = (const float*)d_in[8];
    const float* proj_w = (const float*)d_in[9];
    const float* proj_b = (const float*)d_in[10];
    const float* head_w = (const float*)d_in[11];
    const float* head_b = (const float*)d_in[12];
    float* out = (float*)d_out;

    // prep + CSR
    k_init<<<(TT * NN + 255) / 256, 256>>>((const unsigned*)ei);
    k_prepWsd<<<193, 128>>>(conv_w, proj_w, conv_b, proj_b);
    {
        long long tot = (long long)TT * EE;
        int blocks = (int)((tot + 255) / 256);
        k_count12<<<blocks, 256>>>(ei);
        k_scanA<<<dim3(10, TT), 256>>>();
        k_scanB<<<dim3(10, TT), 256>>>();
        k_fill12<<<blocks, 256>>>(ei);
    }

    // all 12 encoder GCNs
    {
        dim3 gg(NN / 16, TT);
        k_gcn_all<<<gg, 128>>>(x_seq, gcn_w, gcn_b);
    }

    // transfer-matrix chain + biases + Wt pack — ONE launch
    k_Rchain<<<65, 128>>>();

    // one wide GEMM: h(10) -> buffer 0, h(11) -> buffer 1
    k_hbig<<<dim3((NN + 127) / 128, 2), 256>>>();

    // decoder: 6 serial steps with feedback
    int i1 = 0, i2 = 1, idst = 2;
    for (int t = TT; t < TT + HOR; ++t) {
        int hgsel;
        float* outy = out + (long long)(t - TT) * NN * CC;
        if (t == TT) hgsel = TT - 1;     // identical GCN to encoder step 11
        else {
            const float* xin = out + (long long)(t - TT - 1) * NN * CC;
            k_gcn1<<<NN / 16, 128>>>(xin, gcn_w, gcn_b);
            hgsel = -1;
        }
        k_hnew<<<(NN + 127) / 128, 256>>>(i1, i2, hgsel, idst,
                                          head_w, head_b, outy);
        int old1 = i1; i1 = i2; i2 = idst; idst = old1;
    }
}

// round 13
// speedup vs baseline: 2.6850x; 1.0242x over previous
#include <cuda_runtime.h>
#include <cuda_bf16.h>

constexpr int NN  = 20000;   // nodes
constexpr int TT  = 12;      // encoder steps
constexpr int HOR = 6;       // decoder horizon
constexpr int FF  = 16;      // input features (== C, decoder feedback)
constexpr int EE  = 320000;  // edges
constexpr int HH  = 128;     // hidden
constexpr int CC  = 16;      // out channels

// ---------------- scratch (static device globals; no allocation) -----------
__device__ __align__(16) float g_W[384 * HH];         // fused [A;B;C] fp32
__device__ __align__(16) float g_dvec[HH];            // fused bias vector
__device__ __align__(16) unsigned g_Whi_pk[192 * HH]; // bf16x2-packed hi(W)
__device__ __align__(16) unsigned g_Wlo_pk[192 * HH]; // bf16x2-packed lo(W)

// big encoder weight (packed directly by k_Rchain) and biases
__device__ __align__(16) float g_bbig[2][HH];         // bias(10), bias(11)
__device__ __align__(16) unsigned g_Wt_hi[2][768 * HH];
__device__ __align__(16) unsigned g_Wt_lo[2][768 * HH];

// pre-packed bf16 hi/lo activations
__device__ __align__(16) unsigned g_hg12h[TT][NN * 64];
__device__ __align__(16) unsigned g_hg12l[TT][NN * 64];
__device__ __align__(16) unsigned g_hbh[3][NN * 64];
__device__ __align__(16) unsigned g_hbl[3][NN * 64];
__device__ __align__(16) unsigned g_aggh[NN * 64];
__device__ __align__(16) unsigned g_aggl[NN * 64];
__device__ int   g_is64;

// per-edge-set CSR (built once per launch)
__device__ int   g_deg[TT][NN];
__device__ int   g_indptr[TT][NN + 1];
__device__ int   g_cur[TT][NN];
__device__ float g_dinv[TT][NN];
__device__ __align__(8) int2 g_epk[TT][EE];           // packed (src, w_bits)
__device__ int   g_psum[TT][10];

// ---------------- helpers ----------------------------------------------------
__device__ __forceinline__ unsigned pk_bf(__nv_bfloat16 a, __nv_bfloat16 b) {
    __nv_bfloat162 x; x.x = a; x.y = b;
    return *reinterpret_cast<unsigned*>(&x);
}
__device__ __forceinline__ void split_pk(float a, float b,
                                         unsigned& hi, unsigned& lo) {
    __nv_bfloat16 ha = __float2bfloat16(a);
    __nv_bfloat16 hb = __float2bfloat16(b);
    __nv_bfloat16 la = __float2bfloat16(a - __bfloat162float(ha));
    __nv_bfloat16 lb = __float2bfloat16(b - __bfloat162float(hb));
    hi = pk_bf(ha, hb);
    lo = pk_bf(la, lb);
}

__device__ __forceinline__ int load_idx(const void* p, long long e) {
    int v;
    if (g_is64) v = (int)((const long long*)p)[e];
    else        v = ((const int*)p)[e];
    v = v < 0 ? 0 : (v >= NN ? NN - 1 : v);
    return v;
}

// ---------------- launch 1: detect dtype + zero degree arrays ---------------
__global__ void k_init(const unsigned* __restrict__ w) {
    long long idx = (long long)blockIdx.x * blockDim.x + threadIdx.x;
    if (idx < (long long)TT * NN) (&g_deg[0][0])[idx] = 0;
    if (idx == 0) {
        int nz = 0;
        #pragma unroll 8
        for (int i = 0; i < 128; ++i) nz += (w[2 * i + 1] != 0u);
        g_is64 = (nz == 0) ? 1 : 0;
    }
}

// ---------------- launch 2: fold conv/proj -> W (fp32 + bf16 split), dvec ---
__global__ void k_prepWsd(const float* __restrict__ conv_w,
                          const float* __restrict__ proj_w,
                          const float* __restrict__ conv_b,
                          const float* __restrict__ proj_b) {
    int h = threadIdx.x;
    if (blockIdx.x == 192) {             // dvec
        float acc = proj_b[h];
        #pragma unroll 4
        for (int j = 0; j < 384; ++j) acc += conv_b[j] * proj_w[h * 384 + j];
        g_dvec[h] = acc;
        return;
    }
    __shared__ float wa[6][128];
    int kp = blockIdx.x;                 // 0..191
    int c0 = 2 * kp, c1 = c0 + 1;
    float a0 = 0.f, a1 = 0.f;
    if (c0 < 128) {
        wa[0][h] = conv_w[((128 + h) * 128 + c0) * 3 + 0];
        wa[1][h] = conv_w[((128 + h) * 128 + c1) * 3 + 0];
        __syncthreads();
        #pragma unroll 4
        for (int o = 0; o < 128; ++o) {
            float p = proj_w[h * 384 + 128 + o];
            a0 += wa[0][o] * p; a1 += wa[1][o] * p;
        }
    } else if (c0 < 256) {
        int cc0 = c0 - 128, cc1 = c1 - 128;
        wa[0][h] = conv_w[(h * 128 + cc0) * 3 + 0];
        wa[1][h] = conv_w[(h * 128 + cc1) * 3 + 0];
        __syncthreads();
        #pragma unroll 4
        for (int o = 0; o < 128; ++o) {
            float p = proj_w[h * 384 + o];
            a0 += wa[0][o] * p; a1 += wa[1][o] * p;
        }
    } else {
        int cc0 = c0 - 256, cc1 = c1 - 256;
        wa[0][h] = conv_w[(h * 128 + cc0) * 3 + 1];
        wa[1][h] = conv_w[((128 + h) * 128 + cc0) * 3 + 1];
        wa[2][h] = conv_w[((256 + h) * 128 + cc0) * 3 + 1];
        wa[3][h] = conv_w[(h * 128 + cc1) * 3 + 1];
        wa[4][h] = conv_w[((128 + h) * 128 + cc1) * 3 + 1];
        wa[5][h] = conv_w[((256 + h) * 128 + cc1) * 3 + 1];
        __syncthreads();
        #pragma unroll 2
        for (int o = 0; o < 128; ++o) {
            float p0 = proj_w[h * 384 + o];
            float p1 = proj_w[h * 384 + 128 + o];
            float p2 = proj_w[h * 384 + 256 + o];
            a0 += wa[0][o] * p0 + wa[1][o] * p1 + wa[2][o] * p2;
            a1 += wa[3][o] * p0 + wa[4][o] * p1 + wa[5][o] * p2;
        }
    }
    g_W[c0 * 128 + h] = a0;
    g_W[c1 * 128 + h] = a1;
    unsigned hi, lo;
    split_pk(a0, a1, hi, lo);
    g_Whi_pk[kp * 128 + h] = hi;
    g_Wlo_pk[kp * 128 + h] = lo;
}

// ---------------- CSR construction ----------------------------------------
__global__ void k_count12(const void* __restrict__ ei) {
    long long idx = (long long)blockIdx.x * blockDim.x + threadIdx.x;
    if (idx >= (long long)TT * EE) return;
    int set = (int)(idx / EE);
    int e   = (int)(idx % EE);
    int d = load_idx(ei, (long long)set * 2 * EE + EE + e);
    atomicAdd(&g_deg[set][d], 1);
}

// phase A: per-chunk degree sums (10 chunks of 2000 per set)
__global__ void k_scanA() {
    __shared__ int wsum[8];
    int set = blockIdx.y, chunk = blockIdx.x;
    int t = threadIdx.x, lane = t & 31, wid = t >> 5;
    int base = chunk * 2000;
    int acc = 0;
    for (int j = t; j < 2000; j += 256) acc += g_deg[set][base + j];
    #pragma unroll
    for (int d = 16; d > 0; d >>= 1) acc += __shfl_down_sync(~0u, acc, d);
    if (lane == 0) wsum[wid] = acc;
    __syncthreads();
    if (t == 0) {
        int s = 0;
        #pragma unroll
        for (int w = 0; w < 8; ++w) s += wsum[w];
        g_psum[set][chunk] = s;
    }
}

// phase B: in-chunk exclusive scan + indptr/cur/dinv emit
__global__ void k_scanB() {
    __shared__ int sm[2048];
    __shared__ int woff[8];
    __shared__ int s_off;
    int set = blockIdx.y, chunk = blockIdx.x;
    int t = threadIdx.x, lane = t & 31, wid = t >> 5;
    int base = chunk * 2000;
    if (t == 0) {
        int o = 0;
        for (int c = 0; c < chunk; ++c) o += g_psum[set][c];
        s_off = o;
    }
    for (int j = t; j < 2048; j += 256)
        sm[j] = (j < 2000) ? g_deg[set][base + j] : 0;
    __syncthreads();
    int v[8];
    int run = 0;
    #pragma unroll
    for (int i = 0; i < 8; ++i) { v[i] = sm[t * 8 + i]; run += v[i]; }
    int x = run;
    #pragma unroll
    for (int d = 1; d < 32; d <<= 1) {
        int y = __shfl_up_sync(~0u, x, d);
        if (lane >= d) x += y;
    }
    if (lane == 31) woff[wid] = x;
    __syncthreads();
    if (t == 0) {
        int o = 0;
        #pragma unroll
        for (int w = 0; w < 8; ++w) { int tmp = woff[w]; woff[w] = o; o += tmp; }
    }
    __syncthreads();
    int runp = s_off + woff[wid] + (x - run);
    #pragma unroll
    for (int i = 0; i < 8; ++i) {
        int j = t * 8 + i;
        if (j < 2000) {
            int n = base + j;
            g_indptr[set][n] = runp;
            g_cur[set][n]    = runp;
            g_dinv[set][n]   = rsqrtf(1.0f + (float)v[i]);
            runp += v[i];
        }
    }
    if (chunk == 9 && t == 249) g_indptr[set][NN] = runp;
}

__global__ void k_fill12(const void* __restrict__ ei) {
    long long idx = (long long)blockIdx.x * blockDim.x + threadIdx.x;
    if (idx >= (long long)TT * EE) return;
    int set = (int)(idx / EE);
    int e   = (int)(idx % EE);
    long long b = (long long)set * 2 * EE;
    int s = load_idx(ei, b + e);
    int d = load_idx(ei, b + EE + e);
    int pos = atomicAdd(&g_cur[set][d], 1);
    float w = g_dinv[set][s] * g_dinv[set][d];
    g_epk[set][pos] = make_int2(s, __float_as_int(w));
}

// ---------------- fused GCN: aggregate -> weight multiply -> split+pack ------
// block = 16 nodes, 128 threads. Phase1: each node served by 8 lanes
// (2 features each), edge loop unrolled x4 for MLP. Phase2: thread = out col.
__device__ __forceinline__ void gcn_body(const float* __restrict__ x, int set,
                                         unsigned* __restrict__ outh,
                                         unsigned* __restrict__ outl,
                                         const float* __restrict__ gcn_w,
                                         const float* __restrict__ gcn_b,
                                         int row0) {
    __shared__ float Xs[16 * 16];
    __shared__ float Ws[16 * 128];
    int tid = threadIdx.x;
    #pragma unroll
    for (int i = 0; i < 16; ++i) Ws[i * 128 + tid] = gcn_w[i * 128 + tid];

    int lane   = tid & 31;
    int nlocal = (tid >> 5) * 4 + (lane >> 3);
    int f2     = lane & 7;
    int node   = row0 + nlocal;
    float di = g_dinv[set][node];
    float2 acc = *reinterpret_cast<const float2*>(&x[node * 16 + 2 * f2]);
    float d2 = di * di;
    acc.x *= d2; acc.y *= d2;
    int beg = g_indptr[set][node], end = g_indptr[set][node + 1];
    const int2* ep = &g_epk[set][0];
    int i = beg;
    for (; i + 3 < end; i += 4) {
        int2 e0 = __ldg(&ep[i]);
        int2 e1 = __ldg(&ep[i + 1]);
        int2 e2 = __ldg(&ep[i + 2]);
        int2 e3 = __ldg(&ep[i + 3]);
        float2 u0 = *reinterpret_cast<const float2*>(&x[e0.x * 16 + 2 * f2]);
        float2 u1 = *reinterpret_cast<const float2*>(&x[e1.x * 16 + 2 * f2]);
        float2 u2 = *reinterpret_cast<const float2*>(&x[e2.x * 16 + 2 * f2]);
        float2 u3 = *reinterpret_cast<const float2*>(&x[e3.x * 16 + 2 * f2]);
        float w0 = __int_as_float(e0.y), w1 = __int_as_float(e1.y);
        float w2 = __int_as_float(e2.y), w3 = __int_as_float(e3.y);
        acc.x += w0 * u0.x + w1 * u1.x + w2 * u2.x + w3 * u3.x;
        acc.y += w0 * u0.y + w1 * u1.y + w2 * u2.y + w3 * u3.y;
    }
    for (; i < end; ++i) {
        int2 e0 = __ldg(&ep[i]);
        float2 u0 = *reinterpret_cast<const float2*>(&x[e0.x * 16 + 2 * f2]);
        float w0 = __int_as_float(e0.y);
        acc.x += w0 * u0.x; acc.y += w0 * u0.y;
    }
    Xs[nlocal * 16 + 2 * f2]     = acc.x;
    Xs[nlocal * 16 + 2 * f2 + 1] = acc.y;
    __syncthreads();

    float b = gcn_b[tid];
    #pragma unroll
    for (int r = 0; r < 16; ++r) {
        float a = b;
        #pragma unroll
        for (int f = 0; f < 16; ++f) a += Xs[r * 16 + f] * Ws[f * 128 + tid];
        a = fmaxf(a, 0.f);
        float vo = __shfl_xor_sync(0xffffffffu, a, 1);
        if (!(tid & 1)) {
            unsigned hi, lo;
            split_pk(a, vo, hi, lo);
            outh[(row0 + r) * 64 + (tid >> 1)] = hi;
            outl[(row0 + r) * 64 + (tid >> 1)] = lo;
        }
    }
}

__global__ void k_gcn_all(const float* __restrict__ x_seq,
                          const float* __restrict__ gcn_w,
                          const float* __restrict__ gcn_b) {
    int set = blockIdx.y;
    gcn_body(x_seq + (long long)set * NN * FF, set,
             &g_hg12h[set][0], &g_hg12l[set][0], gcn_w, gcn_b, blockIdx.x * 16);
}

__global__ void k_gcn1(const float* __restrict__ x,
                       const float* __restrict__ gcn_w,
                       const float* __restrict__ gcn_b) {
    gcn_body(x, TT - 1, g_aggh, g_aggl, gcn_w, gcn_b, blockIdx.x * 16);
}

// ---------------- single-launch R chain + bias + Wt pack ---------------------
__global__ void k_Rchain() {
    __shared__ float cur[2][128], prev[2][128];
    int b = blockIdx.x;
    int h = threadIdx.x;

    if (b == 64) {                       // bias recurrence
        __shared__ float b1[128], b2[128];
        float d = g_dvec[h];
        b1[h] = 0.f; b2[h] = 0.f;
        __syncthreads();
        for (int t = 0; t <= 11; ++t) {
            float acc = d;
            #pragma unroll 4
            for (int o = 0; o < 128; ++o)
                acc += b1[o] * g_W[(128 + o) * 128 + h] + b2[o] * g_W[o * 128 + h];
            __syncthreads();
            b2[h] = b1[h];
            b1[h] = acc;
            if (t == 10) g_bbig[0][h] = acc;
            if (t == 11) g_bbig[1][h] = acc;
            __syncthreads();
        }
        return;
    }

    int r0 = 2 * b;
    cur[0][h]  = g_W[(256 + r0) * 128 + h];       // R(0) = C
    cur[1][h]  = g_W[(256 + r0 + 1) * 128 + h];
    prev[0][h] = 0.f; prev[1][h] = 0.f;
    g_Wt_hi[0][(11 * 64 + b) * 128 + h] = 0u;
    g_Wt_lo[0][(11 * 64 + b) * 128 + h] = 0u;
    __syncthreads();

    for (int k = 0; k <= 11; ++k) {
        unsigned hi, lo;
        split_pk(cur[0][h], cur[1][h], hi, lo);
        if (k <= 10) {
            int s = 10 - k;
            g_Wt_hi[0][(s * 64 + b) * 128 + h] = hi;
            g_Wt_lo[0][(s * 64 + b) * 128 + h] = lo;
        }
        {
            int s = 11 - k;
            g_Wt_hi[1][(s * 64 + b) * 128 + h] = hi;
            g_Wt_lo[1][(s * 64 + b) * 128 + h] = lo;
        }
        if (k == 11) break;
        float a0 = 0.f, a1 = 0.f;
        #pragma unroll 4
        for (int o = 0; o < 128; ++o) {
            float Bv = g_W[(128 + o) * 128 + h];
            float Av = g_W[o * 128 + h];
            a0 += cur[0][o] * Bv + prev[0][o] * Av;
            a1 += cur[1][o] * Bv + prev[1][o] * Av;
        }
        __syncthreads();
        prev[0][h] = cur[0][h]; prev[1][h] = cur[1][h];
        __syncthreads();
        cur[0][h] = a0; cur[1][h] = a1;
        __syncthreads();
    }
}

// ---------------- MMA helper ---------------------------------------------
__device__ __forceinline__ void mma_bf16(float* c, const unsigned* a,
                                         unsigned b0, unsigned b1) {
    asm volatile(
        "mma.sync.aligned.m16n8k16.row.col.f32.bf16.bf16.f32 "
        "{%0,%1,%2,%3}, {%4,%5,%6,%7}, {%8,%9}, {%0,%1,%2,%3};"
        : "+f"(c[0]), "+f"(c[1]), "+f"(c[2]), "+f"(c[3])
        : "r"(a[0]), "r"(a[1]), "r"(a[2]), "r"(a[3]), "r"(b0), "r"(b1));
}

constexpr int ASTW = 12;   // A smem row stride in words (8 data + 4 pad)
constexpr int WST  = 136;  // W smem row stride in words

// ---------------- big encoder GEMM: h(10), h(11) in one launch ---------------
__global__ void __launch_bounds__(256, 2)
k_hbig() {
    __shared__ __align__(16) unsigned Ah[2][128 * ASTW];
    __shared__ __align__(16) unsigned Al[2][128 * ASTW];
    __shared__ __align__(16) unsigned Wh[2][8 * WST];
    __shared__ __align__(16) unsigned Wl[2][8 * WST];

    int tgt  = blockIdx.y;
    const unsigned* whp = g_Wt_hi[tgt];
    const unsigned* wlp = g_Wt_lo[tgt];

    int t    = threadIdx.x;
    int w    = t >> 5;
    int l    = t & 31;
    int row0 = blockIdx.x * 128;
    int wr   = w * 16;

    float acc[16][4];
    #pragma unroll
    for (int nt = 0; nt < 16; ++nt)
        #pragma unroll
        for (int j = 0; j < 4; ++j) acc[nt][j] = 0.f;

    int arow = t >> 1, ahalf = t & 1;
    int wkk  = t >> 5, wns = l * 4;
    long long agi = (long long)(row0 + arow) * 64 + ahalf * 4;
    bool arow_ok = (row0 + arow) < NN;

    {
        uint4 uh = {0,0,0,0}, ul = {0,0,0,0};
        if (arow_ok) {
            uh = __ldg(reinterpret_cast<const uint4*>(&g_hg12h[0][0] + agi));
            ul = __ldg(reinterpret_cast<const uint4*>(&g_hg12l[0][0] + agi));
        }
        *reinterpret_cast<uint4*>(&Ah[0][arow * ASTW + ahalf * 4]) = uh;
        *reinterpret_cast<uint4*>(&Al[0][arow * ASTW + ahalf * 4]) = ul;
        uint4 pwh = __ldg(reinterpret_cast<const uint4*>(&whp[wkk * 128 + wns]));
        uint4 pwl = __ldg(reinterpret_cast<const uint4*>(&wlp[wkk * 128 + wns]));
        *reinterpret_cast<uint4*>(&Wh[0][wkk * WST + wns]) = pwh;
        *reinterpret_cast<uint4*>(&Wl[0][wkk * WST + wns]) = pwl;
    }
    __syncthreads();

    int rb = wr + (l >> 2);
    int kw = l & 3;

    #pragma unroll 1
    for (int c = 0; c < 96; ++c) {
        int buf = c & 1;
        bool has = (c + 1 < 96);

        uint4 uh = {0,0,0,0}, ul = {0,0,0,0}, pwh, pwl;
        if (has) {
            int cn = c + 1;
            const unsigned* sh_ = &g_hg12h[cn >> 3][0];
            const unsigned* sl_ = &g_hg12l[cn >> 3][0];
            if (arow_ok) {
                uh = __ldg(reinterpret_cast<const uint4*>(sh_ + agi + (cn & 7) * 8));
                ul = __ldg(reinterpret_cast<const uint4*>(sl_ + agi + (cn & 7) * 8));
            }
            pwh = __ldg(reinterpret_cast<const uint4*>(&whp[(cn * 8 + wkk) * 128 + wns]));
            pwl = __ldg(reinterpret_cast<const uint4*>(&wlp[(cn * 8 + wkk) * 128 + wns]));
        }

        const unsigned* ah = &Ah[buf][0];
        const unsigned* al = &Al[buf][0];
        unsigned ahi[4], alo[4];
        ahi[0] = ah[rb * ASTW + kw];
        ahi[1] = ah[(rb + 8) * ASTW + kw];
        ahi[2] = ah[rb * ASTW + 4 + kw];
        ahi[3] = ah[(rb + 8) * ASTW + 4 + kw];
        alo[0] = al[rb * ASTW + kw];
        alo[1] = al[(rb + 8) * ASTW + kw];
        alo[2] = al[rb * ASTW + 4 + kw];
        alo[3] = al[(rb + 8) * ASTW + 4 + kw];
        #pragma unroll
        for (int nt = 0; nt < 16; ++nt) {
            int wb = nt * 8 + (l >> 2);
            unsigned bh0 = Wh[buf][kw * WST + wb];
            unsigned bh1 = Wh[buf][(4 + kw) * WST + wb];
            unsigned bl0 = Wl[buf][kw * WST + wb];
            unsigned bl1 = Wl[buf][(4 + kw) * WST + wb];
            mma_bf16(acc[nt], ahi, bh0, bh1);
            mma_bf16(acc[nt], ahi, bl0, bl1);
            mma_bf16(acc[nt], alo, bh0, bh1);
        }

        if (has) {
            int nbuf = buf ^ 1;
            *reinterpret_cast<uint4*>(&Ah[nbuf][arow * ASTW + ahalf * 4]) = uh;
            *reinterpret_cast<uint4*>(&Al[nbuf][arow * ASTW + ahalf * 4]) = ul;
            *reinterpret_cast<uint4*>(&Wh[nbuf][wkk * WST + wns]) = pwh;
            *reinterpret_cast<uint4*>(&Wl[nbuf][wkk * WST + wns]) = pwl;
        }
        __syncthreads();
    }

    unsigned* dsth = g_hbh[tgt];
    unsigned* dstl = g_hbl[tgt];
    const float* bb = g_bbig[tgt];
    int cw = 2 * (l & 3);
    int rA = row0 + rb;
    #pragma unroll
    for (int nt = 0; nt < 16; ++nt) {
        int col = nt * 8 + cw;
        float2 dv = *reinterpret_cast<const float2*>(&bb[col]);
        unsigned hi, lo;
        if (rA < NN) {
            split_pk(acc[nt][0] + dv.x, acc[nt][1] + dv.y, hi, lo);
            dsth[(long long)rA * 64 + col / 2] = hi;
            dstl[(long long)rA * 64 + col / 2] = lo;
        }
        if (rA + 8 < NN) {
            split_pk(acc[nt][2] + dv.x, acc[nt][3] + dv.y, hi, lo);
            dsth[(long long)(rA + 8) * 64 + col / 2] = hi;
            dstl[(long long)(rA + 8) * 64 + col / 2] = lo;
        }
    }
}

// ---------------- decoder h_new GEMM + fused y head --------------------------
__global__ void __launch_bounds__(256, 2)
k_hnew(int i1, int i2, int hgsel, int idst,
       const float* __restrict__ head_w, const float* __restrict__ head_b,
       float* __restrict__ outy) {
    __shared__ __align__(16) unsigned Ah[2][128 * ASTW];
    __shared__ __align__(16) unsigned Al[2][128 * ASTW];
    __shared__ __align__(16) unsigned Wh[2][8 * WST];
    __shared__ __align__(16) unsigned Wl[2][8 * WST];

    const unsigned* hgh = (hgsel >= 0) ? &g_hg12h[hgsel][0] : g_aggh;
    const unsigned* hgl = (hgsel >= 0) ? &g_hg12l[hgsel][0] : g_aggl;
    const unsigned* h1h = g_hbh[i1];
    const unsigned* h1l = g_hbl[i1];
    const unsigned* h2h = g_hbh[i2];
    const unsigned* h2l = g_hbl[i2];

    int t    = threadIdx.x;
    int w    = t >> 5;
    int l    = t & 31;
    int row0 = blockIdx.x * 128;
    int wr   = w * 16;

    float acc[16][4];
    #pragma unroll
    for (int nt = 0; nt < 16; ++nt)
        #pragma unroll
        for (int j = 0; j < 4; ++j) acc[nt][j] = 0.f;

    int arow = t >> 1, ahalf = t & 1;
    int wkk  = t >> 5, wns = l * 4;
    long long agi = (long long)(row0 + arow) * 64 + ahalf * 4;
    bool arow_ok = (row0 + arow) < NN;

    {
        uint4 uh = {0,0,0,0}, ul = {0,0,0,0};
        if (arow_ok) {
            uh = __ldg(reinterpret_cast<const uint4*>(h1h + agi));
            ul = __ldg(reinterpret_cast<const uint4*>(h1l + agi));
        }
        *reinterpret_cast<uint4*>(&Ah[0][arow * ASTW + ahalf * 4]) = uh;
        *reinterpret_cast<uint4*>(&Al[0][arow * ASTW + ahalf * 4]) = ul;
        uint4 pwh = __ldg(reinterpret_cast<const uint4*>(&g_Whi_pk[wkk * 128 + wns]));
        uint4 pwl = __ldg(reinterpret_cast<const uint4*>(&g_Wlo_pk[wkk * 128 + wns]));
        *reinterpret_cast<uint4*>(&Wh[0][wkk * WST + wns]) = pwh;
        *reinterpret_cast<uint4*>(&Wl[0][wkk * WST + wns]) = pwl;
    }
    __syncthreads();

    int rb = wr + (l >> 2);
    int kw = l & 3;

    for (int c = 0; c < 24; ++c) {
        int buf = c & 1;
        bool has = (c + 1 < 24);

        uint4 uh = {0,0,0,0}, ul = {0,0,0,0}, pwh, pwl;
        if (has) {
            int cn = c + 1;
            const unsigned* sh_ = (cn < 8) ? h1h : (cn < 16) ? h2h : hgh;
            const unsigned* sl_ = (cn < 8) ? h1l : (cn < 16) ? h2l : hgl;
            if (arow_ok) {
                uh = __ldg(reinterpret_cast<const uint4*>(sh_ + agi + (cn & 7) * 8));
                ul = __ldg(reinterpret_cast<const uint4*>(sl_ + agi + (cn & 7) * 8));
            }
            pwh = __ldg(reinterpret_cast<const uint4*>(&g_Whi_pk[(cn * 8 + wkk) * 128 + wns]));
            pwl = __ldg(reinterpret_cast<const uint4*>(&g_Wlo_pk[(cn * 8 + wkk) * 128 + wns]));
        }

        const unsigned* ah = &Ah[buf][0];
        const unsigned* al = &Al[buf][0];
        unsigned ahi[4], alo[4];
        ahi[0] = ah[rb * ASTW + kw];
        ahi[1] = ah[(rb + 8) * ASTW + kw];
        ahi[2] = ah[rb * ASTW + 4 + kw];
        ahi[3] = ah[(rb + 8) * ASTW + 4 + kw];
        alo[0] = al[rb * ASTW + kw];
        alo[1] = al[(rb + 8) * ASTW + kw];
        alo[2] = al[rb * ASTW + 4 + kw];
        alo[3] = al[(rb + 8) * ASTW + 4 + kw];
        #pragma unroll
        for (int nt = 0; nt < 16; ++nt) {
            int wb = nt * 8 + (l >> 2);
            unsigned bh0 = Wh[buf][kw * WST + wb];
            unsigned bh1 = Wh[buf][(4 + kw) * WST + wb];
            unsigned bl0 = Wl[buf][kw * WST + wb];
            unsigned bl1 = Wl[buf][(4 + kw) * WST + wb];
            mma_bf16(acc[nt], ahi, bh0, bh1);
            mma_bf16(acc[nt], ahi, bl0, bl1);
            mma_bf16(acc[nt], alo, bh0, bh1);
        }

        if (has) {
            int nbuf = buf ^ 1;
            *reinterpret_cast<uint4*>(&Ah[nbuf][arow * ASTW + ahalf * 4]) = uh;
            *reinterpret_cast<uint4*>(&Al[nbuf][arow * ASTW + ahalf * 4]) = ul;
            *reinterpret_cast<uint4*>(&Wh[nbuf][wkk * WST + wns]) = pwh;
            *reinterpret_cast<uint4*>(&Wl[nbuf][wkk * WST + wns]) = pwl;
        }
        __syncthreads();
    }

    // epilogue: bias into acc; store packed bf16 hi/lo; fused y head
    unsigned* dsth = g_hbh[idst];
    unsigned* dstl = g_hbl[idst];
    int cw = 2 * (l & 3);
    int rA = row0 + rb;
    #pragma unroll
    for (int nt = 0; nt < 16; ++nt) {
        int col = nt * 8 + cw;
        float2 dv = *reinterpret_cast<const float2*>(&g_dvec[col]);
        acc[nt][0] += dv.x; acc[nt][1] += dv.y;
        acc[nt][2] += dv.x; acc[nt][3] += dv.y;
        unsigned hi, lo;
        if (rA < NN) {
            split_pk(acc[nt][0], acc[nt][1], hi, lo);
            dsth[(long long)rA * 64 + col / 2] = hi;
            dstl[(long long)rA * 64 + col / 2] = lo;
        }
        if (rA + 8 < NN) {
            split_pk(acc[nt][2], acc[nt][3], hi, lo);
            dsth[(long long)(rA + 8) * 64 + col / 2] = hi;
            dstl[(long long)(rA + 8) * 64 + col / 2] = lo;
        }
    }

    // y = h_new @ head_w^T + head_b (reuse dead A-tile smem for head_w)
    float* Hw = reinterpret_cast<float*>(&Ah[0][0]);
    for (int i = t; i < 16 * 128; i += 256) Hw[i] = head_w[i];
    __syncthreads();
    #pragma unroll
    for (int ch = 0; ch < 16; ++ch) {
        float s0 = 0.f, s1 = 0.f;
        #pragma unroll
        for (int nt = 0; nt < 16; ++nt) {
            int col = nt * 8 + cw;
            float w0 = Hw[ch * 128 + col], w1 = Hw[ch * 128 + col + 1];
            s0 += acc[nt][0] * w0 + acc[nt][1] * w1;
            s1 += acc[nt][2] * w0 + acc[nt][3] * w1;
        }
        s0 += __shfl_xor_sync(0xffffffffu, s0, 1);
        s0 += __shfl_xor_sync(0xffffffffu, s0, 2);
        s1 += __shfl_xor_sync(0xffffffffu, s1, 1);
        s1 += __shfl_xor_sync(0xffffffffu, s1, 2);
        if ((l & 3) == 0) {
            float hb = __ldg(&head_b[ch]);
            if (rA < NN)     outy[(long long)rA * 16 + ch] = s0 + hb;
            if (rA + 8 < NN) outy[(long long)(rA + 8) * 16 + ch] = s1 + hb;
        }
    }
}

// ---------------------------------------------------------------------------
extern "C" void kernel_launch(void* const* d_in, const int* in_sizes, int n_in,
                              void* d_out, int out_size) {
    const float* x_seq  = (const float*)d_in[0];
    const void*  ei     = d_in[1];
    const float* gcn_w  = (const float*)d_in[5];
    const float* gcn_b  = (const float*)d_in[6];
    const float* conv_w = (const float*)d_in[7];
    const float* conv_b = (const float*)d_in[8];
    const float* proj_w = (const float*)d_in[9];
    const float* proj_b = (const float*)d_in[10];
    const float* head_w = (const float*)d_in[11];
    const float* head_b = (const float*)d_in[12];
    float* out = (float*)d_out;

    // prep + CSR
    k_init<<<(TT * NN + 255) / 256, 256>>>((const unsigned*)ei);
    k_prepWsd<<<193, 128>>>(conv_w, proj_w, conv_b, proj_b);
    {
        long long tot = (long long)TT * EE;
        int blocks = (int)((tot + 255) / 256);
        k_count12<<<blocks, 256>>>(ei);
        k_scanA<<<dim3(10, TT), 256>>>();
        k_scanB<<<dim3(10, TT), 256>>>();
        k_fill12<<<blocks, 256>>>(ei);
    }

    // all 12 encoder GCNs
    {
        dim3 gg(NN / 16, TT);
        k_gcn_all<<<gg, 128>>>(x_seq, gcn_w, gcn_b);
    }

    // transfer-matrix chain + biases + Wt pack — ONE launch
    k_Rchain<<<65, 128>>>();

    // one wide GEMM: h(10) -> buffer 0, h(11) -> buffer 1
    k_hbig<<<dim3((NN + 127) / 128, 2), 256>>>();

    // decoder: 6 serial steps with feedback
    int i1 = 0, i2 = 1, idst = 2;
    for (int t = TT; t < TT + HOR; ++t) {
        int hgsel;
        float* outy = out + (long long)(t - TT) * NN * CC;
        if (t == TT) hgsel = TT - 1;     // identical GCN to encoder step 11
        else {
            const float* xin = out + (long long)(t - TT - 1) * NN * CC;
            k_gcn1<<<NN / 16, 128>>>(xin, gcn_w, gcn_b);
            hgsel = -1;
        }
        k_hnew<<<(NN + 127) / 128, 256>>>(i1, i2, hgsel, idst,
                                          head_w, head_b, outy);
        int old1 = i1; i1 = i2; i2 = idst; idst = old1;
    }
}